// round 9
// baseline (speedup 1.0000x reference)
#include <cuda_runtime.h>
#include <cuda_bf16.h>
#include <cstdint>

#define RTOT   32768
#define LSEQ   4096
#define NBATCH 8
#define DMODEL 128
#define DPROJ  648
#define DINNER 256
#define CONVD  384
#define NH     8
#define HD     32
#define QC     64
#define NCHK   (LSEQ/QC)
#define NCID   (NBATCH*NH*NCHK)

// ---------------- scratch (device globals) ----------------------------------
__device__ __align__(16) float g_zx [(size_t)RTOT * DPROJ];
__device__ __align__(16) float g_dtb[RTOT * NH];
__device__ __align__(16) float g_y  [RTOT * DINNER];
__device__ __align__(16) float g_S  [(size_t)NCID * QC];
__device__ __align__(16) float g_T  [NCID];
__device__ __align__(16) __nv_bfloat16 g_xch[RTOT * CONVD];          // conv out hi
__device__ __align__(16) __nv_bfloat16 g_xcl[RTOT * CONVD];          // conv out lo
__device__ __align__(16) __nv_bfloat16 g_Uh [(size_t)NCID * 2048];
__device__ __align__(16) __nv_bfloat16 g_Ul [(size_t)NCID * 2048];
__device__ __align__(16) __nv_bfloat16 g_hsh[(size_t)NCID * 2048];
__device__ __align__(16) __nv_bfloat16 g_hsl[(size_t)NCID * 2048];
__device__ __align__(16) __nv_bfloat16 g_ah [RTOT * DMODEL];
__device__ __align__(16) __nv_bfloat16 g_al [RTOT * DMODEL];
__device__ __align__(16) __nv_bfloat16 g_wih[672 * DMODEL];
__device__ __align__(16) __nv_bfloat16 g_wil[672 * DMODEL];
__device__ __align__(16) __nv_bfloat16 g_woh[DMODEL * DINNER];
__device__ __align__(16) __nv_bfloat16 g_wol[DMODEL * DINNER];
// -----------------------------------------------------------------------------

// ---- warp MMA helpers ----
static __device__ __forceinline__ uint32_t smem_u32(const void* p) {
    uint32_t a;
    asm("{ .reg .u64 t; cvta.to.shared.u64 t, %1; cvt.u32.u64 %0, t; }"
        : "=r"(a) : "l"(p));
    return a;
}
#define LDSM4(r, addr) \
    asm volatile("ldmatrix.sync.aligned.m8n8.x4.shared.b16 {%0,%1,%2,%3}, [%4];" \
        : "=r"((r)[0]), "=r"((r)[1]), "=r"((r)[2]), "=r"((r)[3]) : "r"(addr))
#define LDSM4T(r, addr) \
    asm volatile("ldmatrix.sync.aligned.m8n8.x4.trans.shared.b16 {%0,%1,%2,%3}, [%4];" \
        : "=r"((r)[0]), "=r"((r)[1]), "=r"((r)[2]), "=r"((r)[3]) : "r"(addr))
#define MMA16816(d, a, b0, b1) \
    asm volatile("mma.sync.aligned.m16n8k16.row.col.f32.bf16.bf16.f32 " \
        "{%0,%1,%2,%3}, {%4,%5,%6,%7}, {%8,%9}, {%0,%1,%2,%3};" \
        : "+f"((d)[0]), "+f"((d)[1]), "+f"((d)[2]), "+f"((d)[3]) \
        : "r"((a)[0]), "r"((a)[1]), "r"((a)[2]), "r"((a)[3]), "r"(b0), "r"(b1))

static __device__ __forceinline__ void split_bf16(float v, __nv_bfloat16& h,
                                                  __nv_bfloat16& l) {
    h = __float2bfloat16(v);
    l = __float2bfloat16(v - __bfloat162float(h));
}
static __device__ __forceinline__ void split4(float4 v, __nv_bfloat16* h,
                                              __nv_bfloat16* l) {
    split_bf16(v.x, h[0], l[0]); split_bf16(v.y, h[1], l[1]);
    split_bf16(v.z, h[2], l[2]); split_bf16(v.w, h[3], l[3]);
}
static __device__ __forceinline__ float silu(float v) {
    return v / (1.f + __expf(-v));
}

// ---------------- K_w: one-shot weight split -------------------------------
__global__ void k_wsplit(const float* __restrict__ Wi, const float* __restrict__ Wo) {
    int idx = blockIdx.x * 256 + threadIdx.x;
    const int NWI = DPROJ * DMODEL / 4;
    const int NWO = DMODEL * DINNER / 4;
    if (idx < NWI) {
        float4 v = ((const float4*)Wi)[idx];
        __nv_bfloat16 h[4], l[4];
        split4(v, h, l);
        ((uint2*)g_wih)[idx] = *(uint2*)h;
        ((uint2*)g_wil)[idx] = *(uint2*)l;
    } else if (idx < NWI + NWO) {
        int j = idx - NWI;
        float4 v = ((const float4*)Wo)[j];
        __nv_bfloat16 h[4], l[4];
        split4(v, h, l);
        ((uint2*)g_woh)[j] = *(uint2*)h;
        ((uint2*)g_wol)[j] = *(uint2*)l;
    }
}

// ---------------- K0: RMSNorm -> bf16 hi/lo splits --------------------------
__global__ void k_rmsnorm(const float* __restrict__ x, const float* __restrict__ w) {
    int row  = blockIdx.x * 8 + (threadIdx.x >> 5);
    int lane = threadIdx.x & 31;
    float4 v = ((const float4*)(x + (size_t)row * DMODEL))[lane];
    float ss = v.x * v.x + v.y * v.y + v.z * v.z + v.w * v.w;
#pragma unroll
    for (int o = 16; o; o >>= 1) ss += __shfl_xor_sync(0xffffffffu, ss, o);
    float sc = rsqrtf(ss * (1.f / DMODEL) + 1e-5f);
    float4 wv = ((const float4*)w)[lane];
    float4 o4;
    o4.x = v.x * sc * wv.x; o4.y = v.y * sc * wv.y;
    o4.z = v.z * sc * wv.z; o4.w = v.w * sc * wv.w;
    __nv_bfloat16 h[4], l[4];
    split4(o4, h, l);
    ((uint2*)(g_ah + (size_t)row * DMODEL))[lane] = *(uint2*)h;
    ((uint2*)(g_al + (size_t)row * DMODEL))[lane] = *(uint2*)l;
}

// ---------------- K1: in_proj GEMM via HMMA bf16x3, tile 128x96, K=128 ------
#define IP_AH 0
#define IP_AL 17408
#define IP_BH 34816
#define IP_BL 47872
#define IP_TOT 60928
__global__ void __launch_bounds__(256, 1) k_inproj_mma() {
    extern __shared__ __align__(16) __nv_bfloat16 smb[];
    int tid = threadIdx.x, wid = tid >> 5, lane = tid & 31;
    int rowBase = blockIdx.x * 128;
    int colBase = blockIdx.y * 96;

    for (int i = tid; i < 2048; i += 256) {
        int r = i >> 4, c = (i & 15) << 3;
        *(uint4*)&smb[IP_AH + r * 136 + c] =
            *(const uint4*)(g_ah + (size_t)(rowBase + r) * DMODEL + c);
        *(uint4*)&smb[IP_AL + r * 136 + c] =
            *(const uint4*)(g_al + (size_t)(rowBase + r) * DMODEL + c);
    }
    for (int i = tid; i < 1536; i += 256) {
        int r = i >> 4, c = (i & 15) << 3;
        *(uint4*)&smb[IP_BH + r * 136 + c] =
            *(const uint4*)(g_wih + (size_t)(colBase + r) * DMODEL + c);
        *(uint4*)&smb[IP_BL + r * 136 + c] =
            *(const uint4*)(g_wil + (size_t)(colBase + r) * DMODEL + c);
    }
    __syncthreads();

    uint32_t sb = smem_u32(smb);
    int mw = wid & 3, nw = wid >> 2;
    int arow = mw * 32, ncol = nw * 48;
    float acc[2][6][4] = {};
    int lrow = lane & 15, lk = (lane >> 4) << 3;
    int brow = (lane & 7) + ((lane >> 4) & 1) * 8;
    int bk = ((lane >> 3) & 1) << 3;
#pragma unroll
    for (int kf = 0; kf < 8; kf++) {
        int k0 = kf << 4;
        uint32_t ah[2][4], al[2][4];
#pragma unroll
        for (int mi = 0; mi < 2; mi++) {
            uint32_t ad = sb + (uint32_t)(((arow + mi * 16 + lrow) * 136 + k0 + lk) * 2);
            LDSM4(ah[mi], ad + IP_AH * 2);
            LDSM4(al[mi], ad + IP_AL * 2);
        }
        uint32_t bh[3][4], bl[3][4];
#pragma unroll
        for (int ng = 0; ng < 3; ng++) {
            uint32_t ad = sb + (uint32_t)(((ncol + ng * 16 + brow) * 136 + k0 + bk) * 2);
            LDSM4(bh[ng], ad + IP_BH * 2);
            LDSM4(bl[ng], ad + IP_BL * 2);
        }
#pragma unroll
        for (int mi = 0; mi < 2; mi++)
#pragma unroll
            for (int nf = 0; nf < 6; nf++) {
                uint32_t* BH = &bh[nf >> 1][(nf & 1) * 2];
                uint32_t* BL = &bl[nf >> 1][(nf & 1) * 2];
                MMA16816(acc[mi][nf], ah[mi], BH[0], BH[1]);
                MMA16816(acc[mi][nf], ah[mi], BL[0], BL[1]);
                MMA16816(acc[mi][nf], al[mi], BH[0], BH[1]);
            }
    }
    int g = lane >> 2, tg = lane & 3;
#pragma unroll
    for (int mi = 0; mi < 2; mi++) {
        int r = rowBase + arow + mi * 16 + g;
#pragma unroll
        for (int nf = 0; nf < 6; nf++) {
            int c = colBase + ncol + nf * 8 + tg * 2;
            if (c < DPROJ) {
                *(float2*)&g_zx[(size_t)r * DPROJ + c] =
                    make_float2(acc[mi][nf][0], acc[mi][nf][1]);
                *(float2*)&g_zx[(size_t)(r + 8) * DPROJ + c] =
                    make_float2(acc[mi][nf][2], acc[mi][nf][3]);
            }
        }
    }
}

// ---------------- K2: conv(K=4)+SiLU -> bf16 hi/lo splits -------------------
__global__ void __launch_bounds__(384) k_conv4(const float* __restrict__ cw,
                                               const float* __restrict__ cb) {
    int t = threadIdx.x;
    int c = (t % 96) * 4;
    int r0 = blockIdx.x * 32 + (t / 96) * 8;
    bool hist = (r0 & (LSEQ - 1)) != 0;
    float4 wA = *(const float4*)&cw[(c + 0) * 4];
    float4 wB = *(const float4*)&cw[(c + 1) * 4];
    float4 wC = *(const float4*)&cw[(c + 2) * 4];
    float4 wD = *(const float4*)&cw[(c + 3) * 4];
    float4 bias = *(const float4*)&cb[c];
    const float* src = g_zx + 256 + c;
    float4 z = make_float4(0.f, 0.f, 0.f, 0.f);
    float4 x0 = hist ? *(const float4*)&src[(size_t)(r0 - 3) * DPROJ] : z;
    float4 x1 = hist ? *(const float4*)&src[(size_t)(r0 - 2) * DPROJ] : z;
    float4 x2 = hist ? *(const float4*)&src[(size_t)(r0 - 1) * DPROJ] : z;
#pragma unroll
    for (int s = 0; s < 8; s++) {
        int r = r0 + s;
        float4 x3 = *(const float4*)&src[(size_t)r * DPROJ];
        float4 o;
        o.x = silu(bias.x + wA.x * x0.x + wA.y * x1.x + wA.z * x2.x + wA.w * x3.x);
        o.y = silu(bias.y + wB.x * x0.y + wB.y * x1.y + wB.z * x2.y + wB.w * x3.y);
        o.z = silu(bias.z + wC.x * x0.z + wC.y * x1.z + wC.z * x2.z + wC.w * x3.z);
        o.w = silu(bias.w + wD.x * x0.w + wD.y * x1.w + wD.z * x2.w + wD.w * x3.w);
        __nv_bfloat16 h4[4], l4[4];
        split4(o, h4, l4);
        *(uint2*)&g_xch[(size_t)r * CONVD + c] = *(uint2*)h4;
        *(uint2*)&g_xcl[(size_t)r * CONVD + c] = *(uint2*)l4;
        x0 = x1; x1 = x2; x2 = x3;
    }
}

// ---------------- SSD pass A via HMMA bf16x3 --------------------------------
#define SA_BH 0
#define SA_BL 4608
#define SA_XH 9216
#define SA_XL 11776
#define SA_END 14336
__global__ void __launch_bounds__(256) k_ssd_a_mma(const float* __restrict__ A_log,
                                                   const float* __restrict__ dtb) {
    __shared__ __align__(16) __nv_bfloat16 smb[SA_END];
    __shared__ float sdt[64], sS[64], ssc[64];
    int tid = threadIdx.x;
    int cid = blockIdx.x;
    int bh = cid >> 6, c = cid & 63;
    int b = bh >> 3, h = bh & 7;
    int r0 = b * LSEQ + c * QC;
    float A = -__expf(A_log[h]);

    if (tid < 64) {
        float v = g_zx[(size_t)(r0 + tid) * DPROJ + 640 + h] + dtb[h];
        v = (v > 20.f) ? v : log1pf(__expf(v));
        sdt[tid] = v;
        g_dtb[(size_t)(r0 + tid) * NH + h] = v;
    }
    // stage B raw (already split)
    for (int i = tid; i < 512; i += 256) {
        int s = i >> 3, q = (i & 7) * 8;
        *(uint4*)&smb[SA_BH + s * 72 + q] =
            *(const uint4*)&g_xch[(size_t)(r0 + s) * CONVD + 256 + q];
        *(uint4*)&smb[SA_BL + s * 72 + q] =
            *(const uint4*)&g_xcl[(size_t)(r0 + s) * CONVD + 256 + q];
    }
    __syncthreads();
    if (tid < 64) {
        float v = sdt[tid] * A;
#pragma unroll
        for (int o = 1; o < 32; o <<= 1) {
            float u = __shfl_up_sync(0xffffffffu, v, o);
            if ((tid & 31) >= o) v += u;
        }
        sS[tid] = v;
    }
    __syncthreads();
    if (tid >= 32 && tid < 64) sS[tid] += sS[31];
    __syncthreads();
    float T = sS[63];
    if (tid < 64) {
        float sv = sS[tid];
        g_S[(size_t)cid * QC + tid] = sv;
        ssc[tid] = __expf(T - sv) * sdt[tid];
    }
    if (tid == 0) g_T[cid] = T;
    __syncthreads();
    // stage scaled X (reconstruct, scale, re-split)
    for (int i = tid; i < 512; i += 256) {
        int s = i >> 3, q = (i & 7) * 4;
        uint2 hv = *(const uint2*)&g_xch[(size_t)(r0 + s) * CONVD + h * HD + q];
        uint2 lv = *(const uint2*)&g_xcl[(size_t)(r0 + s) * CONVD + h * HD + q];
        __nv_bfloat16* hp = (__nv_bfloat16*)&hv;
        __nv_bfloat16* lp = (__nv_bfloat16*)&lv;
        float sc = ssc[s];
        __nv_bfloat16 h4[4], l4[4];
#pragma unroll
        for (int j = 0; j < 4; j++) {
            float xv = (__bfloat162float(hp[j]) + __bfloat162float(lp[j])) * sc;
            split_bf16(xv, h4[j], l4[j]);
        }
        *(uint2*)&smb[SA_XH + s * 40 + q] = *(uint2*)h4;
        *(uint2*)&smb[SA_XL + s * 40 + q] = *(uint2*)l4;
    }
    __syncthreads();

    uint32_t sb = smem_u32(smb);
    int wid = tid >> 5, lane = tid & 31;
    int mw = wid & 1, nw = wid >> 1;
    int gidx = lane >> 3;
    int a_soff = (gidx >> 1) * 8, a_poff = (gidx & 1) * 8;
    int b_soff = ((lane >> 3) & 1) * 8, b_noff = (lane >> 4) * 8;
    float acc[2][4] = {};
#pragma unroll
    for (int kf = 0; kf < 4; kf++) {
        int k0 = kf << 4;
        uint32_t xh4[4], xl4[4], bh4[4], bl4[4];
        uint32_t ax = sb + (uint32_t)((SA_XH + (k0 + a_soff + (lane & 7)) * 40
                                       + mw * 16 + a_poff) * 2);
        LDSM4T(xh4, ax);
        LDSM4T(xl4, ax + (SA_XL - SA_XH) * 2);
        uint32_t bad = sb + (uint32_t)((SA_BH + (k0 + b_soff + (lane & 7)) * 72
                                        + nw * 16 + b_noff) * 2);
        LDSM4T(bh4, bad);
        LDSM4T(bl4, bad + (SA_BL - SA_BH) * 2);
#pragma unroll
        for (int nf = 0; nf < 2; nf++) {
            MMA16816(acc[nf], xh4, bh4[nf * 2], bh4[nf * 2 + 1]);
            MMA16816(acc[nf], xh4, bl4[nf * 2], bl4[nf * 2 + 1]);
            MMA16816(acc[nf], xl4, bh4[nf * 2], bh4[nf * 2 + 1]);
        }
    }
    int g = lane >> 2, tg = lane & 3;
    size_t ub = (size_t)cid * 2048;
#pragma unroll
    for (int nf = 0; nf < 2; nf++) {
        int p = mw * 16 + g, n = nw * 16 + nf * 8 + tg * 2;
#pragma unroll
        for (int e = 0; e < 2; e++) {
            int pp = p + e * 8;
            __nv_bfloat16 h0, l0, h1, l1;
            split_bf16(acc[nf][e * 2 + 0], h0, l0);
            split_bf16(acc[nf][e * 2 + 1], h1, l1);
            __nv_bfloat16 hh[2] = {h0, h1}, ll[2] = {l0, l1};
            *(uint32_t*)&g_Uh[ub + pp * 64 + n] = *(uint32_t*)hh;
            *(uint32_t*)&g_Ul[ub + pp * 64 + n] = *(uint32_t*)ll;
        }
    }
}

// ---------------- SSD pass B: hs = W @ U via HMMA (W computed in-block) -----
#define SB_WH 0
#define SB_WL 4608
#define SB_UH 9216
#define SB_UL 13824
#define SB_END 18432
__global__ void __launch_bounds__(256) k_ssd_b_mma() {
    __shared__ __align__(16) __nv_bfloat16 smb[SB_END];
    __shared__ float sI[64];
    int tid = threadIdx.x, wid = tid >> 5, lane = tid & 31;
    int bh = blockIdx.x;
    int col0 = blockIdx.y * 64;
    if (tid < 64) {
        float v = g_T[bh * 64 + tid];
#pragma unroll
        for (int o = 1; o < 32; o <<= 1) {
            float u = __shfl_up_sync(0xffffffffu, v, o);
            if ((tid & 31) >= o) v += u;
        }
        sI[tid] = v;
    }
    __syncthreads();
    if (tid >= 32 && tid < 64) sI[tid] += sI[31];
    __syncthreads();
    // fill W split
    for (int i = tid; i < 4096; i += 256) {
        int c = i >> 6, j = i & 63;
        float w = (j < c) ? __expf(sI[c - 1] - sI[j]) : 0.f;
        __nv_bfloat16 h, l;
        split_bf16(w, h, l);
        smb[SB_WH + c * 72 + j] = h;
        smb[SB_WL + c * 72 + j] = l;
    }
    // stage U raw
    for (int i = tid; i < 512; i += 256) {
        int j = i >> 3, q = (i & 7) * 8;
        *(uint4*)&smb[SB_UH + j * 72 + q] =
            *(const uint4*)&g_Uh[((size_t)bh * 64 + j) * 2048 + col0 + q];
        *(uint4*)&smb[SB_UL + j * 72 + q] =
            *(const uint4*)&g_Ul[((size_t)bh * 64 + j) * 2048 + col0 + q];
    }
    __syncthreads();
    uint32_t sb = smem_u32(smb);
    int mw = wid & 3, nw = wid >> 2;
    int crow = mw * 16, ncol = nw * 32;
    int lrow = lane & 15, lk = (lane >> 4) << 3;
    int b_soff = ((lane >> 3) & 1) * 8, b_noff = (lane >> 4) * 8;
    float acc[4][4] = {};
#pragma unroll
    for (int kf = 0; kf < 4; kf++) {
        int k0 = kf << 4;
        uint32_t whf[4], wlf[4];
        uint32_t ad = sb + (uint32_t)((SB_WH + (crow + lrow) * 72 + k0 + lk) * 2);
        LDSM4(whf, ad);
        LDSM4(wlf, ad + (SB_WL - SB_WH) * 2);
        uint32_t uh[2][4], ul[2][4];
#pragma unroll
        for (int hf = 0; hf < 2; hf++) {
            uint32_t ad2 = sb + (uint32_t)((SB_UH + (k0 + b_soff + (lane & 7)) * 72
                                            + ncol + hf * 16 + b_noff) * 2);
            LDSM4T(uh[hf], ad2);
            LDSM4T(ul[hf], ad2 + (SB_UL - SB_UH) * 2);
        }
#pragma unroll
        for (int nf = 0; nf < 4; nf++) {
            uint32_t* BH = &uh[nf >> 1][(nf & 1) * 2];
            uint32_t* BL = &ul[nf >> 1][(nf & 1) * 2];
            MMA16816(acc[nf], whf, BH[0], BH[1]);
            MMA16816(acc[nf], whf, BL[0], BL[1]);
            MMA16816(acc[nf], wlf, BH[0], BH[1]);
        }
    }
    int g = lane >> 2, tg = lane & 3;
#pragma unroll
    for (int nf = 0; nf < 4; nf++) {
        int col = col0 + ncol + nf * 8 + tg * 2;
#pragma unroll
        for (int e = 0; e < 2; e++) {
            int c = crow + g + e * 8;
            __nv_bfloat16 h0, l0, h1, l1;
            split_bf16(acc[nf][e * 2 + 0], h0, l0);
            split_bf16(acc[nf][e * 2 + 1], h1, l1);
            __nv_bfloat16 hh[2] = {h0, h1}, ll[2] = {l0, l1};
            *(uint32_t*)&g_hsh[((size_t)bh * 64 + c) * 2048 + col] = *(uint32_t*)hh;
            *(uint32_t*)&g_hsl[((size_t)bh * 64 + c) * 2048 + col] = *(uint32_t*)ll;
        }
    }
}

// ---------------- SSD pass C via HMMA bf16x3 --------------------------------
#define SC_P  72
#define SC_CH 0
#define SC_CL 4608
#define SC_BH 9216
#define SC_BL 13824
#define SC_XH 18432
#define SC_XL 20992
#define SC_HH 23552
#define SC_HL 25856
#define SC_END 28160
__global__ void __launch_bounds__(256, 2) k_ssd_c_mma(const float* __restrict__ Dp) {
    extern __shared__ __align__(16) __nv_bfloat16 smb[];
    float* Ssm = (float*)(smb + SC_END);
    float* dts = Ssm + 64;
    int tid = threadIdx.x, wid = tid >> 5, lane = tid & 31;
    int cid = blockIdx.x;
    int bh = cid >> 6, c = cid & 63;
    int b = bh >> 3, h = bh & 7;
    int r0 = b * LSEQ + c * QC;
    float Dh = Dp[h];

    for (int i = tid; i < 512; i += 256) {
        int s = i >> 3, q = (i & 7) * 8;
        size_t ro = (size_t)(r0 + s) * CONVD;
        *(uint4*)&smb[SC_CH + s * SC_P + q] = *(const uint4*)&g_xch[ro + 320 + q];
        *(uint4*)&smb[SC_CL + s * SC_P + q] = *(const uint4*)&g_xcl[ro + 320 + q];
        *(uint4*)&smb[SC_BH + s * SC_P + q] = *(const uint4*)&g_xch[ro + 256 + q];
        *(uint4*)&smb[SC_BL + s * SC_P + q] = *(const uint4*)&g_xcl[ro + 256 + q];
    }
    for (int i = tid; i < 256; i += 256) {
        int s = i >> 2, q = (i & 3) * 8;
        size_t ro = (size_t)(r0 + s) * CONVD + h * HD;
        *(uint4*)&smb[SC_XH + s * 40 + q] = *(const uint4*)&g_xch[ro + q];
        *(uint4*)&smb[SC_XL + s * 40 + q] = *(const uint4*)&g_xcl[ro + q];
    }
    for (int i = tid; i < 256; i += 256) {
        int p = i >> 3, q = (i & 7) * 8;
        size_t ho = (size_t)cid * 2048 + p * 64 + q;
        *(uint4*)&smb[SC_HH + p * SC_P + q] = *(const uint4*)&g_hsh[ho];
        *(uint4*)&smb[SC_HL + p * SC_P + q] = *(const uint4*)&g_hsl[ho];
    }
    if (tid < 64) {
        Ssm[tid] = g_S[(size_t)cid * QC + tid];
        dts[tid] = g_dtb[(size_t)(r0 + tid) * NH + h];
    }
    __syncthreads();

    uint32_t sb = smem_u32(smb);
    int mw = wid & 3, nw = wid >> 2;
    int arow = mw * 16;
    int lrow = lane & 15, lk = (lane >> 4) << 3;
    int brow = (lane & 7) + ((lane >> 4) & 1) * 8;
    int bk = ((lane >> 3) & 1) << 3;
    int b_soff = ((lane >> 3) & 1) * 8, b_noff = (lane >> 4) * 8;

    float accg[4][4] = {};
#pragma unroll
    for (int kf = 0; kf < 4; kf++) {
        int k0 = kf << 4;
        uint32_t ch[4], cl[4];
        uint32_t ad = sb + (uint32_t)(((arow + lrow) * SC_P + k0 + lk) * 2);
        LDSM4(ch, ad + SC_CH * 2);
        LDSM4(cl, ad + SC_CL * 2);
        uint32_t bh2[2][4], bl2[2][4];
#pragma unroll
        for (int ng = 0; ng < 2; ng++) {
            uint32_t ad2 = sb + (uint32_t)(((nw * 32 + ng * 16 + brow) * SC_P + k0 + bk) * 2);
            LDSM4(bh2[ng], ad2 + SC_BH * 2);
            LDSM4(bl2[ng], ad2 + SC_BL * 2);
        }
#pragma unroll
        for (int nf = 0; nf < 4; nf++) {
            uint32_t* BH = &bh2[nf >> 1][(nf & 1) * 2];
            uint32_t* BL = &bl2[nf >> 1][(nf & 1) * 2];
            MMA16816(accg[nf], ch, BH[0], BH[1]);
            MMA16816(accg[nf], ch, BL[0], BL[1]);
            MMA16816(accg[nf], cl, BH[0], BH[1]);
        }
    }
    __syncthreads();

    int g = lane >> 2, tg = lane & 3;
    int t0 = arow + g, t1 = arow + g + 8;
    float St0 = Ssm[t0], St1 = Ssm[t1];
#pragma unroll
    for (int nf = 0; nf < 4; nf++) {
#pragma unroll
        for (int e = 0; e < 2; e++) {
            int s = nw * 32 + nf * 8 + tg * 2 + e;
            float ds = dts[s], Ss = Ssm[s];
            float m0 = (s <= t0) ? accg[nf][e]     * __expf(St0 - Ss) * ds : 0.f;
            float m1 = (s <= t1) ? accg[nf][2 + e] * __expf(St1 - Ss) * ds : 0.f;
            __nv_bfloat16 hh0, ll0, hh1, ll1;
            split_bf16(m0, hh0, ll0);
            split_bf16(m1, hh1, ll1);
            smb[SC_BH + t0 * SC_P + s] = hh0;
            smb[SC_BL + t0 * SC_P + s] = ll0;
            smb[SC_BH + t1 * SC_P + s] = hh1;
            smb[SC_BL + t1 * SC_P + s] = ll1;
        }
    }
    __syncthreads();

    int pw = wid >> 2;
    int prow = pw * 16;
    float ayi[2][4] = {}, ayo[2][4] = {};
#pragma unroll
    for (int kf = 0; kf < 4; kf++) {
        int k0 = kf << 4;
        uint32_t ad = sb + (uint32_t)(((arow + lrow) * SC_P + k0 + lk) * 2);
        uint32_t mh[4], ml[4], ch[4], cl[4];
        LDSM4(mh, ad + SC_BH * 2);
        LDSM4(ml, ad + SC_BL * 2);
        LDSM4(ch, ad + SC_CH * 2);
        LDSM4(cl, ad + SC_CL * 2);
        uint32_t xh[4], xl[4], hh2[4], hl2[4];
        uint32_t adx = sb + (uint32_t)((SC_XH + (k0 + b_soff + (lane & 7)) * 40
                                        + prow + b_noff) * 2);
        LDSM4T(xh, adx);
        LDSM4T(xl, adx + (SC_XL - SC_XH) * 2);
        uint32_t adh = sb + (uint32_t)(((prow + brow) * SC_P + k0 + bk) * 2);
        LDSM4(hh2, adh + SC_HH * 2);
        LDSM4(hl2, adh + SC_HL * 2);
#pragma unroll
        for (int nf = 0; nf < 2; nf++) {
            uint32_t* XH = &xh[nf * 2];  uint32_t* XL = &xl[nf * 2];
            uint32_t* HH = &hh2[nf * 2]; uint32_t* HL = &hl2[nf * 2];
            MMA16816(ayi[nf], mh, XH[0], XH[1]);
            MMA16816(ayi[nf], mh, XL[0], XL[1]);
            MMA16816(ayi[nf], ml, XH[0], XH[1]);
            MMA16816(ayo[nf], ch, HH[0], HH[1]);
            MMA16816(ayo[nf], ch, HL[0], HL[1]);
            MMA16816(ayo[nf], cl, HH[0], HH[1]);
        }
    }

    float eS0 = __expf(St0), eS1 = __expf(St1);
#pragma unroll
    for (int nf = 0; nf < 2; nf++) {
        int p = prow + nf * 8 + tg * 2;
        float xv00 = __bfloat162float(smb[SC_XH + t0 * 40 + p])
                   + __bfloat162float(smb[SC_XL + t0 * 40 + p]);
        float xv01 = __bfloat162float(smb[SC_XH + t0 * 40 + p + 1])
                   + __bfloat162float(smb[SC_XL + t0 * 40 + p + 1]);
        float xv10 = __bfloat162float(smb[SC_XH + t1 * 40 + p])
                   + __bfloat162float(smb[SC_XL + t1 * 40 + p]);
        float xv11 = __bfloat162float(smb[SC_XH + t1 * 40 + p + 1])
                   + __bfloat162float(smb[SC_XL + t1 * 40 + p + 1]);
        *(float2*)&g_y[(size_t)(r0 + t0) * DINNER + h * HD + p] =
            make_float2(ayi[nf][0] + eS0 * ayo[nf][0] + Dh * xv00,
                        ayi[nf][1] + eS0 * ayo[nf][1] + Dh * xv01);
        *(float2*)&g_y[(size_t)(r0 + t1) * DINNER + h * HD + p] =
            make_float2(ayi[nf][2] + eS1 * ayo[nf][2] + Dh * xv10,
                        ayi[nf][3] + eS1 * ayo[nf][3] + Dh * xv11);
    }
}

// ---------------- K4: fused gate + gated RMSNorm + out_proj + residual ------
#define OP_AH 0
#define OP_AL 17408
#define OP_BH 34816
#define OP_BL 52224
#define OP_TOT 69632
__global__ void __launch_bounds__(256, 1) k_outproj_mma(const float* __restrict__ x,
                                                        const float* __restrict__ gw,
                                                        float* __restrict__ out) {
    extern __shared__ __align__(16) __nv_bfloat16 smb[];
    float* srow = (float*)(smb + OP_TOT);  // [128] per-row rms scales
    int tid = threadIdx.x, wid = tid >> 5, lane = tid & 31;
    int rowBase = blockIdx.x * 128;
    uint32_t sb = smem_u32(smb);

    // --- pre-phase: per-row gated-RMS scale (each warp: 16 rows) ---
    for (int rr = 0; rr < 16; rr++) {
        int r = rowBase + wid * 16 + rr;
        float4 y0 = *(const float4*)&g_y[(size_t)r * DINNER + lane * 4];
        float4 y1 = *(const float4*)&g_y[(size_t)r * DINNER + 128 + lane * 4];
        float4 z0 = *(const float4*)&g_zx[(size_t)r * DPROJ + lane * 4];
        float4 z1 = *(const float4*)&g_zx[(size_t)r * DPROJ + 128 + lane * 4];
        float g0 = y0.x * silu(z0.x), g1 = y0.y * silu(z0.y);
        float g2 = y0.z * silu(z0.z), g3 = y0.w * silu(z0.w);
        float g4 = y1.x * silu(z1.x), g5 = y1.y * silu(z1.y);
        float g6 = y1.z * silu(z1.z), g7 = y1.w * silu(z1.w);
        float ss = g0 * g0 + g1 * g1 + g2 * g2 + g3 * g3
                 + g4 * g4 + g5 * g5 + g6 * g6 + g7 * g7;
#pragma unroll
        for (int o = 16; o; o >>= 1) ss += __shfl_xor_sync(0xffffffffu, ss, o);
        if (lane == 0)
            srow[wid * 16 + rr] = rsqrtf(ss * (1.f / DINNER) + 1e-5f);
    }
    __syncthreads();

    int mw = wid & 3, nw = wid >> 2;
    int arow = mw * 32, ncol = nw * 64;
    float acc[2][8][4] = {};
    int lrow = lane & 15, lk = (lane >> 4) << 3;
    int brow = (lane & 7) + ((lane >> 4) & 1) * 8;
    int bk = ((lane >> 3) & 1) << 3;

    for (int kc = 0; kc < 2; kc++) {
        if (kc) __syncthreads();
        // stage A: recompute gate, scale, split
        for (int i = tid; i < 2048; i += 256) {
            int r = i >> 4, c = (i & 15) << 3;
            int gr = rowBase + r;
            int gc = kc * 128 + c;
            float4 y0 = *(const float4*)&g_y[(size_t)gr * DINNER + gc];
            float4 y1 = *(const float4*)&g_y[(size_t)gr * DINNER + gc + 4];
            float4 z0 = *(const float4*)&g_zx[(size_t)gr * DPROJ + gc];
            float4 z1 = *(const float4*)&g_zx[(size_t)gr * DPROJ + gc + 4];
            float4 w0 = *(const float4*)&gw[gc];
            float4 w1 = *(const float4*)&gw[gc + 4];
            float sc = srow[r];
            float4 v0, v1;
            v0.x = y0.x * silu(z0.x) * sc * w0.x;
            v0.y = y0.y * silu(z0.y) * sc * w0.y;
            v0.z = y0.z * silu(z0.z) * sc * w0.z;
            v0.w = y0.w * silu(z0.w) * sc * w0.w;
            v1.x = y1.x * silu(z1.x) * sc * w1.x;
            v1.y = y1.y * silu(z1.y) * sc * w1.y;
            v1.z = y1.z * silu(z1.z) * sc * w1.z;
            v1.w = y1.w * silu(z1.w) * sc * w1.w;
            __nv_bfloat16 h8[8], l8[8];
            split4(v0, h8, l8);
            split4(v1, h8 + 4, l8 + 4);
            *(uint4*)&smb[OP_AH + r * 136 + c] = *(uint4*)h8;
            *(uint4*)&smb[OP_AL + r * 136 + c] = *(uint4*)l8;
            size_t bo = (size_t)r * DINNER + kc * 128 + c;
            *(uint4*)&smb[OP_BH + r * 136 + c] = *(const uint4*)(g_woh + bo);
            *(uint4*)&smb[OP_BL + r * 136 + c] = *(const uint4*)(g_wol + bo);
        }
        __syncthreads();
#pragma unroll
        for (int kf = 0; kf < 8; kf++) {
            int k0 = kf << 4;
            uint32_t ah[2][4], al[2][4];
#pragma unroll
            for (int mi = 0; mi < 2; mi++) {
                uint32_t ad = sb + (uint32_t)(((arow + mi * 16 + lrow) * 136 + k0 + lk) * 2);
                LDSM4(ah[mi], ad + OP_AH * 2);
                LDSM4(al[mi], ad + OP_AL * 2);
            }
            uint32_t bh[4][4], bl[4][4];
#pragma unroll
            for (int ng = 0; ng < 4; ng++) {
                uint32_t ad = sb + (uint32_t)(((ncol + ng * 16 + brow) * 136 + k0 + bk) * 2);
                LDSM4(bh[ng], ad + OP_BH * 2);
                LDSM4(bl[ng], ad + OP_BL * 2);
            }
#pragma unroll
            for (int mi = 0; mi < 2; mi++)
#pragma unroll
                for (int nf = 0; nf < 8; nf++) {
                    uint32_t* BH = &bh[nf >> 1][(nf & 1) * 2];
                    uint32_t* BL = &bl[nf >> 1][(nf & 1) * 2];
                    MMA16816(acc[mi][nf], ah[mi], BH[0], BH[1]);
                    MMA16816(acc[mi][nf], ah[mi], BL[0], BL[1]);
                    MMA16816(acc[mi][nf], al[mi], BH[0], BH[1]);
                }
        }
    }
    int g = lane >> 2, tg = lane & 3;
#pragma unroll
    for (int mi = 0; mi < 2; mi++) {
        int r = rowBase + arow + mi * 16 + g;
#pragma unroll
        for (int nf = 0; nf < 8; nf++) {
            int c = ncol + nf * 8 + tg * 2;
            float2 x0 = *(const float2*)&x[(size_t)r * DMODEL + c];
            float2 x1 = *(const float2*)&x[(size_t)(r + 8) * DMODEL + c];
            *(float2*)&out[(size_t)r * DMODEL + c] =
                make_float2(acc[mi][nf][0] + x0.x, acc[mi][nf][1] + x0.y);
            *(float2*)&out[(size_t)(r + 8) * DMODEL + c] =
                make_float2(acc[mi][nf][2] + x1.x, acc[mi][nf][3] + x1.y);
        }
    }
}

extern "C" void kernel_launch(void* const* d_in, const int* in_sizes, int n_in,
                              void* d_out, int out_size) {
    const float* x          = (const float*)d_in[0];
    const float* norm_w     = (const float*)d_in[1];
    const float* in_proj_w  = (const float*)d_in[2];
    const float* conv_w     = (const float*)d_in[3];
    const float* conv_b     = (const float*)d_in[4];
    const float* dt_bias    = (const float*)d_in[5];
    const float* A_log      = (const float*)d_in[6];
    const float* D          = (const float*)d_in[7];
    const float* gnorm_w    = (const float*)d_in[8];
    const float* out_proj_w = (const float*)d_in[9];
    float* out = (float*)d_out;

    const int in_smem   = IP_TOT * 2;
    const int out_smem  = OP_TOT * 2 + 512;
    const int ssdc_smem = SC_END * 2 + 512;
    cudaFuncSetAttribute(k_inproj_mma,  cudaFuncAttributeMaxDynamicSharedMemorySize, in_smem);
    cudaFuncSetAttribute(k_outproj_mma, cudaFuncAttributeMaxDynamicSharedMemorySize, out_smem);
    cudaFuncSetAttribute(k_ssd_c_mma,   cudaFuncAttributeMaxDynamicSharedMemorySize, ssdc_smem);

    k_wsplit<<<113, 256>>>(in_proj_w, out_proj_w);
    k_rmsnorm<<<RTOT / 8, 256>>>(x, norm_w);
    k_inproj_mma<<<dim3(RTOT / 128, 7), 256, in_smem>>>();
    k_conv4<<<RTOT / 32, 384>>>(conv_w, conv_b);
    k_ssd_a_mma<<<NCID, 256>>>(A_log, dt_bias);
    k_ssd_b_mma<<<dim3(NBATCH * NH, 32), 256>>>();
    k_ssd_c_mma<<<NCID, 256, ssdc_smem>>>(D);
    k_outproj_mma<<<RTOT / 128, 256, out_smem>>>(x, gnorm_w, out);
}

// round 10
// speedup vs baseline: 1.1219x; 1.1219x over previous
#include <cuda_runtime.h>
#include <cuda_bf16.h>
#include <cstdint>

#define RTOT   32768
#define LSEQ   4096
#define NBATCH 8
#define DMODEL 128
#define DPROJ  648
#define DINNER 256
#define CONVD  384
#define NH     8
#define HD     32
#define QC     64
#define NCHK   (LSEQ/QC)
#define NCID   (NBATCH*NH*NCHK)

// ---------------- scratch (device globals) ----------------------------------
__device__ __align__(16) float g_zx [(size_t)RTOT * DPROJ];
__device__ __align__(16) float g_xc [RTOT * CONVD];
__device__ __align__(16) float g_dtb[RTOT * NH];
__device__ __align__(16) float g_y  [RTOT * DINNER];
__device__ __align__(16) float g_U  [(size_t)NCID * 2048];
__device__ __align__(16) float g_hs [(size_t)NCID * 2048];
__device__ __align__(16) float g_S  [(size_t)NCID * QC];
__device__ __align__(16) float g_T  [NCID];
__device__ __align__(16) __nv_bfloat16 g_ah [RTOT * DMODEL];
__device__ __align__(16) __nv_bfloat16 g_al [RTOT * DMODEL];
__device__ __align__(16) __nv_bfloat16 g_wih[672 * DMODEL];
__device__ __align__(16) __nv_bfloat16 g_wil[672 * DMODEL];
__device__ __align__(16) __nv_bfloat16 g_gh [RTOT * DINNER];
__device__ __align__(16) __nv_bfloat16 g_gl [RTOT * DINNER];
__device__ __align__(16) __nv_bfloat16 g_woh[DMODEL * DINNER];
__device__ __align__(16) __nv_bfloat16 g_wol[DMODEL * DINNER];
__device__ __align__(16) __nv_bfloat16 g_wbh[64 * 4096];   // chunk-scan W hi
__device__ __align__(16) __nv_bfloat16 g_wbl[64 * 4096];   // chunk-scan W lo
// -----------------------------------------------------------------------------

// ---- warp MMA helpers ----
static __device__ __forceinline__ uint32_t smem_u32(const void* p) {
    uint32_t a;
    asm("{ .reg .u64 t; cvta.to.shared.u64 t, %1; cvt.u32.u64 %0, t; }"
        : "=r"(a) : "l"(p));
    return a;
}
#define LDSM4(r, addr) \
    asm volatile("ldmatrix.sync.aligned.m8n8.x4.shared.b16 {%0,%1,%2,%3}, [%4];" \
        : "=r"((r)[0]), "=r"((r)[1]), "=r"((r)[2]), "=r"((r)[3]) : "r"(addr))
#define LDSM4T(r, addr) \
    asm volatile("ldmatrix.sync.aligned.m8n8.x4.trans.shared.b16 {%0,%1,%2,%3}, [%4];" \
        : "=r"((r)[0]), "=r"((r)[1]), "=r"((r)[2]), "=r"((r)[3]) : "r"(addr))
#define MMA16816(d, a, b0, b1) \
    asm volatile("mma.sync.aligned.m16n8k16.row.col.f32.bf16.bf16.f32 " \
        "{%0,%1,%2,%3}, {%4,%5,%6,%7}, {%8,%9}, {%0,%1,%2,%3};" \
        : "+f"((d)[0]), "+f"((d)[1]), "+f"((d)[2]), "+f"((d)[3]) \
        : "r"((a)[0]), "r"((a)[1]), "r"((a)[2]), "r"((a)[3]), "r"(b0), "r"(b1))

static __device__ __forceinline__ void split_bf16(float v, __nv_bfloat16& h,
                                                  __nv_bfloat16& l) {
    h = __float2bfloat16(v);
    l = __float2bfloat16(v - __bfloat162float(h));
}
static __device__ __forceinline__ void split4(float4 v, __nv_bfloat16* h,
                                              __nv_bfloat16* l) {
    split_bf16(v.x, h[0], l[0]); split_bf16(v.y, h[1], l[1]);
    split_bf16(v.z, h[2], l[2]); split_bf16(v.w, h[3], l[3]);
}
static __device__ __forceinline__ float silu(float v) {
    return v / (1.f + __expf(-v));
}

// ---------------- K_w: one-shot weight split -------------------------------
__global__ void k_wsplit(const float* __restrict__ Wi, const float* __restrict__ Wo) {
    int idx = blockIdx.x * 256 + threadIdx.x;
    const int NWI = DPROJ * DMODEL / 4;
    const int NWO = DMODEL * DINNER / 4;
    if (idx < NWI) {
        float4 v = ((const float4*)Wi)[idx];
        __nv_bfloat16 h[4], l[4];
        split4(v, h, l);
        ((uint2*)g_wih)[idx] = *(uint2*)h;
        ((uint2*)g_wil)[idx] = *(uint2*)l;
    } else if (idx < NWI + NWO) {
        int j = idx - NWI;
        float4 v = ((const float4*)Wo)[j];
        __nv_bfloat16 h[4], l[4];
        split4(v, h, l);
        ((uint2*)g_woh)[j] = *(uint2*)h;
        ((uint2*)g_wol)[j] = *(uint2*)l;
    }
}

// ---------------- K0: RMSNorm -> bf16 hi/lo splits --------------------------
__global__ void k_rmsnorm(const float* __restrict__ x, const float* __restrict__ w) {
    int row  = blockIdx.x * 8 + (threadIdx.x >> 5);
    int lane = threadIdx.x & 31;
    float4 v = ((const float4*)(x + (size_t)row * DMODEL))[lane];
    float ss = v.x * v.x + v.y * v.y + v.z * v.z + v.w * v.w;
#pragma unroll
    for (int o = 16; o; o >>= 1) ss += __shfl_xor_sync(0xffffffffu, ss, o);
    float sc = rsqrtf(ss * (1.f / DMODEL) + 1e-5f);
    float4 wv = ((const float4*)w)[lane];
    float4 o4;
    o4.x = v.x * sc * wv.x; o4.y = v.y * sc * wv.y;
    o4.z = v.z * sc * wv.z; o4.w = v.w * sc * wv.w;
    __nv_bfloat16 h[4], l[4];
    split4(o4, h, l);
    ((uint2*)(g_ah + (size_t)row * DMODEL))[lane] = *(uint2*)h;
    ((uint2*)(g_al + (size_t)row * DMODEL))[lane] = *(uint2*)l;
}

// ---------------- K1: in_proj GEMM via HMMA bf16x3, tile 128x96, K=128 ------
#define IP_AH 0
#define IP_AL 17408
#define IP_BH 34816
#define IP_BL 47872
#define IP_TOT 60928
__global__ void __launch_bounds__(256, 1) k_inproj_mma() {
    extern __shared__ __align__(16) __nv_bfloat16 smb[];
    int tid = threadIdx.x, wid = tid >> 5, lane = tid & 31;
    int rowBase = blockIdx.x * 128;
    int colBase = blockIdx.y * 96;

    for (int i = tid; i < 2048; i += 256) {
        int r = i >> 4, c = (i & 15) << 3;
        *(uint4*)&smb[IP_AH + r * 136 + c] =
            *(const uint4*)(g_ah + (size_t)(rowBase + r) * DMODEL + c);
        *(uint4*)&smb[IP_AL + r * 136 + c] =
            *(const uint4*)(g_al + (size_t)(rowBase + r) * DMODEL + c);
    }
    for (int i = tid; i < 1536; i += 256) {
        int r = i >> 4, c = (i & 15) << 3;
        *(uint4*)&smb[IP_BH + r * 136 + c] =
            *(const uint4*)(g_wih + (size_t)(colBase + r) * DMODEL + c);
        *(uint4*)&smb[IP_BL + r * 136 + c] =
            *(const uint4*)(g_wil + (size_t)(colBase + r) * DMODEL + c);
    }
    __syncthreads();

    uint32_t sb = smem_u32(smb);
    int mw = wid & 3, nw = wid >> 2;
    int arow = mw * 32, ncol = nw * 48;
    float acc[2][6][4] = {};
    int lrow = lane & 15, lk = (lane >> 4) << 3;
    int brow = (lane & 7) + ((lane >> 4) & 1) * 8;
    int bk = ((lane >> 3) & 1) << 3;
#pragma unroll
    for (int kf = 0; kf < 8; kf++) {
        int k0 = kf << 4;
        uint32_t ah[2][4], al[2][4];
#pragma unroll
        for (int mi = 0; mi < 2; mi++) {
            uint32_t ad = sb + (uint32_t)(((arow + mi * 16 + lrow) * 136 + k0 + lk) * 2);
            LDSM4(ah[mi], ad + IP_AH * 2);
            LDSM4(al[mi], ad + IP_AL * 2);
        }
        uint32_t bh[3][4], bl[3][4];
#pragma unroll
        for (int ng = 0; ng < 3; ng++) {
            uint32_t ad = sb + (uint32_t)(((ncol + ng * 16 + brow) * 136 + k0 + bk) * 2);
            LDSM4(bh[ng], ad + IP_BH * 2);
            LDSM4(bl[ng], ad + IP_BL * 2);
        }
#pragma unroll
        for (int mi = 0; mi < 2; mi++)
#pragma unroll
            for (int nf = 0; nf < 6; nf++) {
                uint32_t* BH = &bh[nf >> 1][(nf & 1) * 2];
                uint32_t* BL = &bl[nf >> 1][(nf & 1) * 2];
                MMA16816(acc[mi][nf], ah[mi], BH[0], BH[1]);
                MMA16816(acc[mi][nf], ah[mi], BL[0], BL[1]);
                MMA16816(acc[mi][nf], al[mi], BH[0], BH[1]);
            }
    }
    int g = lane >> 2, tg = lane & 3;
#pragma unroll
    for (int mi = 0; mi < 2; mi++) {
        int r = rowBase + arow + mi * 16 + g;
#pragma unroll
        for (int nf = 0; nf < 6; nf++) {
            int c = colBase + ncol + nf * 8 + tg * 2;
            if (c < DPROJ) {
                *(float2*)&g_zx[(size_t)r * DPROJ + c] =
                    make_float2(acc[mi][nf][0], acc[mi][nf][1]);
                *(float2*)&g_zx[(size_t)(r + 8) * DPROJ + c] =
                    make_float2(acc[mi][nf][2], acc[mi][nf][3]);
            }
        }
    }
}

// ---------------- K2: conv(K=4)+SiLU, float4 sliding-window -----------------
// block 384: tid%96 -> channel quad, tid/96 -> 4-row strip of a 16-row chunk;
// grid 2048 (16 rows per block) for higher occupancy / more MLP.
__global__ void __launch_bounds__(384) k_conv4(const float* __restrict__ cw,
                                               const float* __restrict__ cb) {
    int t = threadIdx.x;
    int c = (t % 96) * 4;
    int r0 = blockIdx.x * 16 + (t / 96) * 4;
    bool hist = (r0 & (LSEQ - 1)) != 0;
    float4 wA = *(const float4*)&cw[(c + 0) * 4];
    float4 wB = *(const float4*)&cw[(c + 1) * 4];
    float4 wC = *(const float4*)&cw[(c + 2) * 4];
    float4 wD = *(const float4*)&cw[(c + 3) * 4];
    float4 bias = *(const float4*)&cb[c];
    const float* src = g_zx + 256 + c;
    float* dst = g_xc + c;
    float4 z = make_float4(0.f, 0.f, 0.f, 0.f);
    float4 x0 = hist ? *(const float4*)&src[(size_t)(r0 - 3) * DPROJ] : z;
    float4 x1 = hist ? *(const float4*)&src[(size_t)(r0 - 2) * DPROJ] : z;
    float4 x2 = hist ? *(const float4*)&src[(size_t)(r0 - 1) * DPROJ] : z;
#pragma unroll
    for (int s = 0; s < 4; s++) {
        int r = r0 + s;
        float4 x3 = *(const float4*)&src[(size_t)r * DPROJ];
        float4 o;
        o.x = silu(bias.x + wA.x * x0.x + wA.y * x1.x + wA.z * x2.x + wA.w * x3.x);
        o.y = silu(bias.y + wB.x * x0.y + wB.y * x1.y + wB.z * x2.y + wB.w * x3.y);
        o.z = silu(bias.z + wC.x * x0.z + wC.y * x1.z + wC.z * x2.z + wC.w * x3.z);
        o.w = silu(bias.w + wD.x * x0.w + wD.y * x1.w + wD.z * x2.w + wD.w * x3.w);
        *(float4*)&dst[(size_t)r * CONVD] = o;
        x0 = x1; x1 = x2; x2 = x3;
    }
}

// ---------------- SSD pass A via HMMA bf16x3 --------------------------------
#define SA_BH 0
#define SA_BL 4608
#define SA_XH 9216
#define SA_XL 11776
#define SA_END 14336
__global__ void __launch_bounds__(256) k_ssd_a_mma(const float* __restrict__ A_log,
                                                   const float* __restrict__ dtb) {
    __shared__ __align__(16) __nv_bfloat16 smb[SA_END];
    __shared__ float sdt[64], sS[64], ssc[64];
    int tid = threadIdx.x;
    int cid = blockIdx.x;
    int bh = cid >> 6, c = cid & 63;
    int b = bh >> 3, h = bh & 7;
    int r0 = b * LSEQ + c * QC;
    float A = -__expf(A_log[h]);

    if (tid < 64) {
        float v = g_zx[(size_t)(r0 + tid) * DPROJ + 640 + h] + dtb[h];
        v = (v > 20.f) ? v : log1pf(__expf(v));
        sdt[tid] = v;
        g_dtb[(size_t)(r0 + tid) * NH + h] = v;
    }
    for (int i = tid; i < 1024; i += 256) {
        int s = i >> 4, q = (i & 15) * 4;
        float4 bv = *(const float4*)&g_xc[(size_t)(r0 + s) * CONVD + 256 + q];
        __nv_bfloat16 h4[4], l4[4];
        split4(bv, h4, l4);
        *(uint2*)&smb[SA_BH + s * 72 + q] = *(uint2*)h4;
        *(uint2*)&smb[SA_BL + s * 72 + q] = *(uint2*)l4;
    }
    __syncthreads();
    if (tid < 64) {
        float v = sdt[tid] * A;
#pragma unroll
        for (int o = 1; o < 32; o <<= 1) {
            float u = __shfl_up_sync(0xffffffffu, v, o);
            if ((tid & 31) >= o) v += u;
        }
        sS[tid] = v;
    }
    __syncthreads();
    if (tid >= 32 && tid < 64) sS[tid] += sS[31];
    __syncthreads();
    float T = sS[63];
    if (tid < 64) {
        float sv = sS[tid];
        g_S[(size_t)cid * QC + tid] = sv;
        ssc[tid] = __expf(T - sv) * sdt[tid];
    }
    if (tid == 0) g_T[cid] = T;
    __syncthreads();
    for (int i = tid; i < 512; i += 256) {
        int s = i >> 3, q = (i & 7) * 4;
        float4 v = *(const float4*)&g_xc[(size_t)(r0 + s) * CONVD + h * HD + q];
        float sc = ssc[s];
        v.x *= sc; v.y *= sc; v.z *= sc; v.w *= sc;
        __nv_bfloat16 h4[4], l4[4];
        split4(v, h4, l4);
        *(uint2*)&smb[SA_XH + s * 40 + q] = *(uint2*)h4;
        *(uint2*)&smb[SA_XL + s * 40 + q] = *(uint2*)l4;
    }
    __syncthreads();

    uint32_t sb = smem_u32(smb);
    int wid = tid >> 5, lane = tid & 31;
    int mw = wid & 1, nw = wid >> 1;
    int gidx = lane >> 3;
    int a_soff = (gidx >> 1) * 8, a_poff = (gidx & 1) * 8;
    int b_soff = ((lane >> 3) & 1) * 8, b_noff = (lane >> 4) * 8;
    float acc[2][4] = {};
#pragma unroll
    for (int kf = 0; kf < 4; kf++) {
        int k0 = kf << 4;
        uint32_t xh4[4], xl4[4], bh4[4], bl4[4];
        uint32_t ax = sb + (uint32_t)((SA_XH + (k0 + a_soff + (lane & 7)) * 40
                                       + mw * 16 + a_poff) * 2);
        LDSM4T(xh4, ax);
        LDSM4T(xl4, ax + (SA_XL - SA_XH) * 2);
        uint32_t bad = sb + (uint32_t)((SA_BH + (k0 + b_soff + (lane & 7)) * 72
                                        + nw * 16 + b_noff) * 2);
        LDSM4T(bh4, bad);
        LDSM4T(bl4, bad + (SA_BL - SA_BH) * 2);
#pragma unroll
        for (int nf = 0; nf < 2; nf++) {
            MMA16816(acc[nf], xh4, bh4[nf * 2], bh4[nf * 2 + 1]);
            MMA16816(acc[nf], xh4, bl4[nf * 2], bl4[nf * 2 + 1]);
            MMA16816(acc[nf], xl4, bh4[nf * 2], bh4[nf * 2 + 1]);
        }
    }
    int g = lane >> 2, tg = lane & 3;
    size_t ub = (size_t)cid * 2048;
#pragma unroll
    for (int nf = 0; nf < 2; nf++) {
        int p = mw * 16 + g, n = nw * 16 + nf * 8 + tg * 2;
        *(float2*)&g_U[ub + p * 64 + n]       = make_float2(acc[nf][0], acc[nf][1]);
        *(float2*)&g_U[ub + (p + 8) * 64 + n] = make_float2(acc[nf][2], acc[nf][3]);
    }
}

// ---------------- SSD pass B step 1: decay matrix W per (b,h) ---------------
__global__ void k_ssd_w() {
    __shared__ float sI[64];
    int bh = blockIdx.x, tid = threadIdx.x;
    if (tid < 64) {
        float v = g_T[bh * 64 + tid];
#pragma unroll
        for (int o = 1; o < 32; o <<= 1) {
            float u = __shfl_up_sync(0xffffffffu, v, o);
            if ((tid & 31) >= o) v += u;
        }
        sI[tid] = v;
    }
    __syncthreads();
    if (tid >= 32 && tid < 64) sI[tid] += sI[31];
    __syncthreads();
    for (int i = tid; i < 4096; i += 256) {
        int c = i >> 6, j = i & 63;
        float w = (j < c) ? __expf(sI[c - 1] - sI[j]) : 0.f;
        __nv_bfloat16 h, l;
        split_bf16(w, h, l);
        g_wbh[(size_t)bh * 4096 + i] = h;
        g_wbl[(size_t)bh * 4096 + i] = l;
    }
}

// ---------------- SSD pass B step 2: hs = W @ U via HMMA bf16x3 -------------
#define SB_WH 0
#define SB_WL 4608
#define SB_UH 9216
#define SB_UL 13824
#define SB_END 18432
__global__ void __launch_bounds__(256) k_ssd_b_mma() {
    __shared__ __align__(16) __nv_bfloat16 smb[SB_END];
    int tid = threadIdx.x, wid = tid >> 5, lane = tid & 31;
    int bh = blockIdx.x;
    int col0 = blockIdx.y * 64;
    for (int i = tid; i < 512; i += 256) {
        int c = i >> 3, q = (i & 7) * 8;
        *(uint4*)&smb[SB_WH + c * 72 + q] =
            *(const uint4*)&g_wbh[(size_t)bh * 4096 + c * 64 + q];
        *(uint4*)&smb[SB_WL + c * 72 + q] =
            *(const uint4*)&g_wbl[(size_t)bh * 4096 + c * 64 + q];
    }
    for (int i = tid; i < 1024; i += 256) {
        int j = i >> 4, q = (i & 15) * 4;
        float4 v = *(const float4*)&g_U[((size_t)bh * 64 + j) * 2048 + col0 + q];
        __nv_bfloat16 h4[4], l4[4];
        split4(v, h4, l4);
        *(uint2*)&smb[SB_UH + j * 72 + q] = *(uint2*)h4;
        *(uint2*)&smb[SB_UL + j * 72 + q] = *(uint2*)l4;
    }
    __syncthreads();
    uint32_t sb = smem_u32(smb);
    int mw = wid & 3, nw = wid >> 2;
    int crow = mw * 16, ncol = nw * 32;
    int lrow = lane & 15, lk = (lane >> 4) << 3;
    int b_soff = ((lane >> 3) & 1) * 8, b_noff = (lane >> 4) * 8;
    float acc[4][4] = {};
#pragma unroll
    for (int kf = 0; kf < 4; kf++) {
        int k0 = kf << 4;
        uint32_t whf[4], wlf[4];
        uint32_t ad = sb + (uint32_t)((SB_WH + (crow + lrow) * 72 + k0 + lk) * 2);
        LDSM4(whf, ad);
        LDSM4(wlf, ad + (SB_WL - SB_WH) * 2);
        uint32_t uh[2][4], ul[2][4];
#pragma unroll
        for (int hf = 0; hf < 2; hf++) {
            uint32_t ad2 = sb + (uint32_t)((SB_UH + (k0 + b_soff + (lane & 7)) * 72
                                            + ncol + hf * 16 + b_noff) * 2);
            LDSM4T(uh[hf], ad2);
            LDSM4T(ul[hf], ad2 + (SB_UL - SB_UH) * 2);
        }
#pragma unroll
        for (int nf = 0; nf < 4; nf++) {
            uint32_t* BH = &uh[nf >> 1][(nf & 1) * 2];
            uint32_t* BL = &ul[nf >> 1][(nf & 1) * 2];
            MMA16816(acc[nf], whf, BH[0], BH[1]);
            MMA16816(acc[nf], whf, BL[0], BL[1]);
            MMA16816(acc[nf], wlf, BH[0], BH[1]);
        }
    }
    int g = lane >> 2, tg = lane & 3;
#pragma unroll
    for (int nf = 0; nf < 4; nf++) {
        int c = crow + g, col = col0 + ncol + nf * 8 + tg * 2;
        *(float2*)&g_hs[((size_t)bh * 64 + c) * 2048 + col] =
            make_float2(acc[nf][0], acc[nf][1]);
        *(float2*)&g_hs[((size_t)bh * 64 + c + 8) * 2048 + col] =
            make_float2(acc[nf][2], acc[nf][3]);
    }
}

// ---------------- SSD pass C via HMMA bf16x3 --------------------------------
#define SC_P  72
#define SC_CH 0
#define SC_CL 4608
#define SC_BH 9216
#define SC_BL 13824
#define SC_XH 18432
#define SC_XL 20992
#define SC_HH 23552
#define SC_HL 25856
#define SC_END 28160
__global__ void __launch_bounds__(256, 2) k_ssd_c_mma(const float* __restrict__ Dp) {
    extern __shared__ __align__(16) __nv_bfloat16 smb[];
    float* Ssm = (float*)(smb + SC_END);
    float* dts = Ssm + 64;
    int tid = threadIdx.x, wid = tid >> 5, lane = tid & 31;
    int cid = blockIdx.x;
    int bh = cid >> 6, c = cid & 63;
    int b = bh >> 3, h = bh & 7;
    int r0 = b * LSEQ + c * QC;
    float Dh = Dp[h];

    for (int i = tid; i < 1024; i += 256) {
        int s = i >> 4, q = (i & 15) * 4;
        float4 cv = *(const float4*)&g_xc[(size_t)(r0 + s) * CONVD + 320 + q];
        float4 bv = *(const float4*)&g_xc[(size_t)(r0 + s) * CONVD + 256 + q];
        __nv_bfloat16 h4[4], l4[4];
        split4(cv, h4, l4);
        *(uint2*)&smb[SC_CH + s * SC_P + q] = *(uint2*)h4;
        *(uint2*)&smb[SC_CL + s * SC_P + q] = *(uint2*)l4;
        split4(bv, h4, l4);
        *(uint2*)&smb[SC_BH + s * SC_P + q] = *(uint2*)h4;
        *(uint2*)&smb[SC_BL + s * SC_P + q] = *(uint2*)l4;
    }
    for (int i = tid; i < 512; i += 256) {
        int s = i >> 3, q = (i & 7) * 4;
        float4 v = *(const float4*)&g_xc[(size_t)(r0 + s) * CONVD + h * HD + q];
        __nv_bfloat16 h4[4], l4[4];
        split4(v, h4, l4);
        *(uint2*)&smb[SC_XH + s * 40 + q] = *(uint2*)h4;
        *(uint2*)&smb[SC_XL + s * 40 + q] = *(uint2*)l4;
    }
    for (int i = tid; i < 512; i += 256) {
        int p = i >> 4, q = (i & 15) * 4;
        float4 v = *(const float4*)&g_hs[(size_t)cid * 2048 + p * 64 + q];
        __nv_bfloat16 h4[4], l4[4];
        split4(v, h4, l4);
        *(uint2*)&smb[SC_HH + p * SC_P + q] = *(uint2*)h4;
        *(uint2*)&smb[SC_HL + p * SC_P + q] = *(uint2*)l4;
    }
    if (tid < 64) {
        Ssm[tid] = g_S[(size_t)cid * QC + tid];
        dts[tid] = g_dtb[(size_t)(r0 + tid) * NH + h];
    }
    __syncthreads();

    uint32_t sb = smem_u32(smb);
    int mw = wid & 3, nw = wid >> 2;
    int arow = mw * 16;
    int lrow = lane & 15, lk = (lane >> 4) << 3;
    int brow = (lane & 7) + ((lane >> 4) & 1) * 8;
    int bk = ((lane >> 3) & 1) << 3;
    int b_soff = ((lane >> 3) & 1) * 8, b_noff = (lane >> 4) * 8;

    float accg[4][4] = {};
#pragma unroll
    for (int kf = 0; kf < 4; kf++) {
        int k0 = kf << 4;
        uint32_t ch[4], cl[4];
        uint32_t ad = sb + (uint32_t)(((arow + lrow) * SC_P + k0 + lk) * 2);
        LDSM4(ch, ad + SC_CH * 2);
        LDSM4(cl, ad + SC_CL * 2);
        uint32_t bh2[2][4], bl2[2][4];
#pragma unroll
        for (int ng = 0; ng < 2; ng++) {
            uint32_t ad2 = sb + (uint32_t)(((nw * 32 + ng * 16 + brow) * SC_P + k0 + bk) * 2);
            LDSM4(bh2[ng], ad2 + SC_BH * 2);
            LDSM4(bl2[ng], ad2 + SC_BL * 2);
        }
#pragma unroll
        for (int nf = 0; nf < 4; nf++) {
            uint32_t* BH = &bh2[nf >> 1][(nf & 1) * 2];
            uint32_t* BL = &bl2[nf >> 1][(nf & 1) * 2];
            MMA16816(accg[nf], ch, BH[0], BH[1]);
            MMA16816(accg[nf], ch, BL[0], BL[1]);
            MMA16816(accg[nf], cl, BH[0], BH[1]);
        }
    }
    __syncthreads();

    int g = lane >> 2, tg = lane & 3;
    int t0 = arow + g, t1 = arow + g + 8;
    float St0 = Ssm[t0], St1 = Ssm[t1];
#pragma unroll
    for (int nf = 0; nf < 4; nf++) {
#pragma unroll
        for (int e = 0; e < 2; e++) {
            int s = nw * 32 + nf * 8 + tg * 2 + e;
            float ds = dts[s], Ss = Ssm[s];
            float m0 = (s <= t0) ? accg[nf][e]     * __expf(St0 - Ss) * ds : 0.f;
            float m1 = (s <= t1) ? accg[nf][2 + e] * __expf(St1 - Ss) * ds : 0.f;
            __nv_bfloat16 hh0, ll0, hh1, ll1;
            split_bf16(m0, hh0, ll0);
            split_bf16(m1, hh1, ll1);
            smb[SC_BH + t0 * SC_P + s] = hh0;
            smb[SC_BL + t0 * SC_P + s] = ll0;
            smb[SC_BH + t1 * SC_P + s] = hh1;
            smb[SC_BL + t1 * SC_P + s] = ll1;
        }
    }
    __syncthreads();

    int pw = wid >> 2;
    int prow = pw * 16;
    float ayi[2][4] = {}, ayo[2][4] = {};
#pragma unroll
    for (int kf = 0; kf < 4; kf++) {
        int k0 = kf << 4;
        uint32_t ad = sb + (uint32_t)(((arow + lrow) * SC_P + k0 + lk) * 2);
        uint32_t mh[4], ml[4], ch[4], cl[4];
        LDSM4(mh, ad + SC_BH * 2);
        LDSM4(ml, ad + SC_BL * 2);
        LDSM4(ch, ad + SC_CH * 2);
        LDSM4(cl, ad + SC_CL * 2);
        uint32_t xh[4], xl[4], hh2[4], hl2[4];
        uint32_t adx = sb + (uint32_t)((SC_XH + (k0 + b_soff + (lane & 7)) * 40
                                        + prow + b_noff) * 2);
        LDSM4T(xh, adx);
        LDSM4T(xl, adx + (SC_XL - SC_XH) * 2);
        uint32_t adh = sb + (uint32_t)(((prow + brow) * SC_P + k0 + bk) * 2);
        LDSM4(hh2, adh + SC_HH * 2);
        LDSM4(hl2, adh + SC_HL * 2);
#pragma unroll
        for (int nf = 0; nf < 2; nf++) {
            uint32_t* XH = &xh[nf * 2];  uint32_t* XL = &xl[nf * 2];
            uint32_t* HH = &hh2[nf * 2]; uint32_t* HL = &hl2[nf * 2];
            MMA16816(ayi[nf], mh, XH[0], XH[1]);
            MMA16816(ayi[nf], mh, XL[0], XL[1]);
            MMA16816(ayi[nf], ml, XH[0], XH[1]);
            MMA16816(ayo[nf], ch, HH[0], HH[1]);
            MMA16816(ayo[nf], ch, HL[0], HL[1]);
            MMA16816(ayo[nf], cl, HH[0], HH[1]);
        }
    }

    float eS0 = __expf(St0), eS1 = __expf(St1);
#pragma unroll
    for (int nf = 0; nf < 2; nf++) {
        int p = prow + nf * 8 + tg * 2;
        float xv00 = __bfloat162float(smb[SC_XH + t0 * 40 + p])
                   + __bfloat162float(smb[SC_XL + t0 * 40 + p]);
        float xv01 = __bfloat162float(smb[SC_XH + t0 * 40 + p + 1])
                   + __bfloat162float(smb[SC_XL + t0 * 40 + p + 1]);
        float xv10 = __bfloat162float(smb[SC_XH + t1 * 40 + p])
                   + __bfloat162float(smb[SC_XL + t1 * 40 + p]);
        float xv11 = __bfloat162float(smb[SC_XH + t1 * 40 + p + 1])
                   + __bfloat162float(smb[SC_XL + t1 * 40 + p + 1]);
        *(float2*)&g_y[(size_t)(r0 + t0) * DINNER + h * HD + p] =
            make_float2(ayi[nf][0] + eS0 * ayo[nf][0] + Dh * xv00,
                        ayi[nf][1] + eS0 * ayo[nf][1] + Dh * xv01);
        *(float2*)&g_y[(size_t)(r0 + t1) * DINNER + h * HD + p] =
            make_float2(ayi[nf][2] + eS1 * ayo[nf][2] + Dh * xv10,
                        ayi[nf][3] + eS1 * ayo[nf][3] + Dh * xv11);
    }
}

// ---------------- K4a: gating + gated RMSNorm (warp/row) --------------------
__global__ void k_gate(const float* __restrict__ gw) {
    int r    = blockIdx.x * 8 + (threadIdx.x >> 5);
    int lane = threadIdx.x & 31;
    float4 y0 = *(const float4*)&g_y[(size_t)r * DINNER + lane * 4];
    float4 y1 = *(const float4*)&g_y[(size_t)r * DINNER + 128 + lane * 4];
    float4 z0 = *(const float4*)&g_zx[(size_t)r * DPROJ + lane * 4];
    float4 z1 = *(const float4*)&g_zx[(size_t)r * DPROJ + 128 + lane * 4];
    float gv[8];
    gv[0] = y0.x * silu(z0.x); gv[1] = y0.y * silu(z0.y);
    gv[2] = y0.z * silu(z0.z); gv[3] = y0.w * silu(z0.w);
    gv[4] = y1.x * silu(z1.x); gv[5] = y1.y * silu(z1.y);
    gv[6] = y1.z * silu(z1.z); gv[7] = y1.w * silu(z1.w);
    float ss = 0.f;
#pragma unroll
    for (int j = 0; j < 8; j++) ss += gv[j] * gv[j];
#pragma unroll
    for (int o = 16; o; o >>= 1) ss += __shfl_xor_sync(0xffffffffu, ss, o);
    float sc = rsqrtf(ss * (1.f / DINNER) + 1e-5f);
    float4 w0 = *(const float4*)&gw[lane * 4];
    float4 w1 = *(const float4*)&gw[128 + lane * 4];
    float wv[8] = {w0.x, w0.y, w0.z, w0.w, w1.x, w1.y, w1.z, w1.w};
    __nv_bfloat16 h[8], l[8];
#pragma unroll
    for (int j = 0; j < 8; j++) split_bf16(gv[j] * sc * wv[j], h[j], l[j]);
    *(uint2*)&g_gh[(size_t)r * DINNER + lane * 4]       = *(uint2*)&h[0];
    *(uint2*)&g_gh[(size_t)r * DINNER + 128 + lane * 4] = *(uint2*)&h[4];
    *(uint2*)&g_gl[(size_t)r * DINNER + lane * 4]       = *(uint2*)&l[0];
    *(uint2*)&g_gl[(size_t)r * DINNER + 128 + lane * 4] = *(uint2*)&l[4];
}

// ---------------- K4b: out_proj HMMA bf16x3 + residual ----------------------
#define OP_AH 0
#define OP_AL 17408
#define OP_BH 34816
#define OP_BL 52224
#define OP_TOT 69632
__global__ void __launch_bounds__(256, 1) k_outproj_mma(const float* __restrict__ x,
                                                        float* __restrict__ out) {
    extern __shared__ __align__(16) __nv_bfloat16 smb[];
    int tid = threadIdx.x, wid = tid >> 5, lane = tid & 31;
    int rowBase = blockIdx.x * 128;
    uint32_t sb = smem_u32(smb);
    int mw = wid & 3, nw = wid >> 2;
    int arow = mw * 32, ncol = nw * 64;
    float acc[2][8][4] = {};
    int lrow = lane & 15, lk = (lane >> 4) << 3;
    int brow = (lane & 7) + ((lane >> 4) & 1) * 8;
    int bk = ((lane >> 3) & 1) << 3;

    for (int kc = 0; kc < 2; kc++) {
        if (kc) __syncthreads();
        for (int i = tid; i < 2048; i += 256) {
            int r = i >> 4, c = (i & 15) << 3;
            size_t ao = (size_t)(rowBase + r) * DINNER + kc * 128 + c;
            *(uint4*)&smb[OP_AH + r * 136 + c] = *(const uint4*)(g_gh + ao);
            *(uint4*)&smb[OP_AL + r * 136 + c] = *(const uint4*)(g_gl + ao);
            size_t bo = (size_t)r * DINNER + kc * 128 + c;
            *(uint4*)&smb[OP_BH + r * 136 + c] = *(const uint4*)(g_woh + bo);
            *(uint4*)&smb[OP_BL + r * 136 + c] = *(const uint4*)(g_wol + bo);
        }
        __syncthreads();
#pragma unroll
        for (int kf = 0; kf < 8; kf++) {
            int k0 = kf << 4;
            uint32_t ah[2][4], al[2][4];
#pragma unroll
            for (int mi = 0; mi < 2; mi++) {
                uint32_t ad = sb + (uint32_t)(((arow + mi * 16 + lrow) * 136 + k0 + lk) * 2);
                LDSM4(ah[mi], ad + OP_AH * 2);
                LDSM4(al[mi], ad + OP_AL * 2);
            }
            uint32_t bh[4][4], bl[4][4];
#pragma unroll
            for (int ng = 0; ng < 4; ng++) {
                uint32_t ad = sb + (uint32_t)(((ncol + ng * 16 + brow) * 136 + k0 + bk) * 2);
                LDSM4(bh[ng], ad + OP_BH * 2);
                LDSM4(bl[ng], ad + OP_BL * 2);
            }
#pragma unroll
            for (int mi = 0; mi < 2; mi++)
#pragma unroll
                for (int nf = 0; nf < 8; nf++) {
                    uint32_t* BH = &bh[nf >> 1][(nf & 1) * 2];
                    uint32_t* BL = &bl[nf >> 1][(nf & 1) * 2];
                    MMA16816(acc[mi][nf], ah[mi], BH[0], BH[1]);
                    MMA16816(acc[mi][nf], ah[mi], BL[0], BL[1]);
                    MMA16816(acc[mi][nf], al[mi], BH[0], BH[1]);
                }
        }
    }
    int g = lane >> 2, tg = lane & 3;
#pragma unroll
    for (int mi = 0; mi < 2; mi++) {
        int r = rowBase + arow + mi * 16 + g;
#pragma unroll
        for (int nf = 0; nf < 8; nf++) {
            int c = ncol + nf * 8 + tg * 2;
            float2 x0 = *(const float2*)&x[(size_t)r * DMODEL + c];
            float2 x1 = *(const float2*)&x[(size_t)(r + 8) * DMODEL + c];
            *(float2*)&out[(size_t)r * DMODEL + c] =
                make_float2(acc[mi][nf][0] + x0.x, acc[mi][nf][1] + x0.y);
            *(float2*)&out[(size_t)(r + 8) * DMODEL + c] =
                make_float2(acc[mi][nf][2] + x1.x, acc[mi][nf][3] + x1.y);
        }
    }
}

extern "C" void kernel_launch(void* const* d_in, const int* in_sizes, int n_in,
                              void* d_out, int out_size) {
    const float* x          = (const float*)d_in[0];
    const float* norm_w     = (const float*)d_in[1];
    const float* in_proj_w  = (const float*)d_in[2];
    const float* conv_w     = (const float*)d_in[3];
    const float* conv_b     = (const float*)d_in[4];
    const float* dt_bias    = (const float*)d_in[5];
    const float* A_log      = (const float*)d_in[6];
    const float* D          = (const float*)d_in[7];
    const float* gnorm_w    = (const float*)d_in[8];
    const float* out_proj_w = (const float*)d_in[9];
    float* out = (float*)d_out;

    const int in_smem   = IP_TOT * 2;
    const int out_smem  = OP_TOT * 2;
    const int ssdc_smem = SC_END * 2 + 512;
    cudaFuncSetAttribute(k_inproj_mma,  cudaFuncAttributeMaxDynamicSharedMemorySize, in_smem);
    cudaFuncSetAttribute(k_outproj_mma, cudaFuncAttributeMaxDynamicSharedMemorySize, out_smem);
    cudaFuncSetAttribute(k_ssd_c_mma,   cudaFuncAttributeMaxDynamicSharedMemorySize, ssdc_smem);

    k_wsplit<<<113, 256>>>(in_proj_w, out_proj_w);
    k_rmsnorm<<<RTOT / 8, 256>>>(x, norm_w);
    k_inproj_mma<<<dim3(RTOT / 128, 7), 256, in_smem>>>();
    k_conv4<<<RTOT / 16, 384>>>(conv_w, conv_b);
    k_ssd_a_mma<<<NCID, 256>>>(A_log, dt_bias);
    k_ssd_w<<<NBATCH * NH, 256>>>();
    k_ssd_b_mma<<<dim3(NBATCH * NH, 32), 256>>>();
    k_ssd_c_mma<<<NCID, 256, ssdc_smem>>>(D);
    k_gate<<<RTOT / 8, 256>>>(gnorm_w);
    k_outproj_mma<<<RTOT / 128, 256, out_smem>>>(x, out);
}

// round 11
// speedup vs baseline: 1.1924x; 1.0628x over previous
#include <cuda_runtime.h>
#include <cuda_bf16.h>
#include <cstdint>

#define RTOT   32768
#define LSEQ   4096
#define NBATCH 8
#define DMODEL 128
#define DPROJ  648
#define DINNER 256
#define CONVD  384
#define NH     8
#define HD     32
#define QC     64
#define NCHK   (LSEQ/QC)
#define NCID   (NBATCH*NH*NCHK)

// ---------------- scratch (device globals) ----------------------------------
__device__ __align__(16) float g_zx [(size_t)RTOT * DPROJ];
__device__ __align__(16) float g_xc [RTOT * CONVD];
__device__ __align__(16) float g_dtb[RTOT * NH];
__device__ __align__(16) float g_y  [RTOT * DINNER];
__device__ __align__(16) float g_U  [(size_t)NCID * 2048];
__device__ __align__(16) float g_hs [(size_t)NCID * 2048];
__device__ __align__(16) float g_S  [(size_t)NCID * QC];
__device__ __align__(16) float g_T  [NCID];
__device__ __align__(16) __nv_bfloat16 g_ah [RTOT * DMODEL];
__device__ __align__(16) __nv_bfloat16 g_al [RTOT * DMODEL];
__device__ __align__(16) __nv_bfloat16 g_wih[672 * DMODEL];
__device__ __align__(16) __nv_bfloat16 g_wil[672 * DMODEL];
__device__ __align__(16) __nv_bfloat16 g_gh [RTOT * DINNER];
__device__ __align__(16) __nv_bfloat16 g_gl [RTOT * DINNER];
__device__ __align__(16) __nv_bfloat16 g_woh[DMODEL * DINNER];
__device__ __align__(16) __nv_bfloat16 g_wol[DMODEL * DINNER];
__device__ __align__(16) __nv_bfloat16 g_wbh[64 * 4096];   // chunk-scan W hi
__device__ __align__(16) __nv_bfloat16 g_wbl[64 * 4096];   // chunk-scan W lo
// -----------------------------------------------------------------------------

// ---- warp MMA helpers ----
static __device__ __forceinline__ uint32_t smem_u32(const void* p) {
    uint32_t a;
    asm("{ .reg .u64 t; cvta.to.shared.u64 t, %1; cvt.u32.u64 %0, t; }"
        : "=r"(a) : "l"(p));
    return a;
}
#define LDSM4(r, addr) \
    asm volatile("ldmatrix.sync.aligned.m8n8.x4.shared.b16 {%0,%1,%2,%3}, [%4];" \
        : "=r"((r)[0]), "=r"((r)[1]), "=r"((r)[2]), "=r"((r)[3]) : "r"(addr))
#define LDSM4T(r, addr) \
    asm volatile("ldmatrix.sync.aligned.m8n8.x4.trans.shared.b16 {%0,%1,%2,%3}, [%4];" \
        : "=r"((r)[0]), "=r"((r)[1]), "=r"((r)[2]), "=r"((r)[3]) : "r"(addr))
#define MMA16816(d, a, b0, b1) \
    asm volatile("mma.sync.aligned.m16n8k16.row.col.f32.bf16.bf16.f32 " \
        "{%0,%1,%2,%3}, {%4,%5,%6,%7}, {%8,%9}, {%0,%1,%2,%3};" \
        : "+f"((d)[0]), "+f"((d)[1]), "+f"((d)[2]), "+f"((d)[3]) \
        : "r"((a)[0]), "r"((a)[1]), "r"((a)[2]), "r"((a)[3]), "r"(b0), "r"(b1))

static __device__ __forceinline__ void split_bf16(float v, __nv_bfloat16& h,
                                                  __nv_bfloat16& l) {
    h = __float2bfloat16(v);
    l = __float2bfloat16(v - __bfloat162float(h));
}
static __device__ __forceinline__ void split4(float4 v, __nv_bfloat16* h,
                                              __nv_bfloat16* l) {
    split_bf16(v.x, h[0], l[0]); split_bf16(v.y, h[1], l[1]);
    split_bf16(v.z, h[2], l[2]); split_bf16(v.w, h[3], l[3]);
}
static __device__ __forceinline__ float silu(float v) {
    return v / (1.f + __expf(-v));
}

// ---------------- K_w: one-shot weight split -------------------------------
__global__ void k_wsplit(const float* __restrict__ Wi, const float* __restrict__ Wo) {
    int idx = blockIdx.x * 256 + threadIdx.x;
    const int NWI = DPROJ * DMODEL / 4;
    const int NWO = DMODEL * DINNER / 4;
    if (idx < NWI) {
        float4 v = ((const float4*)Wi)[idx];
        __nv_bfloat16 h[4], l[4];
        split4(v, h, l);
        ((uint2*)g_wih)[idx] = *(uint2*)h;
        ((uint2*)g_wil)[idx] = *(uint2*)l;
    } else if (idx < NWI + NWO) {
        int j = idx - NWI;
        float4 v = ((const float4*)Wo)[j];
        __nv_bfloat16 h[4], l[4];
        split4(v, h, l);
        ((uint2*)g_woh)[j] = *(uint2*)h;
        ((uint2*)g_wol)[j] = *(uint2*)l;
    }
}

// ---------------- K0: RMSNorm -> bf16 hi/lo splits --------------------------
__global__ void k_rmsnorm(const float* __restrict__ x, const float* __restrict__ w) {
    int row  = blockIdx.x * 8 + (threadIdx.x >> 5);
    int lane = threadIdx.x & 31;
    float4 v = ((const float4*)(x + (size_t)row * DMODEL))[lane];
    float ss = v.x * v.x + v.y * v.y + v.z * v.z + v.w * v.w;
#pragma unroll
    for (int o = 16; o; o >>= 1) ss += __shfl_xor_sync(0xffffffffu, ss, o);
    float sc = rsqrtf(ss * (1.f / DMODEL) + 1e-5f);
    float4 wv = ((const float4*)w)[lane];
    float4 o4;
    o4.x = v.x * sc * wv.x; o4.y = v.y * sc * wv.y;
    o4.z = v.z * sc * wv.z; o4.w = v.w * sc * wv.w;
    __nv_bfloat16 h[4], l[4];
    split4(o4, h, l);
    ((uint2*)(g_ah + (size_t)row * DMODEL))[lane] = *(uint2*)h;
    ((uint2*)(g_al + (size_t)row * DMODEL))[lane] = *(uint2*)l;
}

// ---------------- K1: in_proj GEMM via HMMA bf16x3, tile 64x96, K=128 -------
// 87KB smem -> 2 blocks/SM; one block stages while the other runs MMAs.
#define IP_AH 0
#define IP_AL 8704
#define IP_BH 17408
#define IP_BL 30464
#define IP_TOT 43520
__global__ void __launch_bounds__(256, 2) k_inproj_mma() {
    extern __shared__ __align__(16) __nv_bfloat16 smb[];
    int tid = threadIdx.x, wid = tid >> 5, lane = tid & 31;
    int rowBase = blockIdx.x * 64;
    int colBase = blockIdx.y * 96;

    for (int i = tid; i < 1024; i += 256) {
        int r = i >> 4, c = (i & 15) << 3;
        *(uint4*)&smb[IP_AH + r * 136 + c] =
            *(const uint4*)(g_ah + (size_t)(rowBase + r) * DMODEL + c);
        *(uint4*)&smb[IP_AL + r * 136 + c] =
            *(const uint4*)(g_al + (size_t)(rowBase + r) * DMODEL + c);
    }
    for (int i = tid; i < 1536; i += 256) {
        int r = i >> 4, c = (i & 15) << 3;
        *(uint4*)&smb[IP_BH + r * 136 + c] =
            *(const uint4*)(g_wih + (size_t)(colBase + r) * DMODEL + c);
        *(uint4*)&smb[IP_BL + r * 136 + c] =
            *(const uint4*)(g_wil + (size_t)(colBase + r) * DMODEL + c);
    }
    __syncthreads();

    uint32_t sb = smem_u32(smb);
    int mw = wid & 3, nw = wid >> 2;
    int arow = mw * 16, ncol = nw * 48;
    float acc[6][4] = {};
    int lrow = lane & 15, lk = (lane >> 4) << 3;
    int brow = (lane & 7) + ((lane >> 4) & 1) * 8;
    int bk = ((lane >> 3) & 1) << 3;
#pragma unroll
    for (int kf = 0; kf < 8; kf++) {
        int k0 = kf << 4;
        uint32_t ah[4], al[4];
        uint32_t ad = sb + (uint32_t)(((arow + lrow) * 136 + k0 + lk) * 2);
        LDSM4(ah, ad + IP_AH * 2);
        LDSM4(al, ad + IP_AL * 2);
        uint32_t bh[3][4], bl[3][4];
#pragma unroll
        for (int ng = 0; ng < 3; ng++) {
            uint32_t ad2 = sb + (uint32_t)(((ncol + ng * 16 + brow) * 136 + k0 + bk) * 2);
            LDSM4(bh[ng], ad2 + IP_BH * 2);
            LDSM4(bl[ng], ad2 + IP_BL * 2);
        }
#pragma unroll
        for (int nf = 0; nf < 6; nf++) {
            uint32_t* BH = &bh[nf >> 1][(nf & 1) * 2];
            uint32_t* BL = &bl[nf >> 1][(nf & 1) * 2];
            MMA16816(acc[nf], ah, BH[0], BH[1]);
            MMA16816(acc[nf], ah, BL[0], BL[1]);
            MMA16816(acc[nf], al, BH[0], BH[1]);
        }
    }
    int g = lane >> 2, tg = lane & 3;
    int r = rowBase + arow + g;
#pragma unroll
    for (int nf = 0; nf < 6; nf++) {
        int c = colBase + ncol + nf * 8 + tg * 2;
        if (c < DPROJ) {
            *(float2*)&g_zx[(size_t)r * DPROJ + c] =
                make_float2(acc[nf][0], acc[nf][1]);
            *(float2*)&g_zx[(size_t)(r + 8) * DPROJ + c] =
                make_float2(acc[nf][2], acc[nf][3]);
        }
    }
}

// ---------------- K2: conv(K=4)+SiLU, float4 sliding-window -----------------
__global__ void __launch_bounds__(384) k_conv4(const float* __restrict__ cw,
                                               const float* __restrict__ cb) {
    int t = threadIdx.x;
    int c = (t % 96) * 4;
    int r0 = blockIdx.x * 16 + (t / 96) * 4;
    bool hist = (r0 & (LSEQ - 1)) != 0;
    float4 wA = *(const float4*)&cw[(c + 0) * 4];
    float4 wB = *(const float4*)&cw[(c + 1) * 4];
    float4 wC = *(const float4*)&cw[(c + 2) * 4];
    float4 wD = *(const float4*)&cw[(c + 3) * 4];
    float4 bias = *(const float4*)&cb[c];
    const float* src = g_zx + 256 + c;
    float* dst = g_xc + c;
    float4 z = make_float4(0.f, 0.f, 0.f, 0.f);
    float4 x0 = hist ? *(const float4*)&src[(size_t)(r0 - 3) * DPROJ] : z;
    float4 x1 = hist ? *(const float4*)&src[(size_t)(r0 - 2) * DPROJ] : z;
    float4 x2 = hist ? *(const float4*)&src[(size_t)(r0 - 1) * DPROJ] : z;
#pragma unroll
    for (int s = 0; s < 4; s++) {
        int r = r0 + s;
        float4 x3 = *(const float4*)&src[(size_t)r * DPROJ];
        float4 o;
        o.x = silu(bias.x + wA.x * x0.x + wA.y * x1.x + wA.z * x2.x + wA.w * x3.x);
        o.y = silu(bias.y + wB.x * x0.y + wB.y * x1.y + wB.z * x2.y + wB.w * x3.y);
        o.z = silu(bias.z + wC.x * x0.z + wC.y * x1.z + wC.z * x2.z + wC.w * x3.z);
        o.w = silu(bias.w + wD.x * x0.w + wD.y * x1.w + wD.z * x2.w + wD.w * x3.w);
        *(float4*)&dst[(size_t)r * CONVD] = o;
        x0 = x1; x1 = x2; x2 = x3;
    }
}

// ---------------- SSD pass A via HMMA bf16x3 --------------------------------
#define SA_BH 0
#define SA_BL 4608
#define SA_XH 9216
#define SA_XL 11776
#define SA_END 14336
__global__ void __launch_bounds__(256) k_ssd_a_mma(const float* __restrict__ A_log,
                                                   const float* __restrict__ dtb) {
    __shared__ __align__(16) __nv_bfloat16 smb[SA_END];
    __shared__ float sdt[64], sS[64], ssc[64];
    int tid = threadIdx.x;
    int cid = blockIdx.x;
    int bh = cid >> 6, c = cid & 63;
    int b = bh >> 3, h = bh & 7;
    int r0 = b * LSEQ + c * QC;
    float A = -__expf(A_log[h]);

    if (tid < 64) {
        float v = g_zx[(size_t)(r0 + tid) * DPROJ + 640 + h] + dtb[h];
        v = (v > 20.f) ? v : log1pf(__expf(v));
        sdt[tid] = v;
        g_dtb[(size_t)(r0 + tid) * NH + h] = v;
    }
    for (int i = tid; i < 1024; i += 256) {
        int s = i >> 4, q = (i & 15) * 4;
        float4 bv = *(const float4*)&g_xc[(size_t)(r0 + s) * CONVD + 256 + q];
        __nv_bfloat16 h4[4], l4[4];
        split4(bv, h4, l4);
        *(uint2*)&smb[SA_BH + s * 72 + q] = *(uint2*)h4;
        *(uint2*)&smb[SA_BL + s * 72 + q] = *(uint2*)l4;
    }
    __syncthreads();
    if (tid < 64) {
        float v = sdt[tid] * A;
#pragma unroll
        for (int o = 1; o < 32; o <<= 1) {
            float u = __shfl_up_sync(0xffffffffu, v, o);
            if ((tid & 31) >= o) v += u;
        }
        sS[tid] = v;
    }
    __syncthreads();
    if (tid >= 32 && tid < 64) sS[tid] += sS[31];
    __syncthreads();
    float T = sS[63];
    if (tid < 64) {
        float sv = sS[tid];
        g_S[(size_t)cid * QC + tid] = sv;
        ssc[tid] = __expf(T - sv) * sdt[tid];
    }
    if (tid == 0) g_T[cid] = T;
    __syncthreads();
    for (int i = tid; i < 512; i += 256) {
        int s = i >> 3, q = (i & 7) * 4;
        float4 v = *(const float4*)&g_xc[(size_t)(r0 + s) * CONVD + h * HD + q];
        float sc = ssc[s];
        v.x *= sc; v.y *= sc; v.z *= sc; v.w *= sc;
        __nv_bfloat16 h4[4], l4[4];
        split4(v, h4, l4);
        *(uint2*)&smb[SA_XH + s * 40 + q] = *(uint2*)h4;
        *(uint2*)&smb[SA_XL + s * 40 + q] = *(uint2*)l4;
    }
    __syncthreads();

    uint32_t sb = smem_u32(smb);
    int wid = tid >> 5, lane = tid & 31;
    int mw = wid & 1, nw = wid >> 1;
    int gidx = lane >> 3;
    int a_soff = (gidx >> 1) * 8, a_poff = (gidx & 1) * 8;
    int b_soff = ((lane >> 3) & 1) * 8, b_noff = (lane >> 4) * 8;
    float acc[2][4] = {};
#pragma unroll
    for (int kf = 0; kf < 4; kf++) {
        int k0 = kf << 4;
        uint32_t xh4[4], xl4[4], bh4[4], bl4[4];
        uint32_t ax = sb + (uint32_t)((SA_XH + (k0 + a_soff + (lane & 7)) * 40
                                       + mw * 16 + a_poff) * 2);
        LDSM4T(xh4, ax);
        LDSM4T(xl4, ax + (SA_XL - SA_XH) * 2);
        uint32_t bad = sb + (uint32_t)((SA_BH + (k0 + b_soff + (lane & 7)) * 72
                                        + nw * 16 + b_noff) * 2);
        LDSM4T(bh4, bad);
        LDSM4T(bl4, bad + (SA_BL - SA_BH) * 2);
#pragma unroll
        for (int nf = 0; nf < 2; nf++) {
            MMA16816(acc[nf], xh4, bh4[nf * 2], bh4[nf * 2 + 1]);
            MMA16816(acc[nf], xh4, bl4[nf * 2], bl4[nf * 2 + 1]);
            MMA16816(acc[nf], xl4, bh4[nf * 2], bh4[nf * 2 + 1]);
        }
    }
    int g = lane >> 2, tg = lane & 3;
    size_t ub = (size_t)cid * 2048;
#pragma unroll
    for (int nf = 0; nf < 2; nf++) {
        int p = mw * 16 + g, n = nw * 16 + nf * 8 + tg * 2;
        *(float2*)&g_U[ub + p * 64 + n]       = make_float2(acc[nf][0], acc[nf][1]);
        *(float2*)&g_U[ub + (p + 8) * 64 + n] = make_float2(acc[nf][2], acc[nf][3]);
    }
}

// ---------------- SSD pass B step 1: decay matrix W per (b,h) ---------------
__global__ void k_ssd_w() {
    __shared__ float sI[64];
    int bh = blockIdx.x, tid = threadIdx.x;
    if (tid < 64) {
        float v = g_T[bh * 64 + tid];
#pragma unroll
        for (int o = 1; o < 32; o <<= 1) {
            float u = __shfl_up_sync(0xffffffffu, v, o);
            if ((tid & 31) >= o) v += u;
        }
        sI[tid] = v;
    }
    __syncthreads();
    if (tid >= 32 && tid < 64) sI[tid] += sI[31];
    __syncthreads();
    for (int i = tid; i < 4096; i += 256) {
        int c = i >> 6, j = i & 63;
        float w = (j < c) ? __expf(sI[c - 1] - sI[j]) : 0.f;
        __nv_bfloat16 h, l;
        split_bf16(w, h, l);
        g_wbh[(size_t)bh * 4096 + i] = h;
        g_wbl[(size_t)bh * 4096 + i] = l;
    }
}

// ---------------- SSD pass B step 2: hs = W @ U via HMMA bf16x3 -------------
#define SB_WH 0
#define SB_WL 4608
#define SB_UH 9216
#define SB_UL 13824
#define SB_END 18432
__global__ void __launch_bounds__(256) k_ssd_b_mma() {
    __shared__ __align__(16) __nv_bfloat16 smb[SB_END];
    int tid = threadIdx.x, wid = tid >> 5, lane = tid & 31;
    int bh = blockIdx.x;
    int col0 = blockIdx.y * 64;
    for (int i = tid; i < 512; i += 256) {
        int c = i >> 3, q = (i & 7) * 8;
        *(uint4*)&smb[SB_WH + c * 72 + q] =
            *(const uint4*)&g_wbh[(size_t)bh * 4096 + c * 64 + q];
        *(uint4*)&smb[SB_WL + c * 72 + q] =
            *(const uint4*)&g_wbl[(size_t)bh * 4096 + c * 64 + q];
    }
    for (int i = tid; i < 1024; i += 256) {
        int j = i >> 4, q = (i & 15) * 4;
        float4 v = *(const float4*)&g_U[((size_t)bh * 64 + j) * 2048 + col0 + q];
        __nv_bfloat16 h4[4], l4[4];
        split4(v, h4, l4);
        *(uint2*)&smb[SB_UH + j * 72 + q] = *(uint2*)h4;
        *(uint2*)&smb[SB_UL + j * 72 + q] = *(uint2*)l4;
    }
    __syncthreads();
    uint32_t sb = smem_u32(smb);
    int mw = wid & 3, nw = wid >> 2;
    int crow = mw * 16, ncol = nw * 32;
    int lrow = lane & 15, lk = (lane >> 4) << 3;
    int b_soff = ((lane >> 3) & 1) * 8, b_noff = (lane >> 4) * 8;
    float acc[4][4] = {};
#pragma unroll
    for (int kf = 0; kf < 4; kf++) {
        int k0 = kf << 4;
        uint32_t whf[4], wlf[4];
        uint32_t ad = sb + (uint32_t)((SB_WH + (crow + lrow) * 72 + k0 + lk) * 2);
        LDSM4(whf, ad);
        LDSM4(wlf, ad + (SB_WL - SB_WH) * 2);
        uint32_t uh[2][4], ul[2][4];
#pragma unroll
        for (int hf = 0; hf < 2; hf++) {
            uint32_t ad2 = sb + (uint32_t)((SB_UH + (k0 + b_soff + (lane & 7)) * 72
                                            + ncol + hf * 16 + b_noff) * 2);
            LDSM4T(uh[hf], ad2);
            LDSM4T(ul[hf], ad2 + (SB_UL - SB_UH) * 2);
        }
#pragma unroll
        for (int nf = 0; nf < 4; nf++) {
            uint32_t* BH = &uh[nf >> 1][(nf & 1) * 2];
            uint32_t* BL = &ul[nf >> 1][(nf & 1) * 2];
            MMA16816(acc[nf], whf, BH[0], BH[1]);
            MMA16816(acc[nf], whf, BL[0], BL[1]);
            MMA16816(acc[nf], wlf, BH[0], BH[1]);
        }
    }
    int g = lane >> 2, tg = lane & 3;
#pragma unroll
    for (int nf = 0; nf < 4; nf++) {
        int c = crow + g, col = col0 + ncol + nf * 8 + tg * 2;
        *(float2*)&g_hs[((size_t)bh * 64 + c) * 2048 + col] =
            make_float2(acc[nf][0], acc[nf][1]);
        *(float2*)&g_hs[((size_t)bh * 64 + c + 8) * 2048 + col] =
            make_float2(acc[nf][2], acc[nf][3]);
    }
}

// ---------------- SSD pass C via HMMA bf16x3 --------------------------------
#define SC_P  72
#define SC_CH 0
#define SC_CL 4608
#define SC_BH 9216
#define SC_BL 13824
#define SC_XH 18432
#define SC_XL 20992
#define SC_HH 23552
#define SC_HL 25856
#define SC_END 28160
__global__ void __launch_bounds__(256, 2) k_ssd_c_mma(const float* __restrict__ Dp) {
    extern __shared__ __align__(16) __nv_bfloat16 smb[];
    float* Ssm = (float*)(smb + SC_END);
    float* dts = Ssm + 64;
    int tid = threadIdx.x, wid = tid >> 5, lane = tid & 31;
    int cid = blockIdx.x;
    int bh = cid >> 6, c = cid & 63;
    int b = bh >> 3, h = bh & 7;
    int r0 = b * LSEQ + c * QC;
    float Dh = Dp[h];

    for (int i = tid; i < 1024; i += 256) {
        int s = i >> 4, q = (i & 15) * 4;
        float4 cv = *(const float4*)&g_xc[(size_t)(r0 + s) * CONVD + 320 + q];
        float4 bv = *(const float4*)&g_xc[(size_t)(r0 + s) * CONVD + 256 + q];
        __nv_bfloat16 h4[4], l4[4];
        split4(cv, h4, l4);
        *(uint2*)&smb[SC_CH + s * SC_P + q] = *(uint2*)h4;
        *(uint2*)&smb[SC_CL + s * SC_P + q] = *(uint2*)l4;
        split4(bv, h4, l4);
        *(uint2*)&smb[SC_BH + s * SC_P + q] = *(uint2*)h4;
        *(uint2*)&smb[SC_BL + s * SC_P + q] = *(uint2*)l4;
    }
    for (int i = tid; i < 512; i += 256) {
        int s = i >> 3, q = (i & 7) * 4;
        float4 v = *(const float4*)&g_xc[(size_t)(r0 + s) * CONVD + h * HD + q];
        __nv_bfloat16 h4[4], l4[4];
        split4(v, h4, l4);
        *(uint2*)&smb[SC_XH + s * 40 + q] = *(uint2*)h4;
        *(uint2*)&smb[SC_XL + s * 40 + q] = *(uint2*)l4;
    }
    for (int i = tid; i < 512; i += 256) {
        int p = i >> 4, q = (i & 15) * 4;
        float4 v = *(const float4*)&g_hs[(size_t)cid * 2048 + p * 64 + q];
        __nv_bfloat16 h4[4], l4[4];
        split4(v, h4, l4);
        *(uint2*)&smb[SC_HH + p * SC_P + q] = *(uint2*)h4;
        *(uint2*)&smb[SC_HL + p * SC_P + q] = *(uint2*)l4;
    }
    if (tid < 64) {
        Ssm[tid] = g_S[(size_t)cid * QC + tid];
        dts[tid] = g_dtb[(size_t)(r0 + tid) * NH + h];
    }
    __syncthreads();

    uint32_t sb = smem_u32(smb);
    int mw = wid & 3, nw = wid >> 2;
    int arow = mw * 16;
    int lrow = lane & 15, lk = (lane >> 4) << 3;
    int brow = (lane & 7) + ((lane >> 4) & 1) * 8;
    int bk = ((lane >> 3) & 1) << 3;
    int b_soff = ((lane >> 3) & 1) * 8, b_noff = (lane >> 4) * 8;

    float accg[4][4] = {};
#pragma unroll
    for (int kf = 0; kf < 4; kf++) {
        int k0 = kf << 4;
        uint32_t ch[4], cl[4];
        uint32_t ad = sb + (uint32_t)(((arow + lrow) * SC_P + k0 + lk) * 2);
        LDSM4(ch, ad + SC_CH * 2);
        LDSM4(cl, ad + SC_CL * 2);
        uint32_t bh2[2][4], bl2[2][4];
#pragma unroll
        for (int ng = 0; ng < 2; ng++) {
            uint32_t ad2 = sb + (uint32_t)(((nw * 32 + ng * 16 + brow) * SC_P + k0 + bk) * 2);
            LDSM4(bh2[ng], ad2 + SC_BH * 2);
            LDSM4(bl2[ng], ad2 + SC_BL * 2);
        }
#pragma unroll
        for (int nf = 0; nf < 4; nf++) {
            uint32_t* BH = &bh2[nf >> 1][(nf & 1) * 2];
            uint32_t* BL = &bl2[nf >> 1][(nf & 1) * 2];
            MMA16816(accg[nf], ch, BH[0], BH[1]);
            MMA16816(accg[nf], ch, BL[0], BL[1]);
            MMA16816(accg[nf], cl, BH[0], BH[1]);
        }
    }
    __syncthreads();

    int g = lane >> 2, tg = lane & 3;
    int t0 = arow + g, t1 = arow + g + 8;
    float St0 = Ssm[t0], St1 = Ssm[t1];
#pragma unroll
    for (int nf = 0; nf < 4; nf++) {
#pragma unroll
        for (int e = 0; e < 2; e++) {
            int s = nw * 32 + nf * 8 + tg * 2 + e;
            float ds = dts[s], Ss = Ssm[s];
            float m0 = (s <= t0) ? accg[nf][e]     * __expf(St0 - Ss) * ds : 0.f;
            float m1 = (s <= t1) ? accg[nf][2 + e] * __expf(St1 - Ss) * ds : 0.f;
            __nv_bfloat16 hh0, ll0, hh1, ll1;
            split_bf16(m0, hh0, ll0);
            split_bf16(m1, hh1, ll1);
            smb[SC_BH + t0 * SC_P + s] = hh0;
            smb[SC_BL + t0 * SC_P + s] = ll0;
            smb[SC_BH + t1 * SC_P + s] = hh1;
            smb[SC_BL + t1 * SC_P + s] = ll1;
        }
    }
    __syncthreads();

    int pw = wid >> 2;
    int prow = pw * 16;
    float ayi[2][4] = {}, ayo[2][4] = {};
#pragma unroll
    for (int kf = 0; kf < 4; kf++) {
        int k0 = kf << 4;
        uint32_t ad = sb + (uint32_t)(((arow + lrow) * SC_P + k0 + lk) * 2);
        uint32_t mh[4], ml[4], ch[4], cl[4];
        LDSM4(mh, ad + SC_BH * 2);
        LDSM4(ml, ad + SC_BL * 2);
        LDSM4(ch, ad + SC_CH * 2);
        LDSM4(cl, ad + SC_CL * 2);
        uint32_t xh[4], xl[4], hh2[4], hl2[4];
        uint32_t adx = sb + (uint32_t)((SC_XH + (k0 + b_soff + (lane & 7)) * 40
                                        + prow + b_noff) * 2);
        LDSM4T(xh, adx);
        LDSM4T(xl, adx + (SC_XL - SC_XH) * 2);
        uint32_t adh = sb + (uint32_t)(((prow + brow) * SC_P + k0 + bk) * 2);
        LDSM4(hh2, adh + SC_HH * 2);
        LDSM4(hl2, adh + SC_HL * 2);
#pragma unroll
        for (int nf = 0; nf < 2; nf++) {
            uint32_t* XH = &xh[nf * 2];  uint32_t* XL = &xl[nf * 2];
            uint32_t* HH = &hh2[nf * 2]; uint32_t* HL = &hl2[nf * 2];
            MMA16816(ayi[nf], mh, XH[0], XH[1]);
            MMA16816(ayi[nf], mh, XL[0], XL[1]);
            MMA16816(ayi[nf], ml, XH[0], XH[1]);
            MMA16816(ayo[nf], ch, HH[0], HH[1]);
            MMA16816(ayo[nf], ch, HL[0], HL[1]);
            MMA16816(ayo[nf], cl, HH[0], HH[1]);
        }
    }

    float eS0 = __expf(St0), eS1 = __expf(St1);
#pragma unroll
    for (int nf = 0; nf < 2; nf++) {
        int p = prow + nf * 8 + tg * 2;
        float xv00 = __bfloat162float(smb[SC_XH + t0 * 40 + p])
                   + __bfloat162float(smb[SC_XL + t0 * 40 + p]);
        float xv01 = __bfloat162float(smb[SC_XH + t0 * 40 + p + 1])
                   + __bfloat162float(smb[SC_XL + t0 * 40 + p + 1]);
        float xv10 = __bfloat162float(smb[SC_XH + t1 * 40 + p])
                   + __bfloat162float(smb[SC_XL + t1 * 40 + p]);
        float xv11 = __bfloat162float(smb[SC_XH + t1 * 40 + p + 1])
                   + __bfloat162float(smb[SC_XL + t1 * 40 + p + 1]);
        *(float2*)&g_y[(size_t)(r0 + t0) * DINNER + h * HD + p] =
            make_float2(ayi[nf][0] + eS0 * ayo[nf][0] + Dh * xv00,
                        ayi[nf][1] + eS0 * ayo[nf][1] + Dh * xv01);
        *(float2*)&g_y[(size_t)(r0 + t1) * DINNER + h * HD + p] =
            make_float2(ayi[nf][2] + eS1 * ayo[nf][2] + Dh * xv10,
                        ayi[nf][3] + eS1 * ayo[nf][3] + Dh * xv11);
    }
}

// ---------------- K4a: gating + gated RMSNorm (warp/row) --------------------
__global__ void k_gate(const float* __restrict__ gw) {
    int r    = blockIdx.x * 8 + (threadIdx.x >> 5);
    int lane = threadIdx.x & 31;
    float4 y0 = *(const float4*)&g_y[(size_t)r * DINNER + lane * 4];
    float4 y1 = *(const float4*)&g_y[(size_t)r * DINNER + 128 + lane * 4];
    float4 z0 = *(const float4*)&g_zx[(size_t)r * DPROJ + lane * 4];
    float4 z1 = *(const float4*)&g_zx[(size_t)r * DPROJ + 128 + lane * 4];
    float gv[8];
    gv[0] = y0.x * silu(z0.x); gv[1] = y0.y * silu(z0.y);
    gv[2] = y0.z * silu(z0.z); gv[3] = y0.w * silu(z0.w);
    gv[4] = y1.x * silu(z1.x); gv[5] = y1.y * silu(z1.y);
    gv[6] = y1.z * silu(z1.z); gv[7] = y1.w * silu(z1.w);
    float ss = 0.f;
#pragma unroll
    for (int j = 0; j < 8; j++) ss += gv[j] * gv[j];
#pragma unroll
    for (int o = 16; o; o >>= 1) ss += __shfl_xor_sync(0xffffffffu, ss, o);
    float sc = rsqrtf(ss * (1.f / DINNER) + 1e-5f);
    float4 w0 = *(const float4*)&gw[lane * 4];
    float4 w1 = *(const float4*)&gw[128 + lane * 4];
    float wv[8] = {w0.x, w0.y, w0.z, w0.w, w1.x, w1.y, w1.z, w1.w};
    __nv_bfloat16 h[8], l[8];
#pragma unroll
    for (int j = 0; j < 8; j++) split_bf16(gv[j] * sc * wv[j], h[j], l[j]);
    *(uint2*)&g_gh[(size_t)r * DINNER + lane * 4]       = *(uint2*)&h[0];
    *(uint2*)&g_gh[(size_t)r * DINNER + 128 + lane * 4] = *(uint2*)&h[4];
    *(uint2*)&g_gl[(size_t)r * DINNER + lane * 4]       = *(uint2*)&l[0];
    *(uint2*)&g_gl[(size_t)r * DINNER + 128 + lane * 4] = *(uint2*)&l[4];
}

// ---------------- K4b: out_proj HMMA bf16x3 + residual, tile 64x128 ---------
// 104.5KB smem -> 2 blocks/SM for stage/compute overlap.
#define OP_AH 0
#define OP_AL 8704
#define OP_BH 17408
#define OP_BL 34816
#define OP_TOT 52224
__global__ void __launch_bounds__(256, 2) k_outproj_mma(const float* __restrict__ x,
                                                        float* __restrict__ out) {
    extern __shared__ __align__(16) __nv_bfloat16 smb[];
    int tid = threadIdx.x, wid = tid >> 5, lane = tid & 31;
    int rowBase = blockIdx.x * 64;
    uint32_t sb = smem_u32(smb);
    int mw = wid & 3, nw = wid >> 2;
    int arow = mw * 16, ncol = nw * 64;
    float acc[8][4] = {};
    int lrow = lane & 15, lk = (lane >> 4) << 3;
    int brow = (lane & 7) + ((lane >> 4) & 1) * 8;
    int bk = ((lane >> 3) & 1) << 3;

    for (int kc = 0; kc < 2; kc++) {
        if (kc) __syncthreads();
        for (int i = tid; i < 1024; i += 256) {
            int r = i >> 4, c = (i & 15) << 3;
            size_t ao = (size_t)(rowBase + r) * DINNER + kc * 128 + c;
            *(uint4*)&smb[OP_AH + r * 136 + c] = *(const uint4*)(g_gh + ao);
            *(uint4*)&smb[OP_AL + r * 136 + c] = *(const uint4*)(g_gl + ao);
        }
        for (int i = tid; i < 2048; i += 256) {
            int r = i >> 4, c = (i & 15) << 3;
            size_t bo = (size_t)r * DINNER + kc * 128 + c;
            *(uint4*)&smb[OP_BH + r * 136 + c] = *(const uint4*)(g_woh + bo);
            *(uint4*)&smb[OP_BL + r * 136 + c] = *(const uint4*)(g_wol + bo);
        }
        __syncthreads();
#pragma unroll
        for (int kf = 0; kf < 8; kf++) {
            int k0 = kf << 4;
            uint32_t ah[4], al[4];
            uint32_t ad = sb + (uint32_t)(((arow + lrow) * 136 + k0 + lk) * 2);
            LDSM4(ah, ad + OP_AH * 2);
            LDSM4(al, ad + OP_AL * 2);
            uint32_t bh[4][4], bl[4][4];
#pragma unroll
            for (int ng = 0; ng < 4; ng++) {
                uint32_t ad2 = sb + (uint32_t)(((ncol + ng * 16 + brow) * 136 + k0 + bk) * 2);
                LDSM4(bh[ng], ad2 + OP_BH * 2);
                LDSM4(bl[ng], ad2 + OP_BL * 2);
            }
#pragma unroll
            for (int nf = 0; nf < 8; nf++) {
                uint32_t* BH = &bh[nf >> 1][(nf & 1) * 2];
                uint32_t* BL = &bl[nf >> 1][(nf & 1) * 2];
                MMA16816(acc[nf], ah, BH[0], BH[1]);
                MMA16816(acc[nf], ah, BL[0], BL[1]);
                MMA16816(acc[nf], al, BH[0], BH[1]);
            }
        }
    }
    int g = lane >> 2, tg = lane & 3;
    int r = rowBase + arow + g;
#pragma unroll
    for (int nf = 0; nf < 8; nf++) {
        int c = ncol + nf * 8 + tg * 2;
        float2 x0 = *(const float2*)&x[(size_t)r * DMODEL + c];
        float2 x1 = *(const float2*)&x[(size_t)(r + 8) * DMODEL + c];
        *(float2*)&out[(size_t)r * DMODEL + c] =
            make_float2(acc[nf][0] + x0.x, acc[nf][1] + x0.y);
        *(float2*)&out[(size_t)(r + 8) * DMODEL + c] =
            make_float2(acc[nf][2] + x1.x, acc[nf][3] + x1.y);
    }
}

extern "C" void kernel_launch(void* const* d_in, const int* in_sizes, int n_in,
                              void* d_out, int out_size) {
    const float* x          = (const float*)d_in[0];
    const float* norm_w     = (const float*)d_in[1];
    const float* in_proj_w  = (const float*)d_in[2];
    const float* conv_w     = (const float*)d_in[3];
    const float* conv_b     = (const float*)d_in[4];
    const float* dt_bias    = (const float*)d_in[5];
    const float* A_log      = (const float*)d_in[6];
    const float* D          = (const float*)d_in[7];
    const float* gnorm_w    = (const float*)d_in[8];
    const float* out_proj_w = (const float*)d_in[9];
    float* out = (float*)d_out;

    const int in_smem   = IP_TOT * 2;   // 87040 B
    const int out_smem  = OP_TOT * 2;   // 104448 B
    const int ssdc_smem = SC_END * 2 + 512;
    cudaFuncSetAttribute(k_inproj_mma,  cudaFuncAttributeMaxDynamicSharedMemorySize, in_smem);
    cudaFuncSetAttribute(k_outproj_mma, cudaFuncAttributeMaxDynamicSharedMemorySize, out_smem);
    cudaFuncSetAttribute(k_ssd_c_mma,   cudaFuncAttributeMaxDynamicSharedMemorySize, ssdc_smem);

    k_wsplit<<<113, 256>>>(in_proj_w, out_proj_w);
    k_rmsnorm<<<RTOT / 8, 256>>>(x, norm_w);
    k_inproj_mma<<<dim3(RTOT / 64, 7), 256, in_smem>>>();
    k_conv4<<<RTOT / 16, 384>>>(conv_w, conv_b);
    k_ssd_a_mma<<<NCID, 256>>>(A_log, dt_bias);
    k_ssd_w<<<NBATCH * NH, 256>>>();
    k_ssd_b_mma<<<dim3(NBATCH * NH, 32), 256>>>();
    k_ssd_c_mma<<<NCID, 256, ssdc_smem>>>(D);
    k_gate<<<RTOT / 8, 256>>>(gnorm_w);
    k_outproj_mma<<<RTOT / 64, 256, out_smem>>>(x, out);
}

// round 12
// speedup vs baseline: 1.2364x; 1.0369x over previous
#include <cuda_runtime.h>
#include <cuda_bf16.h>
#include <cstdint>

#define RTOT   32768
#define LSEQ   4096
#define NBATCH 8
#define DMODEL 128
#define DPROJ  648
#define DINNER 256
#define CONVD  384
#define NH     8
#define HD     32
#define QC     64
#define NCHK   (LSEQ/QC)
#define NCID   (NBATCH*NH*NCHK)

// ---------------- scratch (device globals) ----------------------------------
__device__ __align__(16) float g_zx [(size_t)RTOT * DPROJ];
__device__ __align__(16) float g_dtb[RTOT * NH];
__device__ __align__(16) float g_y  [RTOT * DINNER];
__device__ __align__(16) float g_S  [(size_t)NCID * QC];
__device__ __align__(16) float g_T  [NCID];
__device__ __align__(16) __nv_bfloat16 g_xch[RTOT * CONVD];
__device__ __align__(16) __nv_bfloat16 g_xcl[RTOT * CONVD];
__device__ __align__(16) __nv_bfloat16 g_Uh [(size_t)NCID * 2048];
__device__ __align__(16) __nv_bfloat16 g_Ul [(size_t)NCID * 2048];
__device__ __align__(16) __nv_bfloat16 g_hsh[(size_t)NCID * 2048];
__device__ __align__(16) __nv_bfloat16 g_hsl[(size_t)NCID * 2048];
__device__ __align__(16) __nv_bfloat16 g_ah [RTOT * DMODEL];
__device__ __align__(16) __nv_bfloat16 g_al [RTOT * DMODEL];
__device__ __align__(16) __nv_bfloat16 g_wih[672 * DMODEL];
__device__ __align__(16) __nv_bfloat16 g_wil[672 * DMODEL];
__device__ __align__(16) __nv_bfloat16 g_gh [RTOT * DINNER];
__device__ __align__(16) __nv_bfloat16 g_gl [RTOT * DINNER];
__device__ __align__(16) __nv_bfloat16 g_woh[DMODEL * DINNER];
__device__ __align__(16) __nv_bfloat16 g_wol[DMODEL * DINNER];
// -----------------------------------------------------------------------------

// ---- warp MMA helpers ----
static __device__ __forceinline__ uint32_t smem_u32(const void* p) {
    uint32_t a;
    asm("{ .reg .u64 t; cvta.to.shared.u64 t, %1; cvt.u32.u64 %0, t; }"
        : "=r"(a) : "l"(p));
    return a;
}
#define LDSM4(r, addr) \
    asm volatile("ldmatrix.sync.aligned.m8n8.x4.shared.b16 {%0,%1,%2,%3}, [%4];" \
        : "=r"((r)[0]), "=r"((r)[1]), "=r"((r)[2]), "=r"((r)[3]) : "r"(addr))
#define LDSM4T(r, addr) \
    asm volatile("ldmatrix.sync.aligned.m8n8.x4.trans.shared.b16 {%0,%1,%2,%3}, [%4];" \
        : "=r"((r)[0]), "=r"((r)[1]), "=r"((r)[2]), "=r"((r)[3]) : "r"(addr))
#define MMA16816(d, a, b0, b1) \
    asm volatile("mma.sync.aligned.m16n8k16.row.col.f32.bf16.bf16.f32 " \
        "{%0,%1,%2,%3}, {%4,%5,%6,%7}, {%8,%9}, {%0,%1,%2,%3};" \
        : "+f"((d)[0]), "+f"((d)[1]), "+f"((d)[2]), "+f"((d)[3]) \
        : "r"((a)[0]), "r"((a)[1]), "r"((a)[2]), "r"((a)[3]), "r"(b0), "r"(b1))

static __device__ __forceinline__ void split_bf16(float v, __nv_bfloat16& h,
                                                  __nv_bfloat16& l) {
    h = __float2bfloat16(v);
    l = __float2bfloat16(v - __bfloat162float(h));
}
static __device__ __forceinline__ void split4(float4 v, __nv_bfloat16* h,
                                              __nv_bfloat16* l) {
    split_bf16(v.x, h[0], l[0]); split_bf16(v.y, h[1], l[1]);
    split_bf16(v.z, h[2], l[2]); split_bf16(v.w, h[3], l[3]);
}
static __device__ __forceinline__ float silu(float v) {
    return v / (1.f + __expf(-v));
}

// ---------------- K_w: one-shot weight split -------------------------------
__global__ void k_wsplit(const float* __restrict__ Wi, const float* __restrict__ Wo) {
    int idx = blockIdx.x * 256 + threadIdx.x;
    const int NWI = DPROJ * DMODEL / 4;
    const int NWO = DMODEL * DINNER / 4;
    if (idx < NWI) {
        float4 v = ((const float4*)Wi)[idx];
        __nv_bfloat16 h[4], l[4];
        split4(v, h, l);
        ((uint2*)g_wih)[idx] = *(uint2*)h;
        ((uint2*)g_wil)[idx] = *(uint2*)l;
    } else if (idx < NWI + NWO) {
        int j = idx - NWI;
        float4 v = ((const float4*)Wo)[j];
        __nv_bfloat16 h[4], l[4];
        split4(v, h, l);
        ((uint2*)g_woh)[j] = *(uint2*)h;
        ((uint2*)g_wol)[j] = *(uint2*)l;
    }
}

// ---------------- K0: RMSNorm -> bf16 hi/lo splits --------------------------
__global__ void k_rmsnorm(const float* __restrict__ x, const float* __restrict__ w) {
    int row  = blockIdx.x * 8 + (threadIdx.x >> 5);
    int lane = threadIdx.x & 31;
    float4 v = ((const float4*)(x + (size_t)row * DMODEL))[lane];
    float ss = v.x * v.x + v.y * v.y + v.z * v.z + v.w * v.w;
#pragma unroll
    for (int o = 16; o; o >>= 1) ss += __shfl_xor_sync(0xffffffffu, ss, o);
    float sc = rsqrtf(ss * (1.f / DMODEL) + 1e-5f);
    float4 wv = ((const float4*)w)[lane];
    float4 o4;
    o4.x = v.x * sc * wv.x; o4.y = v.y * sc * wv.y;
    o4.z = v.z * sc * wv.z; o4.w = v.w * sc * wv.w;
    __nv_bfloat16 h[4], l[4];
    split4(o4, h, l);
    ((uint2*)(g_ah + (size_t)row * DMODEL))[lane] = *(uint2*)h;
    ((uint2*)(g_al + (size_t)row * DMODEL))[lane] = *(uint2*)l;
}

// ---------------- K1: in_proj GEMM via HMMA bf16x3, tile 64x96, K=128 -------
#define IP_AH 0
#define IP_AL 8704
#define IP_BH 17408
#define IP_BL 30464
#define IP_TOT 43520
__global__ void __launch_bounds__(256, 2) k_inproj_mma() {
    extern __shared__ __align__(16) __nv_bfloat16 smb[];
    int tid = threadIdx.x, wid = tid >> 5, lane = tid & 31;
    int rowBase = blockIdx.x * 64;
    int colBase = blockIdx.y * 96;

    for (int i = tid; i < 1024; i += 256) {
        int r = i >> 4, c = (i & 15) << 3;
        *(uint4*)&smb[IP_AH + r * 136 + c] =
            *(const uint4*)(g_ah + (size_t)(rowBase + r) * DMODEL + c);
        *(uint4*)&smb[IP_AL + r * 136 + c] =
            *(const uint4*)(g_al + (size_t)(rowBase + r) * DMODEL + c);
    }
    for (int i = tid; i < 1536; i += 256) {
        int r = i >> 4, c = (i & 15) << 3;
        *(uint4*)&smb[IP_BH + r * 136 + c] =
            *(const uint4*)(g_wih + (size_t)(colBase + r) * DMODEL + c);
        *(uint4*)&smb[IP_BL + r * 136 + c] =
            *(const uint4*)(g_wil + (size_t)(colBase + r) * DMODEL + c);
    }
    __syncthreads();

    uint32_t sb = smem_u32(smb);
    int mw = wid & 3, nw = wid >> 2;
    int arow = mw * 16, ncol = nw * 48;
    float acc[6][4] = {};
    int lrow = lane & 15, lk = (lane >> 4) << 3;
    int brow = (lane & 7) + ((lane >> 4) & 1) * 8;
    int bk = ((lane >> 3) & 1) << 3;
#pragma unroll
    for (int kf = 0; kf < 8; kf++) {
        int k0 = kf << 4;
        uint32_t ah[4], al[4];
        uint32_t ad = sb + (uint32_t)(((arow + lrow) * 136 + k0 + lk) * 2);
        LDSM4(ah, ad + IP_AH * 2);
        LDSM4(al, ad + IP_AL * 2);
        uint32_t bh[3][4], bl[3][4];
#pragma unroll
        for (int ng = 0; ng < 3; ng++) {
            uint32_t ad2 = sb + (uint32_t)(((ncol + ng * 16 + brow) * 136 + k0 + bk) * 2);
            LDSM4(bh[ng], ad2 + IP_BH * 2);
            LDSM4(bl[ng], ad2 + IP_BL * 2);
        }
#pragma unroll
        for (int nf = 0; nf < 6; nf++) {
            uint32_t* BH = &bh[nf >> 1][(nf & 1) * 2];
            uint32_t* BL = &bl[nf >> 1][(nf & 1) * 2];
            MMA16816(acc[nf], ah, BH[0], BH[1]);
            MMA16816(acc[nf], ah, BL[0], BL[1]);
            MMA16816(acc[nf], al, BH[0], BH[1]);
        }
    }
    int g = lane >> 2, tg = lane & 3;
    int r = rowBase + arow + g;
#pragma unroll
    for (int nf = 0; nf < 6; nf++) {
        int c = colBase + ncol + nf * 8 + tg * 2;
        if (c < DPROJ) {
            *(float2*)&g_zx[(size_t)r * DPROJ + c] =
                make_float2(acc[nf][0], acc[nf][1]);
            *(float2*)&g_zx[(size_t)(r + 8) * DPROJ + c] =
                make_float2(acc[nf][2], acc[nf][3]);
        }
    }
}

// ---------------- K2: conv(K=4)+SiLU -> bf16 hi/lo splits -------------------
__global__ void __launch_bounds__(384) k_conv4(const float* __restrict__ cw,
                                               const float* __restrict__ cb) {
    int t = threadIdx.x;
    int c = (t % 96) * 4;
    int r0 = blockIdx.x * 16 + (t / 96) * 4;
    bool hist = (r0 & (LSEQ - 1)) != 0;
    float4 wA = *(const float4*)&cw[(c + 0) * 4];
    float4 wB = *(const float4*)&cw[(c + 1) * 4];
    float4 wC = *(const float4*)&cw[(c + 2) * 4];
    float4 wD = *(const float4*)&cw[(c + 3) * 4];
    float4 bias = *(const float4*)&cb[c];
    const float* src = g_zx + 256 + c;
    float4 z = make_float4(0.f, 0.f, 0.f, 0.f);
    float4 x0 = hist ? *(const float4*)&src[(size_t)(r0 - 3) * DPROJ] : z;
    float4 x1 = hist ? *(const float4*)&src[(size_t)(r0 - 2) * DPROJ] : z;
    float4 x2 = hist ? *(const float4*)&src[(size_t)(r0 - 1) * DPROJ] : z;
#pragma unroll
    for (int s = 0; s < 4; s++) {
        int r = r0 + s;
        float4 x3 = *(const float4*)&src[(size_t)r * DPROJ];
        float4 o;
        o.x = silu(bias.x + wA.x * x0.x + wA.y * x1.x + wA.z * x2.x + wA.w * x3.x);
        o.y = silu(bias.y + wB.x * x0.y + wB.y * x1.y + wB.z * x2.y + wB.w * x3.y);
        o.z = silu(bias.z + wC.x * x0.z + wC.y * x1.z + wC.z * x2.z + wC.w * x3.z);
        o.w = silu(bias.w + wD.x * x0.w + wD.y * x1.w + wD.z * x2.w + wD.w * x3.w);
        __nv_bfloat16 h4[4], l4[4];
        split4(o, h4, l4);
        *(uint2*)&g_xch[(size_t)r * CONVD + c] = *(uint2*)h4;
        *(uint2*)&g_xcl[(size_t)r * CONVD + c] = *(uint2*)l4;
        x0 = x1; x1 = x2; x2 = x3;
    }
}

// ---------------- SSD pass A via HMMA bf16x3 --------------------------------
#define SA_BH 0
#define SA_BL 4608
#define SA_XH 9216
#define SA_XL 11776
#define SA_END 14336
__global__ void __launch_bounds__(256) k_ssd_a_mma(const float* __restrict__ A_log,
                                                   const float* __restrict__ dtb) {
    __shared__ __align__(16) __nv_bfloat16 smb[SA_END];
    __shared__ float sdt[64], sS[64], ssc[64];
    int tid = threadIdx.x;
    int cid = blockIdx.x;
    int bh = cid >> 6, c = cid & 63;
    int b = bh >> 3, h = bh & 7;
    int r0 = b * LSEQ + c * QC;
    float A = -__expf(A_log[h]);

    if (tid < 64) {
        float v = g_zx[(size_t)(r0 + tid) * DPROJ + 640 + h] + dtb[h];
        v = (v > 20.f) ? v : log1pf(__expf(v));
        sdt[tid] = v;
        g_dtb[(size_t)(r0 + tid) * NH + h] = v;
    }
    // stage B raw (pre-split by conv)
    for (int i = tid; i < 512; i += 256) {
        int s = i >> 3, q = (i & 7) * 8;
        *(uint4*)&smb[SA_BH + s * 72 + q] =
            *(const uint4*)&g_xch[(size_t)(r0 + s) * CONVD + 256 + q];
        *(uint4*)&smb[SA_BL + s * 72 + q] =
            *(const uint4*)&g_xcl[(size_t)(r0 + s) * CONVD + 256 + q];
    }
    __syncthreads();
    if (tid < 64) {
        float v = sdt[tid] * A;
#pragma unroll
        for (int o = 1; o < 32; o <<= 1) {
            float u = __shfl_up_sync(0xffffffffu, v, o);
            if ((tid & 31) >= o) v += u;
        }
        sS[tid] = v;
    }
    __syncthreads();
    if (tid >= 32 && tid < 64) sS[tid] += sS[31];
    __syncthreads();
    float T = sS[63];
    if (tid < 64) {
        float sv = sS[tid];
        g_S[(size_t)cid * QC + tid] = sv;
        ssc[tid] = __expf(T - sv) * sdt[tid];
    }
    if (tid == 0) g_T[cid] = T;
    __syncthreads();
    // stage scaled X (reconstruct, scale, re-split)
    for (int i = tid; i < 512; i += 256) {
        int s = i >> 3, q = (i & 7) * 4;
        uint2 hv = *(const uint2*)&g_xch[(size_t)(r0 + s) * CONVD + h * HD + q];
        uint2 lv = *(const uint2*)&g_xcl[(size_t)(r0 + s) * CONVD + h * HD + q];
        __nv_bfloat16* hp = (__nv_bfloat16*)&hv;
        __nv_bfloat16* lp = (__nv_bfloat16*)&lv;
        float sc = ssc[s];
        __nv_bfloat16 h4[4], l4[4];
#pragma unroll
        for (int j = 0; j < 4; j++) {
            float xv = (__bfloat162float(hp[j]) + __bfloat162float(lp[j])) * sc;
            split_bf16(xv, h4[j], l4[j]);
        }
        *(uint2*)&smb[SA_XH + s * 40 + q] = *(uint2*)h4;
        *(uint2*)&smb[SA_XL + s * 40 + q] = *(uint2*)l4;
    }
    __syncthreads();

    uint32_t sb = smem_u32(smb);
    int wid = tid >> 5, lane = tid & 31;
    int mw = wid & 1, nw = wid >> 1;
    int gidx = lane >> 3;
    int a_soff = (gidx >> 1) * 8, a_poff = (gidx & 1) * 8;
    int b_soff = ((lane >> 3) & 1) * 8, b_noff = (lane >> 4) * 8;
    float acc[2][4] = {};
#pragma unroll
    for (int kf = 0; kf < 4; kf++) {
        int k0 = kf << 4;
        uint32_t xh4[4], xl4[4], bh4[4], bl4[4];
        uint32_t ax = sb + (uint32_t)((SA_XH + (k0 + a_soff + (lane & 7)) * 40
                                       + mw * 16 + a_poff) * 2);
        LDSM4T(xh4, ax);
        LDSM4T(xl4, ax + (SA_XL - SA_XH) * 2);
        uint32_t bad = sb + (uint32_t)((SA_BH + (k0 + b_soff + (lane & 7)) * 72
                                        + nw * 16 + b_noff) * 2);
        LDSM4T(bh4, bad);
        LDSM4T(bl4, bad + (SA_BL - SA_BH) * 2);
#pragma unroll
        for (int nf = 0; nf < 2; nf++) {
            MMA16816(acc[nf], xh4, bh4[nf * 2], bh4[nf * 2 + 1]);
            MMA16816(acc[nf], xh4, bl4[nf * 2], bl4[nf * 2 + 1]);
            MMA16816(acc[nf], xl4, bh4[nf * 2], bh4[nf * 2 + 1]);
        }
    }
    int g = lane >> 2, tg = lane & 3;
    size_t ub = (size_t)cid * 2048;
#pragma unroll
    for (int nf = 0; nf < 2; nf++) {
        int p = mw * 16 + g, n = nw * 16 + nf * 8 + tg * 2;
#pragma unroll
        for (int e = 0; e < 2; e++) {
            int pp = p + e * 8;
            __nv_bfloat16 h0, l0, h1, l1;
            split_bf16(acc[nf][e * 2 + 0], h0, l0);
            split_bf16(acc[nf][e * 2 + 1], h1, l1);
            __nv_bfloat16 hh[2] = {h0, h1}, ll[2] = {l0, l1};
            *(uint32_t*)&g_Uh[ub + pp * 64 + n] = *(uint32_t*)hh;
            *(uint32_t*)&g_Ul[ub + pp * 64 + n] = *(uint32_t*)ll;
        }
    }
}

// ---------------- SSD pass B: hs = W @ U via HMMA (W computed in-block) -----
#define SB_WH 0
#define SB_WL 4608
#define SB_UH 9216
#define SB_UL 13824
#define SB_END 18432
__global__ void __launch_bounds__(256) k_ssd_b_mma() {
    __shared__ __align__(16) __nv_bfloat16 smb[SB_END];
    __shared__ float sI[64];
    int tid = threadIdx.x, wid = tid >> 5, lane = tid & 31;
    int bh = blockIdx.x;
    int col0 = blockIdx.y * 64;
    if (tid < 64) {
        float v = g_T[bh * 64 + tid];
#pragma unroll
        for (int o = 1; o < 32; o <<= 1) {
            float u = __shfl_up_sync(0xffffffffu, v, o);
            if ((tid & 31) >= o) v += u;
        }
        sI[tid] = v;
    }
    __syncthreads();
    if (tid >= 32 && tid < 64) sI[tid] += sI[31];
    __syncthreads();
    // fill W split in smem
    for (int i = tid; i < 4096; i += 256) {
        int c = i >> 6, j = i & 63;
        float w = (j < c) ? __expf(sI[c - 1] - sI[j]) : 0.f;
        __nv_bfloat16 h, l;
        split_bf16(w, h, l);
        smb[SB_WH + c * 72 + j] = h;
        smb[SB_WL + c * 72 + j] = l;
    }
    // stage U raw (pre-split)
    for (int i = tid; i < 512; i += 256) {
        int j = i >> 3, q = (i & 7) * 8;
        *(uint4*)&smb[SB_UH + j * 72 + q] =
            *(const uint4*)&g_Uh[((size_t)bh * 64 + j) * 2048 + col0 + q];
        *(uint4*)&smb[SB_UL + j * 72 + q] =
            *(const uint4*)&g_Ul[((size_t)bh * 64 + j) * 2048 + col0 + q];
    }
    __syncthreads();
    uint32_t sb = smem_u32(smb);
    int mw = wid & 3, nw = wid >> 2;
    int crow = mw * 16, ncol = nw * 32;
    int lrow = lane & 15, lk = (lane >> 4) << 3;
    int b_soff = ((lane >> 3) & 1) * 8, b_noff = (lane >> 4) * 8;
    float acc[4][4] = {};
#pragma unroll
    for (int kf = 0; kf < 4; kf++) {
        int k0 = kf << 4;
        uint32_t whf[4], wlf[4];
        uint32_t ad = sb + (uint32_t)((SB_WH + (crow + lrow) * 72 + k0 + lk) * 2);
        LDSM4(whf, ad);
        LDSM4(wlf, ad + (SB_WL - SB_WH) * 2);
        uint32_t uh[2][4], ul[2][4];
#pragma unroll
        for (int hf = 0; hf < 2; hf++) {
            uint32_t ad2 = sb + (uint32_t)((SB_UH + (k0 + b_soff + (lane & 7)) * 72
                                            + ncol + hf * 16 + b_noff) * 2);
            LDSM4T(uh[hf], ad2);
            LDSM4T(ul[hf], ad2 + (SB_UL - SB_UH) * 2);
        }
#pragma unroll
        for (int nf = 0; nf < 4; nf++) {
            uint32_t* BH = &uh[nf >> 1][(nf & 1) * 2];
            uint32_t* BL = &ul[nf >> 1][(nf & 1) * 2];
            MMA16816(acc[nf], whf, BH[0], BH[1]);
            MMA16816(acc[nf], whf, BL[0], BL[1]);
            MMA16816(acc[nf], wlf, BH[0], BH[1]);
        }
    }
    int g = lane >> 2, tg = lane & 3;
#pragma unroll
    for (int nf = 0; nf < 4; nf++) {
        int col = col0 + ncol + nf * 8 + tg * 2;
#pragma unroll
        for (int e = 0; e < 2; e++) {
            int c = crow + g + e * 8;
            __nv_bfloat16 h0, l0, h1, l1;
            split_bf16(acc[nf][e * 2 + 0], h0, l0);
            split_bf16(acc[nf][e * 2 + 1], h1, l1);
            __nv_bfloat16 hh[2] = {h0, h1}, ll[2] = {l0, l1};
            *(uint32_t*)&g_hsh[((size_t)bh * 64 + c) * 2048 + col] = *(uint32_t*)hh;
            *(uint32_t*)&g_hsl[((size_t)bh * 64 + c) * 2048 + col] = *(uint32_t*)ll;
        }
    }
}

// ---------------- SSD pass C via HMMA bf16x3 --------------------------------
#define SC_P  72
#define SC_CH 0
#define SC_CL 4608
#define SC_BH 9216
#define SC_BL 13824
#define SC_XH 18432
#define SC_XL 20992
#define SC_HH 23552
#define SC_HL 25856
#define SC_END 28160
__global__ void __launch_bounds__(256, 2) k_ssd_c_mma(const float* __restrict__ Dp) {
    extern __shared__ __align__(16) __nv_bfloat16 smb[];
    float* Ssm = (float*)(smb + SC_END);
    float* dts = Ssm + 64;
    int tid = threadIdx.x, wid = tid >> 5, lane = tid & 31;
    int cid = blockIdx.x;
    int bh = cid >> 6, c = cid & 63;
    int b = bh >> 3, h = bh & 7;
    int r0 = b * LSEQ + c * QC;
    float Dh = Dp[h];

    for (int i = tid; i < 512; i += 256) {
        int s = i >> 3, q = (i & 7) * 8;
        size_t ro = (size_t)(r0 + s) * CONVD;
        *(uint4*)&smb[SC_CH + s * SC_P + q] = *(const uint4*)&g_xch[ro + 320 + q];
        *(uint4*)&smb[SC_CL + s * SC_P + q] = *(const uint4*)&g_xcl[ro + 320 + q];
        *(uint4*)&smb[SC_BH + s * SC_P + q] = *(const uint4*)&g_xch[ro + 256 + q];
        *(uint4*)&smb[SC_BL + s * SC_P + q] = *(const uint4*)&g_xcl[ro + 256 + q];
    }
    for (int i = tid; i < 256; i += 256) {
        int s = i >> 2, q = (i & 3) * 8;
        size_t ro = (size_t)(r0 + s) * CONVD + h * HD;
        *(uint4*)&smb[SC_XH + s * 40 + q] = *(const uint4*)&g_xch[ro + q];
        *(uint4*)&smb[SC_XL + s * 40 + q] = *(const uint4*)&g_xcl[ro + q];
    }
    for (int i = tid; i < 256; i += 256) {
        int p = i >> 3, q = (i & 7) * 8;
        size_t ho = (size_t)cid * 2048 + p * 64 + q;
        *(uint4*)&smb[SC_HH + p * SC_P + q] = *(const uint4*)&g_hsh[ho];
        *(uint4*)&smb[SC_HL + p * SC_P + q] = *(const uint4*)&g_hsl[ho];
    }
    if (tid < 64) {
        Ssm[tid] = g_S[(size_t)cid * QC + tid];
        dts[tid] = g_dtb[(size_t)(r0 + tid) * NH + h];
    }
    __syncthreads();

    uint32_t sb = smem_u32(smb);
    int mw = wid & 3, nw = wid >> 2;
    int arow = mw * 16;
    int lrow = lane & 15, lk = (lane >> 4) << 3;
    int brow = (lane & 7) + ((lane >> 4) & 1) * 8;
    int bk = ((lane >> 3) & 1) << 3;
    int b_soff = ((lane >> 3) & 1) * 8, b_noff = (lane >> 4) * 8;

    float accg[4][4] = {};
#pragma unroll
    for (int kf = 0; kf < 4; kf++) {
        int k0 = kf << 4;
        uint32_t ch[4], cl[4];
        uint32_t ad = sb + (uint32_t)(((arow + lrow) * SC_P + k0 + lk) * 2);
        LDSM4(ch, ad + SC_CH * 2);
        LDSM4(cl, ad + SC_CL * 2);
        uint32_t bh2[2][4], bl2[2][4];
#pragma unroll
        for (int ng = 0; ng < 2; ng++) {
            uint32_t ad2 = sb + (uint32_t)(((nw * 32 + ng * 16 + brow) * SC_P + k0 + bk) * 2);
            LDSM4(bh2[ng], ad2 + SC_BH * 2);
            LDSM4(bl2[ng], ad2 + SC_BL * 2);
        }
#pragma unroll
        for (int nf = 0; nf < 4; nf++) {
            uint32_t* BH = &bh2[nf >> 1][(nf & 1) * 2];
            uint32_t* BL = &bl2[nf >> 1][(nf & 1) * 2];
            MMA16816(accg[nf], ch, BH[0], BH[1]);
            MMA16816(accg[nf], ch, BL[0], BL[1]);
            MMA16816(accg[nf], cl, BH[0], BH[1]);
        }
    }
    __syncthreads();

    int g = lane >> 2, tg = lane & 3;
    int t0 = arow + g, t1 = arow + g + 8;
    float St0 = Ssm[t0], St1 = Ssm[t1];
#pragma unroll
    for (int nf = 0; nf < 4; nf++) {
#pragma unroll
        for (int e = 0; e < 2; e++) {
            int s = nw * 32 + nf * 8 + tg * 2 + e;
            float ds = dts[s], Ss = Ssm[s];
            float m0 = (s <= t0) ? accg[nf][e]     * __expf(St0 - Ss) * ds : 0.f;
            float m1 = (s <= t1) ? accg[nf][2 + e] * __expf(St1 - Ss) * ds : 0.f;
            __nv_bfloat16 hh0, ll0, hh1, ll1;
            split_bf16(m0, hh0, ll0);
            split_bf16(m1, hh1, ll1);
            smb[SC_BH + t0 * SC_P + s] = hh0;
            smb[SC_BL + t0 * SC_P + s] = ll0;
            smb[SC_BH + t1 * SC_P + s] = hh1;
            smb[SC_BL + t1 * SC_P + s] = ll1;
        }
    }
    __syncthreads();

    int pw = wid >> 2;
    int prow = pw * 16;
    float ayi[2][4] = {}, ayo[2][4] = {};
#pragma unroll
    for (int kf = 0; kf < 4; kf++) {
        int k0 = kf << 4;
        uint32_t ad = sb + (uint32_t)(((arow + lrow) * SC_P + k0 + lk) * 2);
        uint32_t mh[4], ml[4], ch[4], cl[4];
        LDSM4(mh, ad + SC_BH * 2);
        LDSM4(ml, ad + SC_BL * 2);
        LDSM4(ch, ad + SC_CH * 2);
        LDSM4(cl, ad + SC_CL * 2);
        uint32_t xh[4], xl[4], hh2[4], hl2[4];
        uint32_t adx = sb + (uint32_t)((SC_XH + (k0 + b_soff + (lane & 7)) * 40
                                        + prow + b_noff) * 2);
        LDSM4T(xh, adx);
        LDSM4T(xl, adx + (SC_XL - SC_XH) * 2);
        uint32_t adh = sb + (uint32_t)(((prow + brow) * SC_P + k0 + bk) * 2);
        LDSM4(hh2, adh + SC_HH * 2);
        LDSM4(hl2, adh + SC_HL * 2);
#pragma unroll
        for (int nf = 0; nf < 2; nf++) {
            uint32_t* XH = &xh[nf * 2];  uint32_t* XL = &xl[nf * 2];
            uint32_t* HH = &hh2[nf * 2]; uint32_t* HL = &hl2[nf * 2];
            MMA16816(ayi[nf], mh, XH[0], XH[1]);
            MMA16816(ayi[nf], mh, XL[0], XL[1]);
            MMA16816(ayi[nf], ml, XH[0], XH[1]);
            MMA16816(ayo[nf], ch, HH[0], HH[1]);
            MMA16816(ayo[nf], ch, HL[0], HL[1]);
            MMA16816(ayo[nf], cl, HH[0], HH[1]);
        }
    }

    float eS0 = __expf(St0), eS1 = __expf(St1);
#pragma unroll
    for (int nf = 0; nf < 2; nf++) {
        int p = prow + nf * 8 + tg * 2;
        float xv00 = __bfloat162float(smb[SC_XH + t0 * 40 + p])
                   + __bfloat162float(smb[SC_XL + t0 * 40 + p]);
        float xv01 = __bfloat162float(smb[SC_XH + t0 * 40 + p + 1])
                   + __bfloat162float(smb[SC_XL + t0 * 40 + p + 1]);
        float xv10 = __bfloat162float(smb[SC_XH + t1 * 40 + p])
                   + __bfloat162float(smb[SC_XL + t1 * 40 + p]);
        float xv11 = __bfloat162float(smb[SC_XH + t1 * 40 + p + 1])
                   + __bfloat162float(smb[SC_XL + t1 * 40 + p + 1]);
        *(float2*)&g_y[(size_t)(r0 + t0) * DINNER + h * HD + p] =
            make_float2(ayi[nf][0] + eS0 * ayo[nf][0] + Dh * xv00,
                        ayi[nf][1] + eS0 * ayo[nf][1] + Dh * xv01);
        *(float2*)&g_y[(size_t)(r0 + t1) * DINNER + h * HD + p] =
            make_float2(ayi[nf][2] + eS1 * ayo[nf][2] + Dh * xv10,
                        ayi[nf][3] + eS1 * ayo[nf][3] + Dh * xv11);
    }
}

// ---------------- K4a: gating + gated RMSNorm (warp/row) --------------------
__global__ void k_gate(const float* __restrict__ gw) {
    int r    = blockIdx.x * 8 + (threadIdx.x >> 5);
    int lane = threadIdx.x & 31;
    float4 y0 = *(const float4*)&g_y[(size_t)r * DINNER + lane * 4];
    float4 y1 = *(const float4*)&g_y[(size_t)r * DINNER + 128 + lane * 4];
    float4 z0 = *(const float4*)&g_zx[(size_t)r * DPROJ + lane * 4];
    float4 z1 = *(const float4*)&g_zx[(size_t)r * DPROJ + 128 + lane * 4];
    float gv[8];
    gv[0] = y0.x * silu(z0.x); gv[1] = y0.y * silu(z0.y);
    gv[2] = y0.z * silu(z0.z); gv[3] = y0.w * silu(z0.w);
    gv[4] = y1.x * silu(z1.x); gv[5] = y1.y * silu(z1.y);
    gv[6] = y1.z * silu(z1.z); gv[7] = y1.w * silu(z1.w);
    float ss = 0.f;
#pragma unroll
    for (int j = 0; j < 8; j++) ss += gv[j] * gv[j];
#pragma unroll
    for (int o = 16; o; o >>= 1) ss += __shfl_xor_sync(0xffffffffu, ss, o);
    float sc = rsqrtf(ss * (1.f / DINNER) + 1e-5f);
    float4 w0 = *(const float4*)&gw[lane * 4];
    float4 w1 = *(const float4*)&gw[128 + lane * 4];
    float wv[8] = {w0.x, w0.y, w0.z, w0.w, w1.x, w1.y, w1.z, w1.w};
    __nv_bfloat16 h[8], l[8];
#pragma unroll
    for (int j = 0; j < 8; j++) split_bf16(gv[j] * sc * wv[j], h[j], l[j]);
    *(uint2*)&g_gh[(size_t)r * DINNER + lane * 4]       = *(uint2*)&h[0];
    *(uint2*)&g_gh[(size_t)r * DINNER + 128 + lane * 4] = *(uint2*)&h[4];
    *(uint2*)&g_gl[(size_t)r * DINNER + lane * 4]       = *(uint2*)&l[0];
    *(uint2*)&g_gl[(size_t)r * DINNER + 128 + lane * 4] = *(uint2*)&l[4];
}

// ---------------- K4b: out_proj HMMA bf16x3 + residual, tile 64x128 ---------
#define OP_AH 0
#define OP_AL 8704
#define OP_BH 17408
#define OP_BL 34816
#define OP_TOT 52224
__global__ void __launch_bounds__(256, 2) k_outproj_mma(const float* __restrict__ x,
                                                        float* __restrict__ out) {
    extern __shared__ __align__(16) __nv_bfloat16 smb[];
    int tid = threadIdx.x, wid = tid >> 5, lane = tid & 31;
    int rowBase = blockIdx.x * 64;
    uint32_t sb = smem_u32(smb);
    int mw = wid & 3, nw = wid >> 2;
    int arow = mw * 16, ncol = nw * 64;
    float acc[8][4] = {};
    int lrow = lane & 15, lk = (lane >> 4) << 3;
    int brow = (lane & 7) + ((lane >> 4) & 1) * 8;
    int bk = ((lane >> 3) & 1) << 3;

    for (int kc = 0; kc < 2; kc++) {
        if (kc) __syncthreads();
        for (int i = tid; i < 1024; i += 256) {
            int r = i >> 4, c = (i & 15) << 3;
            size_t ao = (size_t)(rowBase + r) * DINNER + kc * 128 + c;
            *(uint4*)&smb[OP_AH + r * 136 + c] = *(const uint4*)(g_gh + ao);
            *(uint4*)&smb[OP_AL + r * 136 + c] = *(const uint4*)(g_gl + ao);
        }
        for (int i = tid; i < 2048; i += 256) {
            int r = i >> 4, c = (i & 15) << 3;
            size_t bo = (size_t)r * DINNER + kc * 128 + c;
            *(uint4*)&smb[OP_BH + r * 136 + c] = *(const uint4*)(g_woh + bo);
            *(uint4*)&smb[OP_BL + r * 136 + c] = *(const uint4*)(g_wol + bo);
        }
        __syncthreads();
#pragma unroll
        for (int kf = 0; kf < 8; kf++) {
            int k0 = kf << 4;
            uint32_t ah[4], al[4];
            uint32_t ad = sb + (uint32_t)(((arow + lrow) * 136 + k0 + lk) * 2);
            LDSM4(ah, ad + OP_AH * 2);
            LDSM4(al, ad + OP_AL * 2);
            uint32_t bh[4][4], bl[4][4];
#pragma unroll
            for (int ng = 0; ng < 4; ng++) {
                uint32_t ad2 = sb + (uint32_t)(((ncol + ng * 16 + brow) * 136 + k0 + bk) * 2);
                LDSM4(bh[ng], ad2 + OP_BH * 2);
                LDSM4(bl[ng], ad2 + OP_BL * 2);
            }
#pragma unroll
            for (int nf = 0; nf < 8; nf++) {
                uint32_t* BH = &bh[nf >> 1][(nf & 1) * 2];
                uint32_t* BL = &bl[nf >> 1][(nf & 1) * 2];
                MMA16816(acc[nf], ah, BH[0], BH[1]);
                MMA16816(acc[nf], ah, BL[0], BL[1]);
                MMA16816(acc[nf], al, BH[0], BH[1]);
            }
        }
    }
    int g = lane >> 2, tg = lane & 3;
    int r = rowBase + arow + g;
#pragma unroll
    for (int nf = 0; nf < 8; nf++) {
        int c = ncol + nf * 8 + tg * 2;
        float2 x0 = *(const float2*)&x[(size_t)r * DMODEL + c];
        float2 x1 = *(const float2*)&x[(size_t)(r + 8) * DMODEL + c];
        *(float2*)&out[(size_t)r * DMODEL + c] =
            make_float2(acc[nf][0] + x0.x, acc[nf][1] + x0.y);
        *(float2*)&out[(size_t)(r + 8) * DMODEL + c] =
            make_float2(acc[nf][2] + x1.x, acc[nf][3] + x1.y);
    }
}

extern "C" void kernel_launch(void* const* d_in, const int* in_sizes, int n_in,
                              void* d_out, int out_size) {
    const float* x          = (const float*)d_in[0];
    const float* norm_w     = (const float*)d_in[1];
    const float* in_proj_w  = (const float*)d_in[2];
    const float* conv_w     = (const float*)d_in[3];
    const float* conv_b     = (const float*)d_in[4];
    const float* dt_bias    = (const float*)d_in[5];
    const float* A_log      = (const float*)d_in[6];
    const float* D          = (const float*)d_in[7];
    const float* gnorm_w    = (const float*)d_in[8];
    const float* out_proj_w = (const float*)d_in[9];
    float* out = (float*)d_out;

    const int in_smem   = IP_TOT * 2;   // 87040 B
    const int out_smem  = OP_TOT * 2;   // 104448 B
    const int ssdc_smem = SC_END * 2 + 512;
    cudaFuncSetAttribute(k_inproj_mma,  cudaFuncAttributeMaxDynamicSharedMemorySize, in_smem);
    cudaFuncSetAttribute(k_outproj_mma, cudaFuncAttributeMaxDynamicSharedMemorySize, out_smem);
    cudaFuncSetAttribute(k_ssd_c_mma,   cudaFuncAttributeMaxDynamicSharedMemorySize, ssdc_smem);

    k_wsplit<<<113, 256>>>(in_proj_w, out_proj_w);
    k_rmsnorm<<<RTOT / 8, 256>>>(x, norm_w);
    k_inproj_mma<<<dim3(RTOT / 64, 7), 256, in_smem>>>();
    k_conv4<<<RTOT / 16, 384>>>(conv_w, conv_b);
    k_ssd_a_mma<<<NCID, 256>>>(A_log, dt_bias);
    k_ssd_b_mma<<<dim3(NBATCH * NH, 32), 256>>>();
    k_ssd_c_mma<<<NCID, 256, ssdc_smem>>>(D);
    k_gate<<<RTOT / 8, 256>>>(gnorm_w);
    k_outproj_mma<<<RTOT / 64, 256, out_smem>>>(x, out);
}

// round 13
// speedup vs baseline: 1.2369x; 1.0004x over previous
#include <cuda_runtime.h>
#include <cuda_bf16.h>
#include <cstdint>

#define RTOT   32768
#define LSEQ   4096
#define NBATCH 8
#define DMODEL 128
#define DPROJ  648
#define DINNER 256
#define CONVD  384
#define NH     8
#define HD     32
#define QC     64
#define NCHK   (LSEQ/QC)
#define NCID   (NBATCH*NH*NCHK)

// ---------------- scratch (device globals) ----------------------------------
__device__ __align__(16) float g_zx [(size_t)RTOT * DPROJ];
__device__ __align__(16) float g_dtb[RTOT * NH];
__device__ __align__(16) float g_y  [RTOT * DINNER];
__device__ __align__(16) float g_S  [(size_t)NCID * QC];
__device__ __align__(16) float g_T  [NCID];
__device__ __align__(16) __nv_bfloat16 g_xch[RTOT * CONVD];
__device__ __align__(16) __nv_bfloat16 g_xcl[RTOT * CONVD];
__device__ __align__(16) __nv_bfloat16 g_Uh [(size_t)NCID * 2048];
__device__ __align__(16) __nv_bfloat16 g_Ul [(size_t)NCID * 2048];
__device__ __align__(16) __nv_bfloat16 g_hsh[(size_t)NCID * 2048];
__device__ __align__(16) __nv_bfloat16 g_hsl[(size_t)NCID * 2048];
__device__ __align__(16) __nv_bfloat16 g_ah [RTOT * DMODEL];
__device__ __align__(16) __nv_bfloat16 g_al [RTOT * DMODEL];
__device__ __align__(16) __nv_bfloat16 g_wih[672 * DMODEL];
__device__ __align__(16) __nv_bfloat16 g_wil[672 * DMODEL];
__device__ __align__(16) __nv_bfloat16 g_gh [RTOT * DINNER];
__device__ __align__(16) __nv_bfloat16 g_gl [RTOT * DINNER];
__device__ __align__(16) __nv_bfloat16 g_woh[DMODEL * DINNER];
__device__ __align__(16) __nv_bfloat16 g_wol[DMODEL * DINNER];
// -----------------------------------------------------------------------------

// ---- warp MMA helpers ----
static __device__ __forceinline__ uint32_t smem_u32(const void* p) {
    uint32_t a;
    asm("{ .reg .u64 t; cvta.to.shared.u64 t, %1; cvt.u32.u64 %0, t; }"
        : "=r"(a) : "l"(p));
    return a;
}
#define LDSM4(r, addr) \
    asm volatile("ldmatrix.sync.aligned.m8n8.x4.shared.b16 {%0,%1,%2,%3}, [%4];" \
        : "=r"((r)[0]), "=r"((r)[1]), "=r"((r)[2]), "=r"((r)[3]) : "r"(addr))
#define LDSM4T(r, addr) \
    asm volatile("ldmatrix.sync.aligned.m8n8.x4.trans.shared.b16 {%0,%1,%2,%3}, [%4];" \
        : "=r"((r)[0]), "=r"((r)[1]), "=r"((r)[2]), "=r"((r)[3]) : "r"(addr))
#define MMA16816(d, a, b0, b1) \
    asm volatile("mma.sync.aligned.m16n8k16.row.col.f32.bf16.bf16.f32 " \
        "{%0,%1,%2,%3}, {%4,%5,%6,%7}, {%8,%9}, {%0,%1,%2,%3};" \
        : "+f"((d)[0]), "+f"((d)[1]), "+f"((d)[2]), "+f"((d)[3]) \
        : "r"((a)[0]), "r"((a)[1]), "r"((a)[2]), "r"((a)[3]), "r"(b0), "r"(b1))

static __device__ __forceinline__ void split_bf16(float v, __nv_bfloat16& h,
                                                  __nv_bfloat16& l) {
    h = __float2bfloat16(v);
    l = __float2bfloat16(v - __bfloat162float(h));
}
static __device__ __forceinline__ void split4(float4 v, __nv_bfloat16* h,
                                              __nv_bfloat16* l) {
    split_bf16(v.x, h[0], l[0]); split_bf16(v.y, h[1], l[1]);
    split_bf16(v.z, h[2], l[2]); split_bf16(v.w, h[3], l[3]);
}
static __device__ __forceinline__ float silu(float v) {
    return v / (1.f + __expf(-v));
}

// ---------------- K0: fused weight-split + RMSNorm --------------------------
// blocks [0,4096): rmsnorm (8 rows/block); blocks [4096,4209): weight split.
__global__ void k_prep(const float* __restrict__ x, const float* __restrict__ w,
                       const float* __restrict__ Wi, const float* __restrict__ Wo) {
    if (blockIdx.x < 4096) {
        int row  = blockIdx.x * 8 + (threadIdx.x >> 5);
        int lane = threadIdx.x & 31;
        float4 v = ((const float4*)(x + (size_t)row * DMODEL))[lane];
        float ss = v.x * v.x + v.y * v.y + v.z * v.z + v.w * v.w;
#pragma unroll
        for (int o = 16; o; o >>= 1) ss += __shfl_xor_sync(0xffffffffu, ss, o);
        float sc = rsqrtf(ss * (1.f / DMODEL) + 1e-5f);
        float4 wv = ((const float4*)w)[lane];
        float4 o4;
        o4.x = v.x * sc * wv.x; o4.y = v.y * sc * wv.y;
        o4.z = v.z * sc * wv.z; o4.w = v.w * sc * wv.w;
        __nv_bfloat16 h[4], l[4];
        split4(o4, h, l);
        ((uint2*)(g_ah + (size_t)row * DMODEL))[lane] = *(uint2*)h;
        ((uint2*)(g_al + (size_t)row * DMODEL))[lane] = *(uint2*)l;
    } else {
        int idx = (blockIdx.x - 4096) * 256 + threadIdx.x;
        const int NWI = DPROJ * DMODEL / 4;
        const int NWO = DMODEL * DINNER / 4;
        if (idx < NWI) {
            float4 v = ((const float4*)Wi)[idx];
            __nv_bfloat16 h[4], l[4];
            split4(v, h, l);
            ((uint2*)g_wih)[idx] = *(uint2*)h;
            ((uint2*)g_wil)[idx] = *(uint2*)l;
        } else if (idx < NWI + NWO) {
            int j = idx - NWI;
            float4 v = ((const float4*)Wo)[j];
            __nv_bfloat16 h[4], l[4];
            split4(v, h, l);
            ((uint2*)g_woh)[j] = *(uint2*)h;
            ((uint2*)g_wol)[j] = *(uint2*)l;
        }
    }
}

// ---------------- K1: in_proj GEMM via HMMA bf16x3, tile 64x96, K=128 -------
#define IP_AH 0
#define IP_AL 8704
#define IP_BH 17408
#define IP_BL 30464
#define IP_TOT 43520
__global__ void __launch_bounds__(256, 2) k_inproj_mma() {
    extern __shared__ __align__(16) __nv_bfloat16 smb[];
    int tid = threadIdx.x, wid = tid >> 5, lane = tid & 31;
    int rowBase = blockIdx.x * 64;
    int colBase = blockIdx.y * 96;

    for (int i = tid; i < 1024; i += 256) {
        int r = i >> 4, c = (i & 15) << 3;
        *(uint4*)&smb[IP_AH + r * 136 + c] =
            *(const uint4*)(g_ah + (size_t)(rowBase + r) * DMODEL + c);
        *(uint4*)&smb[IP_AL + r * 136 + c] =
            *(const uint4*)(g_al + (size_t)(rowBase + r) * DMODEL + c);
    }
    for (int i = tid; i < 1536; i += 256) {
        int r = i >> 4, c = (i & 15) << 3;
        *(uint4*)&smb[IP_BH + r * 136 + c] =
            *(const uint4*)(g_wih + (size_t)(colBase + r) * DMODEL + c);
        *(uint4*)&smb[IP_BL + r * 136 + c] =
            *(const uint4*)(g_wil + (size_t)(colBase + r) * DMODEL + c);
    }
    __syncthreads();

    uint32_t sb = smem_u32(smb);
    int mw = wid & 3, nw = wid >> 2;
    int arow = mw * 16, ncol = nw * 48;
    float acc[6][4] = {};
    int lrow = lane & 15, lk = (lane >> 4) << 3;
    int brow = (lane & 7) + ((lane >> 4) & 1) * 8;
    int bk = ((lane >> 3) & 1) << 3;
#pragma unroll
    for (int kf = 0; kf < 8; kf++) {
        int k0 = kf << 4;
        uint32_t ah[4], al[4];
        uint32_t ad = sb + (uint32_t)(((arow + lrow) * 136 + k0 + lk) * 2);
        LDSM4(ah, ad + IP_AH * 2);
        LDSM4(al, ad + IP_AL * 2);
        uint32_t bh[3][4], bl[3][4];
#pragma unroll
        for (int ng = 0; ng < 3; ng++) {
            uint32_t ad2 = sb + (uint32_t)(((ncol + ng * 16 + brow) * 136 + k0 + bk) * 2);
            LDSM4(bh[ng], ad2 + IP_BH * 2);
            LDSM4(bl[ng], ad2 + IP_BL * 2);
        }
#pragma unroll
        for (int nf = 0; nf < 6; nf++) {
            uint32_t* BH = &bh[nf >> 1][(nf & 1) * 2];
            uint32_t* BL = &bl[nf >> 1][(nf & 1) * 2];
            MMA16816(acc[nf], ah, BH[0], BH[1]);
            MMA16816(acc[nf], ah, BL[0], BL[1]);
            MMA16816(acc[nf], al, BH[0], BH[1]);
        }
    }
    int g = lane >> 2, tg = lane & 3;
    int r = rowBase + arow + g;
#pragma unroll
    for (int nf = 0; nf < 6; nf++) {
        int c = colBase + ncol + nf * 8 + tg * 2;
        if (c < DPROJ) {
            *(float2*)&g_zx[(size_t)r * DPROJ + c] =
                make_float2(acc[nf][0], acc[nf][1]);
            *(float2*)&g_zx[(size_t)(r + 8) * DPROJ + c] =
                make_float2(acc[nf][2], acc[nf][3]);
        }
    }
}

// ---------------- K2: conv(K=4)+SiLU -> bf16 hi/lo splits -------------------
__global__ void __launch_bounds__(384) k_conv4(const float* __restrict__ cw,
                                               const float* __restrict__ cb) {
    int t = threadIdx.x;
    int c = (t % 96) * 4;
    int r0 = blockIdx.x * 16 + (t / 96) * 4;
    bool hist = (r0 & (LSEQ - 1)) != 0;
    float4 wA = *(const float4*)&cw[(c + 0) * 4];
    float4 wB = *(const float4*)&cw[(c + 1) * 4];
    float4 wC = *(const float4*)&cw[(c + 2) * 4];
    float4 wD = *(const float4*)&cw[(c + 3) * 4];
    float4 bias = *(const float4*)&cb[c];
    const float* src = g_zx + 256 + c;
    float4 z = make_float4(0.f, 0.f, 0.f, 0.f);
    float4 x0 = hist ? *(const float4*)&src[(size_t)(r0 - 3) * DPROJ] : z;
    float4 x1 = hist ? *(const float4*)&src[(size_t)(r0 - 2) * DPROJ] : z;
    float4 x2 = hist ? *(const float4*)&src[(size_t)(r0 - 1) * DPROJ] : z;
#pragma unroll
    for (int s = 0; s < 4; s++) {
        int r = r0 + s;
        float4 x3 = *(const float4*)&src[(size_t)r * DPROJ];
        float4 o;
        o.x = silu(bias.x + wA.x * x0.x + wA.y * x1.x + wA.z * x2.x + wA.w * x3.x);
        o.y = silu(bias.y + wB.x * x0.y + wB.y * x1.y + wB.z * x2.y + wB.w * x3.y);
        o.z = silu(bias.z + wC.x * x0.z + wC.y * x1.z + wC.z * x2.z + wC.w * x3.z);
        o.w = silu(bias.w + wD.x * x0.w + wD.y * x1.w + wD.z * x2.w + wD.w * x3.w);
        __nv_bfloat16 h4[4], l4[4];
        split4(o, h4, l4);
        *(uint2*)&g_xch[(size_t)r * CONVD + c] = *(uint2*)h4;
        *(uint2*)&g_xcl[(size_t)r * CONVD + c] = *(uint2*)l4;
        x0 = x1; x1 = x2; x2 = x3;
    }
}

// ---------------- SSD pass A via HMMA bf16x3 --------------------------------
#define SA_BH 0
#define SA_BL 4608
#define SA_XH 9216
#define SA_XL 11776
#define SA_END 14336
__global__ void __launch_bounds__(256) k_ssd_a_mma(const float* __restrict__ A_log,
                                                   const float* __restrict__ dtb) {
    __shared__ __align__(16) __nv_bfloat16 smb[SA_END];
    __shared__ float sdt[64], sS[64], ssc[64];
    int tid = threadIdx.x;
    int cid = blockIdx.x;
    int bh = cid >> 6, c = cid & 63;
    int b = bh >> 3, h = bh & 7;
    int r0 = b * LSEQ + c * QC;
    float A = -__expf(A_log[h]);

    if (tid < 64) {
        float v = g_zx[(size_t)(r0 + tid) * DPROJ + 640 + h] + dtb[h];
        v = (v > 20.f) ? v : log1pf(__expf(v));
        sdt[tid] = v;
        g_dtb[(size_t)(r0 + tid) * NH + h] = v;
    }
    for (int i = tid; i < 512; i += 256) {
        int s = i >> 3, q = (i & 7) * 8;
        *(uint4*)&smb[SA_BH + s * 72 + q] =
            *(const uint4*)&g_xch[(size_t)(r0 + s) * CONVD + 256 + q];
        *(uint4*)&smb[SA_BL + s * 72 + q] =
            *(const uint4*)&g_xcl[(size_t)(r0 + s) * CONVD + 256 + q];
    }
    __syncthreads();
    if (tid < 64) {
        float v = sdt[tid] * A;
#pragma unroll
        for (int o = 1; o < 32; o <<= 1) {
            float u = __shfl_up_sync(0xffffffffu, v, o);
            if ((tid & 31) >= o) v += u;
        }
        sS[tid] = v;
    }
    __syncthreads();
    if (tid >= 32 && tid < 64) sS[tid] += sS[31];
    __syncthreads();
    float T = sS[63];
    if (tid < 64) {
        float sv = sS[tid];
        g_S[(size_t)cid * QC + tid] = sv;
        ssc[tid] = __expf(T - sv) * sdt[tid];
    }
    if (tid == 0) g_T[cid] = T;
    __syncthreads();
    for (int i = tid; i < 512; i += 256) {
        int s = i >> 3, q = (i & 7) * 4;
        uint2 hv = *(const uint2*)&g_xch[(size_t)(r0 + s) * CONVD + h * HD + q];
        uint2 lv = *(const uint2*)&g_xcl[(size_t)(r0 + s) * CONVD + h * HD + q];
        __nv_bfloat16* hp = (__nv_bfloat16*)&hv;
        __nv_bfloat16* lp = (__nv_bfloat16*)&lv;
        float sc = ssc[s];
        __nv_bfloat16 h4[4], l4[4];
#pragma unroll
        for (int j = 0; j < 4; j++) {
            float xv = (__bfloat162float(hp[j]) + __bfloat162float(lp[j])) * sc;
            split_bf16(xv, h4[j], l4[j]);
        }
        *(uint2*)&smb[SA_XH + s * 40 + q] = *(uint2*)h4;
        *(uint2*)&smb[SA_XL + s * 40 + q] = *(uint2*)l4;
    }
    __syncthreads();

    uint32_t sb = smem_u32(smb);
    int wid = tid >> 5, lane = tid & 31;
    int mw = wid & 1, nw = wid >> 1;
    int gidx = lane >> 3;
    int a_soff = (gidx >> 1) * 8, a_poff = (gidx & 1) * 8;
    int b_soff = ((lane >> 3) & 1) * 8, b_noff = (lane >> 4) * 8;
    float acc[2][4] = {};
#pragma unroll
    for (int kf = 0; kf < 4; kf++) {
        int k0 = kf << 4;
        uint32_t xh4[4], xl4[4], bh4[4], bl4[4];
        uint32_t ax = sb + (uint32_t)((SA_XH + (k0 + a_soff + (lane & 7)) * 40
                                       + mw * 16 + a_poff) * 2);
        LDSM4T(xh4, ax);
        LDSM4T(xl4, ax + (SA_XL - SA_XH) * 2);
        uint32_t bad = sb + (uint32_t)((SA_BH + (k0 + b_soff + (lane & 7)) * 72
                                        + nw * 16 + b_noff) * 2);
        LDSM4T(bh4, bad);
        LDSM4T(bl4, bad + (SA_BL - SA_BH) * 2);
#pragma unroll
        for (int nf = 0; nf < 2; nf++) {
            MMA16816(acc[nf], xh4, bh4[nf * 2], bh4[nf * 2 + 1]);
            MMA16816(acc[nf], xh4, bl4[nf * 2], bl4[nf * 2 + 1]);
            MMA16816(acc[nf], xl4, bh4[nf * 2], bh4[nf * 2 + 1]);
        }
    }
    int g = lane >> 2, tg = lane & 3;
    size_t ub = (size_t)cid * 2048;
#pragma unroll
    for (int nf = 0; nf < 2; nf++) {
        int p = mw * 16 + g, n = nw * 16 + nf * 8 + tg * 2;
#pragma unroll
        for (int e = 0; e < 2; e++) {
            int pp = p + e * 8;
            __nv_bfloat16 h0, l0, h1, l1;
            split_bf16(acc[nf][e * 2 + 0], h0, l0);
            split_bf16(acc[nf][e * 2 + 1], h1, l1);
            __nv_bfloat16 hh[2] = {h0, h1}, ll[2] = {l0, l1};
            *(uint32_t*)&g_Uh[ub + pp * 64 + n] = *(uint32_t*)hh;
            *(uint32_t*)&g_Ul[ub + pp * 64 + n] = *(uint32_t*)ll;
        }
    }
}

// ---------------- SSD pass B: hs = W @ U via HMMA (W computed in-block) -----
#define SB_WH 0
#define SB_WL 4608
#define SB_UH 9216
#define SB_UL 13824
#define SB_END 18432
__global__ void __launch_bounds__(256) k_ssd_b_mma() {
    __shared__ __align__(16) __nv_bfloat16 smb[SB_END];
    __shared__ float sI[64];
    int tid = threadIdx.x, wid = tid >> 5, lane = tid & 31;
    int bh = blockIdx.x;
    int col0 = blockIdx.y * 64;
    if (tid < 64) {
        float v = g_T[bh * 64 + tid];
#pragma unroll
        for (int o = 1; o < 32; o <<= 1) {
            float u = __shfl_up_sync(0xffffffffu, v, o);
            if ((tid & 31) >= o) v += u;
        }
        sI[tid] = v;
    }
    __syncthreads();
    if (tid >= 32 && tid < 64) sI[tid] += sI[31];
    __syncthreads();
    for (int i = tid; i < 4096; i += 256) {
        int c = i >> 6, j = i & 63;
        float w = (j < c) ? __expf(sI[c - 1] - sI[j]) : 0.f;
        __nv_bfloat16 h, l;
        split_bf16(w, h, l);
        smb[SB_WH + c * 72 + j] = h;
        smb[SB_WL + c * 72 + j] = l;
    }
    for (int i = tid; i < 512; i += 256) {
        int j = i >> 3, q = (i & 7) * 8;
        *(uint4*)&smb[SB_UH + j * 72 + q] =
            *(const uint4*)&g_Uh[((size_t)bh * 64 + j) * 2048 + col0 + q];
        *(uint4*)&smb[SB_UL + j * 72 + q] =
            *(const uint4*)&g_Ul[((size_t)bh * 64 + j) * 2048 + col0 + q];
    }
    __syncthreads();
    uint32_t sb = smem_u32(smb);
    int mw = wid & 3, nw = wid >> 2;
    int crow = mw * 16, ncol = nw * 32;
    int lrow = lane & 15, lk = (lane >> 4) << 3;
    int b_soff = ((lane >> 3) & 1) * 8, b_noff = (lane >> 4) * 8;
    float acc[4][4] = {};
#pragma unroll
    for (int kf = 0; kf < 4; kf++) {
        int k0 = kf << 4;
        uint32_t whf[4], wlf[4];
        uint32_t ad = sb + (uint32_t)((SB_WH + (crow + lrow) * 72 + k0 + lk) * 2);
        LDSM4(whf, ad);
        LDSM4(wlf, ad + (SB_WL - SB_WH) * 2);
        uint32_t uh[2][4], ul[2][4];
#pragma unroll
        for (int hf = 0; hf < 2; hf++) {
            uint32_t ad2 = sb + (uint32_t)((SB_UH + (k0 + b_soff + (lane & 7)) * 72
                                            + ncol + hf * 16 + b_noff) * 2);
            LDSM4T(uh[hf], ad2);
            LDSM4T(ul[hf], ad2 + (SB_UL - SB_UH) * 2);
        }
#pragma unroll
        for (int nf = 0; nf < 4; nf++) {
            uint32_t* BH = &uh[nf >> 1][(nf & 1) * 2];
            uint32_t* BL = &ul[nf >> 1][(nf & 1) * 2];
            MMA16816(acc[nf], whf, BH[0], BH[1]);
            MMA16816(acc[nf], whf, BL[0], BL[1]);
            MMA16816(acc[nf], wlf, BH[0], BH[1]);
        }
    }
    int g = lane >> 2, tg = lane & 3;
#pragma unroll
    for (int nf = 0; nf < 4; nf++) {
        int col = col0 + ncol + nf * 8 + tg * 2;
#pragma unroll
        for (int e = 0; e < 2; e++) {
            int c = crow + g + e * 8;
            __nv_bfloat16 h0, l0, h1, l1;
            split_bf16(acc[nf][e * 2 + 0], h0, l0);
            split_bf16(acc[nf][e * 2 + 1], h1, l1);
            __nv_bfloat16 hh[2] = {h0, h1}, ll[2] = {l0, l1};
            *(uint32_t*)&g_hsh[((size_t)bh * 64 + c) * 2048 + col] = *(uint32_t*)hh;
            *(uint32_t*)&g_hsl[((size_t)bh * 64 + c) * 2048 + col] = *(uint32_t*)ll;
        }
    }
}

// ---------------- SSD pass C via HMMA bf16x3 (occ 3) ------------------------
#define SC_P  72
#define SC_CH 0
#define SC_CL 4608
#define SC_BH 9216
#define SC_BL 13824
#define SC_XH 18432
#define SC_XL 20992
#define SC_HH 23552
#define SC_HL 25856
#define SC_END 28160
__global__ void __launch_bounds__(256, 3) k_ssd_c_mma(const float* __restrict__ Dp) {
    extern __shared__ __align__(16) __nv_bfloat16 smb[];
    float* Ssm = (float*)(smb + SC_END);
    float* dts = Ssm + 64;
    int tid = threadIdx.x, wid = tid >> 5, lane = tid & 31;
    int cid = blockIdx.x;
    int bh = cid >> 6, c = cid & 63;
    int b = bh >> 3, h = bh & 7;
    int r0 = b * LSEQ + c * QC;
    float Dh = Dp[h];

    for (int i = tid; i < 512; i += 256) {
        int s = i >> 3, q = (i & 7) * 8;
        size_t ro = (size_t)(r0 + s) * CONVD;
        *(uint4*)&smb[SC_CH + s * SC_P + q] = *(const uint4*)&g_xch[ro + 320 + q];
        *(uint4*)&smb[SC_CL + s * SC_P + q] = *(const uint4*)&g_xcl[ro + 320 + q];
        *(uint4*)&smb[SC_BH + s * SC_P + q] = *(const uint4*)&g_xch[ro + 256 + q];
        *(uint4*)&smb[SC_BL + s * SC_P + q] = *(const uint4*)&g_xcl[ro + 256 + q];
    }
    for (int i = tid; i < 256; i += 256) {
        int s = i >> 2, q = (i & 3) * 8;
        size_t ro = (size_t)(r0 + s) * CONVD + h * HD;
        *(uint4*)&smb[SC_XH + s * 40 + q] = *(const uint4*)&g_xch[ro + q];
        *(uint4*)&smb[SC_XL + s * 40 + q] = *(const uint4*)&g_xcl[ro + q];
    }
    for (int i = tid; i < 256; i += 256) {
        int p = i >> 3, q = (i & 7) * 8;
        size_t ho = (size_t)cid * 2048 + p * 64 + q;
        *(uint4*)&smb[SC_HH + p * SC_P + q] = *(const uint4*)&g_hsh[ho];
        *(uint4*)&smb[SC_HL + p * SC_P + q] = *(const uint4*)&g_hsl[ho];
    }
    if (tid < 64) {
        Ssm[tid] = g_S[(size_t)cid * QC + tid];
        dts[tid] = g_dtb[(size_t)(r0 + tid) * NH + h];
    }
    __syncthreads();

    uint32_t sb = smem_u32(smb);
    int mw = wid & 3, nw = wid >> 2;
    int arow = mw * 16;
    int lrow = lane & 15, lk = (lane >> 4) << 3;
    int brow = (lane & 7) + ((lane >> 4) & 1) * 8;
    int bk = ((lane >> 3) & 1) << 3;
    int b_soff = ((lane >> 3) & 1) * 8, b_noff = (lane >> 4) * 8;

    float accg[4][4] = {};
    // warps with t-range fully below s-range are fully masked -> skip phase 1
    if (!(nw == 1 && mw < 2)) {
#pragma unroll
        for (int kf = 0; kf < 4; kf++) {
            int k0 = kf << 4;
            uint32_t ch[4], cl[4];
            uint32_t ad = sb + (uint32_t)(((arow + lrow) * SC_P + k0 + lk) * 2);
            LDSM4(ch, ad + SC_CH * 2);
            LDSM4(cl, ad + SC_CL * 2);
            uint32_t bh2[2][4], bl2[2][4];
#pragma unroll
            for (int ng = 0; ng < 2; ng++) {
                uint32_t ad2 = sb + (uint32_t)(((nw * 32 + ng * 16 + brow) * SC_P + k0 + bk) * 2);
                LDSM4(bh2[ng], ad2 + SC_BH * 2);
                LDSM4(bl2[ng], ad2 + SC_BL * 2);
            }
#pragma unroll
            for (int nf = 0; nf < 4; nf++) {
                uint32_t* BH = &bh2[nf >> 1][(nf & 1) * 2];
                uint32_t* BL = &bl2[nf >> 1][(nf & 1) * 2];
                MMA16816(accg[nf], ch, BH[0], BH[1]);
                MMA16816(accg[nf], ch, BL[0], BL[1]);
                MMA16816(accg[nf], cl, BH[0], BH[1]);
            }
        }
    }
    __syncthreads();

    int g = lane >> 2, tg = lane & 3;
    int t0 = arow + g, t1 = arow + g + 8;
    float St0 = Ssm[t0], St1 = Ssm[t1];
#pragma unroll
    for (int nf = 0; nf < 4; nf++) {
#pragma unroll
        for (int e = 0; e < 2; e++) {
            int s = nw * 32 + nf * 8 + tg * 2 + e;
            float ds = dts[s], Ss = Ssm[s];
            float m0 = (s <= t0) ? accg[nf][e]     * __expf(St0 - Ss) * ds : 0.f;
            float m1 = (s <= t1) ? accg[nf][2 + e] * __expf(St1 - Ss) * ds : 0.f;
            __nv_bfloat16 hh0, ll0, hh1, ll1;
            split_bf16(m0, hh0, ll0);
            split_bf16(m1, hh1, ll1);
            smb[SC_BH + t0 * SC_P + s] = hh0;
            smb[SC_BL + t0 * SC_P + s] = ll0;
            smb[SC_BH + t1 * SC_P + s] = hh1;
            smb[SC_BL + t1 * SC_P + s] = ll1;
        }
    }
    __syncthreads();

    int pw = wid >> 2;
    int prow = pw * 16;
    float ayi[2][4] = {}, ayo[2][4] = {};
#pragma unroll
    for (int kf = 0; kf < 4; kf++) {
        int k0 = kf << 4;
        uint32_t ad = sb + (uint32_t)(((arow + lrow) * SC_P + k0 + lk) * 2);
        uint32_t mh[4], ml[4], ch[4], cl[4];
        LDSM4(mh, ad + SC_BH * 2);
        LDSM4(ml, ad + SC_BL * 2);
        LDSM4(ch, ad + SC_CH * 2);
        LDSM4(cl, ad + SC_CL * 2);
        uint32_t xh[4], xl[4], hh2[4], hl2[4];
        uint32_t adx = sb + (uint32_t)((SC_XH + (k0 + b_soff + (lane & 7)) * 40
                                        + prow + b_noff) * 2);
        LDSM4T(xh, adx);
        LDSM4T(xl, adx + (SC_XL - SC_XH) * 2);
        uint32_t adh = sb + (uint32_t)(((prow + brow) * SC_P + k0 + bk) * 2);
        LDSM4(hh2, adh + SC_HH * 2);
        LDSM4(hl2, adh + SC_HL * 2);
#pragma unroll
        for (int nf = 0; nf < 2; nf++) {
            uint32_t* XH = &xh[nf * 2];  uint32_t* XL = &xl[nf * 2];
            uint32_t* HH = &hh2[nf * 2]; uint32_t* HL = &hl2[nf * 2];
            MMA16816(ayi[nf], mh, XH[0], XH[1]);
            MMA16816(ayi[nf], mh, XL[0], XL[1]);
            MMA16816(ayi[nf], ml, XH[0], XH[1]);
            MMA16816(ayo[nf], ch, HH[0], HH[1]);
            MMA16816(ayo[nf], ch, HL[0], HL[1]);
            MMA16816(ayo[nf], cl, HH[0], HH[1]);
        }
    }

    float eS0 = __expf(St0), eS1 = __expf(St1);
#pragma unroll
    for (int nf = 0; nf < 2; nf++) {
        int p = prow + nf * 8 + tg * 2;
        float xv00 = __bfloat162float(smb[SC_XH + t0 * 40 + p])
                   + __bfloat162float(smb[SC_XL + t0 * 40 + p]);
        float xv01 = __bfloat162float(smb[SC_XH + t0 * 40 + p + 1])
                   + __bfloat162float(smb[SC_XL + t0 * 40 + p + 1]);
        float xv10 = __bfloat162float(smb[SC_XH + t1 * 40 + p])
                   + __bfloat162float(smb[SC_XL + t1 * 40 + p]);
        float xv11 = __bfloat162float(smb[SC_XH + t1 * 40 + p + 1])
                   + __bfloat162float(smb[SC_XL + t1 * 40 + p + 1]);
        *(float2*)&g_y[(size_t)(r0 + t0) * DINNER + h * HD + p] =
            make_float2(ayi[nf][0] + eS0 * ayo[nf][0] + Dh * xv00,
                        ayi[nf][1] + eS0 * ayo[nf][1] + Dh * xv01);
        *(float2*)&g_y[(size_t)(r0 + t1) * DINNER + h * HD + p] =
            make_float2(ayi[nf][2] + eS1 * ayo[nf][2] + Dh * xv10,
                        ayi[nf][3] + eS1 * ayo[nf][3] + Dh * xv11);
    }
}

// ---------------- K4a: gating + gated RMSNorm (warp/row) --------------------
__global__ void k_gate(const float* __restrict__ gw) {
    int r    = blockIdx.x * 8 + (threadIdx.x >> 5);
    int lane = threadIdx.x & 31;
    float4 y0 = *(const float4*)&g_y[(size_t)r * DINNER + lane * 4];
    float4 y1 = *(const float4*)&g_y[(size_t)r * DINNER + 128 + lane * 4];
    float4 z0 = *(const float4*)&g_zx[(size_t)r * DPROJ + lane * 4];
    float4 z1 = *(const float4*)&g_zx[(size_t)r * DPROJ + 128 + lane * 4];
    float gv[8];
    gv[0] = y0.x * silu(z0.x); gv[1] = y0.y * silu(z0.y);
    gv[2] = y0.z * silu(z0.z); gv[3] = y0.w * silu(z0.w);
    gv[4] = y1.x * silu(z1.x); gv[5] = y1.y * silu(z1.y);
    gv[6] = y1.z * silu(z1.z); gv[7] = y1.w * silu(z1.w);
    float ss = 0.f;
#pragma unroll
    for (int j = 0; j < 8; j++) ss += gv[j] * gv[j];
#pragma unroll
    for (int o = 16; o; o >>= 1) ss += __shfl_xor_sync(0xffffffffu, ss, o);
    float sc = rsqrtf(ss * (1.f / DINNER) + 1e-5f);
    float4 w0 = *(const float4*)&gw[lane * 4];
    float4 w1 = *(const float4*)&gw[128 + lane * 4];
    float wv[8] = {w0.x, w0.y, w0.z, w0.w, w1.x, w1.y, w1.z, w1.w};
    __nv_bfloat16 h[8], l[8];
#pragma unroll
    for (int j = 0; j < 8; j++) split_bf16(gv[j] * sc * wv[j], h[j], l[j]);
    *(uint2*)&g_gh[(size_t)r * DINNER + lane * 4]       = *(uint2*)&h[0];
    *(uint2*)&g_gh[(size_t)r * DINNER + 128 + lane * 4] = *(uint2*)&h[4];
    *(uint2*)&g_gl[(size_t)r * DINNER + lane * 4]       = *(uint2*)&l[0];
    *(uint2*)&g_gl[(size_t)r * DINNER + 128 + lane * 4] = *(uint2*)&l[4];
}

// ---------------- K4b: out_proj HMMA bf16x3 + residual, tile 64x128 ---------
#define OP_AH 0
#define OP_AL 8704
#define OP_BH 17408
#define OP_BL 34816
#define OP_TOT 52224
__global__ void __launch_bounds__(256, 2) k_outproj_mma(const float* __restrict__ x,
                                                        float* __restrict__ out) {
    extern __shared__ __align__(16) __nv_bfloat16 smb[];
    int tid = threadIdx.x, wid = tid >> 5, lane = tid & 31;
    int rowBase = blockIdx.x * 64;
    uint32_t sb = smem_u32(smb);
    int mw = wid & 3, nw = wid >> 2;
    int arow = mw * 16, ncol = nw * 64;
    float acc[8][4] = {};
    int lrow = lane & 15, lk = (lane >> 4) << 3;
    int brow = (lane & 7) + ((lane >> 4) & 1) * 8;
    int bk = ((lane >> 3) & 1) << 3;

    for (int kc = 0; kc < 2; kc++) {
        if (kc) __syncthreads();
        for (int i = tid; i < 1024; i += 256) {
            int r = i >> 4, c = (i & 15) << 3;
            size_t ao = (size_t)(rowBase + r) * DINNER + kc * 128 + c;
            *(uint4*)&smb[OP_AH + r * 136 + c] = *(const uint4*)(g_gh + ao);
            *(uint4*)&smb[OP_AL + r * 136 + c] = *(const uint4*)(g_gl + ao);
        }
        for (int i = tid; i < 2048; i += 256) {
            int r = i >> 4, c = (i & 15) << 3;
            size_t bo = (size_t)r * DINNER + kc * 128 + c;
            *(uint4*)&smb[OP_BH + r * 136 + c] = *(const uint4*)(g_woh + bo);
            *(uint4*)&smb[OP_BL + r * 136 + c] = *(const uint4*)(g_wol + bo);
        }
        __syncthreads();
#pragma unroll
        for (int kf = 0; kf < 8; kf++) {
            int k0 = kf << 4;
            uint32_t ah[4], al[4];
            uint32_t ad = sb + (uint32_t)(((arow + lrow) * 136 + k0 + lk) * 2);
            LDSM4(ah, ad + OP_AH * 2);
            LDSM4(al, ad + OP_AL * 2);
            uint32_t bh[4][4], bl[4][4];
#pragma unroll
            for (int ng = 0; ng < 4; ng++) {
                uint32_t ad2 = sb + (uint32_t)(((ncol + ng * 16 + brow) * 136 + k0 + bk) * 2);
                LDSM4(bh[ng], ad2 + OP_BH * 2);
                LDSM4(bl[ng], ad2 + OP_BL * 2);
            }
#pragma unroll
            for (int nf = 0; nf < 8; nf++) {
                uint32_t* BH = &bh[nf >> 1][(nf & 1) * 2];
                uint32_t* BL = &bl[nf >> 1][(nf & 1) * 2];
                MMA16816(acc[nf], ah, BH[0], BH[1]);
                MMA16816(acc[nf], ah, BL[0], BL[1]);
                MMA16816(acc[nf], al, BH[0], BH[1]);
            }
        }
    }
    int g = lane >> 2, tg = lane & 3;
    int r = rowBase + arow + g;
#pragma unroll
    for (int nf = 0; nf < 8; nf++) {
        int c = ncol + nf * 8 + tg * 2;
        float2 x0 = *(const float2*)&x[(size_t)r * DMODEL + c];
        float2 x1 = *(const float2*)&x[(size_t)(r + 8) * DMODEL + c];
        *(float2*)&out[(size_t)r * DMODEL + c] =
            make_float2(acc[nf][0] + x0.x, acc[nf][1] + x0.y);
        *(float2*)&out[(size_t)(r + 8) * DMODEL + c] =
            make_float2(acc[nf][2] + x1.x, acc[nf][3] + x1.y);
    }
}

extern "C" void kernel_launch(void* const* d_in, const int* in_sizes, int n_in,
                              void* d_out, int out_size) {
    const float* x          = (const float*)d_in[0];
    const float* norm_w     = (const float*)d_in[1];
    const float* in_proj_w  = (const float*)d_in[2];
    const float* conv_w     = (const float*)d_in[3];
    const float* conv_b     = (const float*)d_in[4];
    const float* dt_bias    = (const float*)d_in[5];
    const float* A_log      = (const float*)d_in[6];
    const float* D          = (const float*)d_in[7];
    const float* gnorm_w    = (const float*)d_in[8];
    const float* out_proj_w = (const float*)d_in[9];
    float* out = (float*)d_out;

    const int in_smem   = IP_TOT * 2;   // 87040 B
    const int out_smem  = OP_TOT * 2;   // 104448 B
    const int ssdc_smem = SC_END * 2 + 512;
    cudaFuncSetAttribute(k_inproj_mma,  cudaFuncAttributeMaxDynamicSharedMemorySize, in_smem);
    cudaFuncSetAttribute(k_outproj_mma, cudaFuncAttributeMaxDynamicSharedMemorySize, out_smem);
    cudaFuncSetAttribute(k_ssd_c_mma,   cudaFuncAttributeMaxDynamicSharedMemorySize, ssdc_smem);

    k_prep<<<4096 + 113, 256>>>(x, norm_w, in_proj_w, out_proj_w);
    k_inproj_mma<<<dim3(RTOT / 64, 7), 256, in_smem>>>();
    k_conv4<<<RTOT / 16, 384>>>(conv_w, conv_b);
    k_ssd_a_mma<<<NCID, 256>>>(A_log, dt_bias);
    k_ssd_b_mma<<<dim3(NBATCH * NH, 32), 256>>>();
    k_ssd_c_mma<<<NCID, 256, ssdc_smem>>>(D);
    k_gate<<<RTOT / 8, 256>>>(gnorm_w);
    k_outproj_mma<<<RTOT / 64, 256, out_smem>>>(x, out);
}

// round 14
// speedup vs baseline: 1.2570x; 1.0162x over previous
#include <cuda_runtime.h>
#include <cuda_bf16.h>
#include <cstdint>

#define RTOT   32768
#define LSEQ   4096
#define NBATCH 8
#define DMODEL 128
#define DPROJ  648
#define DINNER 256
#define CONVD  384
#define NH     8
#define HD     32
#define QC     64
#define NCHK   (LSEQ/QC)
#define NCID   (NBATCH*NH*NCHK)

// ---------------- scratch (device globals) ----------------------------------
__device__ __align__(16) float g_zx [(size_t)RTOT * DPROJ];
__device__ __align__(16) float g_dtb[RTOT * NH];
__device__ __align__(16) float g_y  [RTOT * DINNER];
__device__ __align__(16) float g_S  [(size_t)NCID * QC];
__device__ __align__(16) float g_ssc[(size_t)NCID * QC];
__device__ __align__(16) float g_T  [NCID];
__device__ __align__(16) __nv_bfloat16 g_xch[RTOT * CONVD];
__device__ __align__(16) __nv_bfloat16 g_xcl[RTOT * CONVD];
__device__ __align__(16) __nv_bfloat16 g_Uh [(size_t)NCID * 2048];
__device__ __align__(16) __nv_bfloat16 g_Ul [(size_t)NCID * 2048];
__device__ __align__(16) __nv_bfloat16 g_hsh[(size_t)NCID * 2048];
__device__ __align__(16) __nv_bfloat16 g_hsl[(size_t)NCID * 2048];
__device__ __align__(16) __nv_bfloat16 g_ah [RTOT * DMODEL];
__device__ __align__(16) __nv_bfloat16 g_al [RTOT * DMODEL];
__device__ __align__(16) __nv_bfloat16 g_wih[672 * DMODEL];
__device__ __align__(16) __nv_bfloat16 g_wil[672 * DMODEL];
__device__ __align__(16) __nv_bfloat16 g_gh [RTOT * DINNER];
__device__ __align__(16) __nv_bfloat16 g_gl [RTOT * DINNER];
__device__ __align__(16) __nv_bfloat16 g_woh[DMODEL * DINNER];
__device__ __align__(16) __nv_bfloat16 g_wol[DMODEL * DINNER];
// -----------------------------------------------------------------------------

// ---- warp MMA helpers ----
static __device__ __forceinline__ uint32_t smem_u32(const void* p) {
    uint32_t a;
    asm("{ .reg .u64 t; cvta.to.shared.u64 t, %1; cvt.u32.u64 %0, t; }"
        : "=r"(a) : "l"(p));
    return a;
}
#define LDSM4(r, addr) \
    asm volatile("ldmatrix.sync.aligned.m8n8.x4.shared.b16 {%0,%1,%2,%3}, [%4];" \
        : "=r"((r)[0]), "=r"((r)[1]), "=r"((r)[2]), "=r"((r)[3]) : "r"(addr))
#define LDSM4T(r, addr) \
    asm volatile("ldmatrix.sync.aligned.m8n8.x4.trans.shared.b16 {%0,%1,%2,%3}, [%4];" \
        : "=r"((r)[0]), "=r"((r)[1]), "=r"((r)[2]), "=r"((r)[3]) : "r"(addr))
#define MMA16816(d, a, b0, b1) \
    asm volatile("mma.sync.aligned.m16n8k16.row.col.f32.bf16.bf16.f32 " \
        "{%0,%1,%2,%3}, {%4,%5,%6,%7}, {%8,%9}, {%0,%1,%2,%3};" \
        : "+f"((d)[0]), "+f"((d)[1]), "+f"((d)[2]), "+f"((d)[3]) \
        : "r"((a)[0]), "r"((a)[1]), "r"((a)[2]), "r"((a)[3]), "r"(b0), "r"(b1))

static __device__ __forceinline__ void split_bf16(float v, __nv_bfloat16& h,
                                                  __nv_bfloat16& l) {
    h = __float2bfloat16(v);
    l = __float2bfloat16(v - __bfloat162float(h));
}
static __device__ __forceinline__ void split4(float4 v, __nv_bfloat16* h,
                                              __nv_bfloat16* l) {
    split_bf16(v.x, h[0], l[0]); split_bf16(v.y, h[1], l[1]);
    split_bf16(v.z, h[2], l[2]); split_bf16(v.w, h[3], l[3]);
}
static __device__ __forceinline__ float silu(float v) {
    return v / (1.f + __expf(-v));
}

// ---------------- K0: fused weight-split + RMSNorm --------------------------
__global__ void k_prep(const float* __restrict__ x, const float* __restrict__ w,
                       const float* __restrict__ Wi, const float* __restrict__ Wo) {
    if (blockIdx.x < 4096) {
        int row  = blockIdx.x * 8 + (threadIdx.x >> 5);
        int lane = threadIdx.x & 31;
        float4 v = ((const float4*)(x + (size_t)row * DMODEL))[lane];
        float ss = v.x * v.x + v.y * v.y + v.z * v.z + v.w * v.w;
#pragma unroll
        for (int o = 16; o; o >>= 1) ss += __shfl_xor_sync(0xffffffffu, ss, o);
        float sc = rsqrtf(ss * (1.f / DMODEL) + 1e-5f);
        float4 wv = ((const float4*)w)[lane];
        float4 o4;
        o4.x = v.x * sc * wv.x; o4.y = v.y * sc * wv.y;
        o4.z = v.z * sc * wv.z; o4.w = v.w * sc * wv.w;
        __nv_bfloat16 h[4], l[4];
        split4(o4, h, l);
        ((uint2*)(g_ah + (size_t)row * DMODEL))[lane] = *(uint2*)h;
        ((uint2*)(g_al + (size_t)row * DMODEL))[lane] = *(uint2*)l;
    } else {
        int idx = (blockIdx.x - 4096) * 256 + threadIdx.x;
        const int NWI = DPROJ * DMODEL / 4;
        const int NWO = DMODEL * DINNER / 4;
        if (idx < NWI) {
            float4 v = ((const float4*)Wi)[idx];
            __nv_bfloat16 h[4], l[4];
            split4(v, h, l);
            ((uint2*)g_wih)[idx] = *(uint2*)h;
            ((uint2*)g_wil)[idx] = *(uint2*)l;
        } else if (idx < NWI + NWO) {
            int j = idx - NWI;
            float4 v = ((const float4*)Wo)[j];
            __nv_bfloat16 h[4], l[4];
            split4(v, h, l);
            ((uint2*)g_woh)[j] = *(uint2*)h;
            ((uint2*)g_wol)[j] = *(uint2*)l;
        }
    }
}

// ---------------- K1: in_proj GEMM via HMMA bf16x3, tile 64x96, K=128 -------
#define IP_AH 0
#define IP_AL 8704
#define IP_BH 17408
#define IP_BL 30464
#define IP_TOT 43520
__global__ void __launch_bounds__(256, 2) k_inproj_mma() {
    extern __shared__ __align__(16) __nv_bfloat16 smb[];
    int tid = threadIdx.x, wid = tid >> 5, lane = tid & 31;
    int rowBase = blockIdx.x * 64;
    int colBase = blockIdx.y * 96;

    for (int i = tid; i < 1024; i += 256) {
        int r = i >> 4, c = (i & 15) << 3;
        *(uint4*)&smb[IP_AH + r * 136 + c] =
            *(const uint4*)(g_ah + (size_t)(rowBase + r) * DMODEL + c);
        *(uint4*)&smb[IP_AL + r * 136 + c] =
            *(const uint4*)(g_al + (size_t)(rowBase + r) * DMODEL + c);
    }
    for (int i = tid; i < 1536; i += 256) {
        int r = i >> 4, c = (i & 15) << 3;
        *(uint4*)&smb[IP_BH + r * 136 + c] =
            *(const uint4*)(g_wih + (size_t)(colBase + r) * DMODEL + c);
        *(uint4*)&smb[IP_BL + r * 136 + c] =
            *(const uint4*)(g_wil + (size_t)(colBase + r) * DMODEL + c);
    }
    __syncthreads();

    uint32_t sb = smem_u32(smb);
    int mw = wid & 3, nw = wid >> 2;
    int arow = mw * 16, ncol = nw * 48;
    float acc[6][4] = {};
    int lrow = lane & 15, lk = (lane >> 4) << 3;
    int brow = (lane & 7) + ((lane >> 4) & 1) * 8;
    int bk = ((lane >> 3) & 1) << 3;
#pragma unroll
    for (int kf = 0; kf < 8; kf++) {
        int k0 = kf << 4;
        uint32_t ah[4], al[4];
        uint32_t ad = sb + (uint32_t)(((arow + lrow) * 136 + k0 + lk) * 2);
        LDSM4(ah, ad + IP_AH * 2);
        LDSM4(al, ad + IP_AL * 2);
        uint32_t bh[3][4], bl[3][4];
#pragma unroll
        for (int ng = 0; ng < 3; ng++) {
            uint32_t ad2 = sb + (uint32_t)(((ncol + ng * 16 + brow) * 136 + k0 + bk) * 2);
            LDSM4(bh[ng], ad2 + IP_BH * 2);
            LDSM4(bl[ng], ad2 + IP_BL * 2);
        }
#pragma unroll
        for (int nf = 0; nf < 6; nf++) {
            uint32_t* BH = &bh[nf >> 1][(nf & 1) * 2];
            uint32_t* BL = &bl[nf >> 1][(nf & 1) * 2];
            MMA16816(acc[nf], ah, BH[0], BH[1]);
            MMA16816(acc[nf], ah, BL[0], BL[1]);
            MMA16816(acc[nf], al, BH[0], BH[1]);
        }
    }
    int g = lane >> 2, tg = lane & 3;
    int r = rowBase + arow + g;
#pragma unroll
    for (int nf = 0; nf < 6; nf++) {
        int c = colBase + ncol + nf * 8 + tg * 2;
        if (c < DPROJ) {
            *(float2*)&g_zx[(size_t)r * DPROJ + c] =
                make_float2(acc[nf][0], acc[nf][1]);
            *(float2*)&g_zx[(size_t)(r + 8) * DPROJ + c] =
                make_float2(acc[nf][2], acc[nf][3]);
        }
    }
}

// ---------------- K2: conv(K=4)+SiLU -> bf16 hi/lo splits -------------------
__global__ void __launch_bounds__(384) k_conv4(const float* __restrict__ cw,
                                               const float* __restrict__ cb) {
    int t = threadIdx.x;
    int c = (t % 96) * 4;
    int r0 = blockIdx.x * 16 + (t / 96) * 4;
    bool hist = (r0 & (LSEQ - 1)) != 0;
    float4 wA = *(const float4*)&cw[(c + 0) * 4];
    float4 wB = *(const float4*)&cw[(c + 1) * 4];
    float4 wC = *(const float4*)&cw[(c + 2) * 4];
    float4 wD = *(const float4*)&cw[(c + 3) * 4];
    float4 bias = *(const float4*)&cb[c];
    const float* src = g_zx + 256 + c;
    float4 z = make_float4(0.f, 0.f, 0.f, 0.f);
    float4 x0 = hist ? *(const float4*)&src[(size_t)(r0 - 3) * DPROJ] : z;
    float4 x1 = hist ? *(const float4*)&src[(size_t)(r0 - 2) * DPROJ] : z;
    float4 x2 = hist ? *(const float4*)&src[(size_t)(r0 - 1) * DPROJ] : z;
#pragma unroll
    for (int s = 0; s < 4; s++) {
        int r = r0 + s;
        float4 x3 = *(const float4*)&src[(size_t)r * DPROJ];
        float4 o;
        o.x = silu(bias.x + wA.x * x0.x + wA.y * x1.x + wA.z * x2.x + wA.w * x3.x);
        o.y = silu(bias.y + wB.x * x0.y + wB.y * x1.y + wB.z * x2.y + wB.w * x3.y);
        o.z = silu(bias.z + wC.x * x0.z + wC.y * x1.z + wC.z * x2.z + wC.w * x3.z);
        o.w = silu(bias.w + wD.x * x0.w + wD.y * x1.w + wD.z * x2.w + wD.w * x3.w);
        __nv_bfloat16 h4[4], l4[4];
        split4(o, h4, l4);
        *(uint2*)&g_xch[(size_t)r * CONVD + c] = *(uint2*)h4;
        *(uint2*)&g_xcl[(size_t)r * CONVD + c] = *(uint2*)l4;
        x0 = x1; x1 = x2; x2 = x3;
    }
}

// ---------------- K_dt: dt + cumsum + scales per (b,chunk) ------------------
// block = (b, c): 64 rows x 8 heads. Coalesced dt loads; 8 one-warp 64-scans.
__global__ void __launch_bounds__(256) k_dtscan(const float* __restrict__ A_log,
                                                const float* __restrict__ dtb) {
    __shared__ float sdt[512];   // [h][s]
    int tid = threadIdx.x;
    int bc = blockIdx.x;
    int b = bc >> 6, c = bc & 63;
    int r0 = b * LSEQ + c * QC;
#pragma unroll
    for (int i = tid; i < 512; i += 256) {
        int s = i >> 3, hh = i & 7;
        float v = g_zx[(size_t)(r0 + s) * DPROJ + 640 + hh] + dtb[hh];
        v = (v > 20.f) ? v : log1pf(__expf(v));
        sdt[hh * 64 + s] = v;
        g_dtb[(size_t)(r0 + s) * NH + hh] = v;
    }
    __syncthreads();
    int w = tid >> 5, j = tid & 31;   // warp w handles head w
    float A = -__expf(A_log[w]);
    float d0 = sdt[w * 64 + 2 * j], d1 = sdt[w * 64 + 2 * j + 1];
    float v0 = d0 * A, v1 = d1 * A;
    float pair = v0 + v1;
    float ps = pair;
#pragma unroll
    for (int o = 1; o < 32; o <<= 1) {
        float u = __shfl_up_sync(0xffffffffu, ps, o);
        if (j >= o) ps += u;
    }
    float S0 = ps - pair + v0, S1 = ps;
    float T = __shfl_sync(0xffffffffu, ps, 31);
    int cid = ((b * NH + w) << 6) | c;
    *(float2*)&g_S[(size_t)cid * QC + 2 * j]   = make_float2(S0, S1);
    *(float2*)&g_ssc[(size_t)cid * QC + 2 * j] =
        make_float2(__expf(T - S0) * d0, __expf(T - S1) * d1);
    if (j == 0) g_T[cid] = T;
}

// ---------------- SSD pass A via HMMA bf16x3 (single sync) ------------------
#define SA_BH 0
#define SA_BL 4608
#define SA_XH 9216
#define SA_XL 11776
#define SA_END 14336
__global__ void __launch_bounds__(256) k_ssd_a_mma() {
    __shared__ __align__(16) __nv_bfloat16 smb[SA_END];
    int tid = threadIdx.x;
    int cid = blockIdx.x;
    int bh = cid >> 6, c = cid & 63;
    int b = bh >> 3, h = bh & 7;
    int r0 = b * LSEQ + c * QC;

    // stage B raw (pre-split by conv)
    for (int i = tid; i < 512; i += 256) {
        int s = i >> 3, q = (i & 7) * 8;
        *(uint4*)&smb[SA_BH + s * 72 + q] =
            *(const uint4*)&g_xch[(size_t)(r0 + s) * CONVD + 256 + q];
        *(uint4*)&smb[SA_BL + s * 72 + q] =
            *(const uint4*)&g_xcl[(size_t)(r0 + s) * CONVD + 256 + q];
    }
    // stage scaled X (scale precomputed by k_dtscan)
    for (int i = tid; i < 512; i += 256) {
        int s = i >> 3, q = (i & 7) * 4;
        uint2 hv = *(const uint2*)&g_xch[(size_t)(r0 + s) * CONVD + h * HD + q];
        uint2 lv = *(const uint2*)&g_xcl[(size_t)(r0 + s) * CONVD + h * HD + q];
        __nv_bfloat16* hp = (__nv_bfloat16*)&hv;
        __nv_bfloat16* lp = (__nv_bfloat16*)&lv;
        float sc = g_ssc[(size_t)cid * QC + s];
        __nv_bfloat16 h4[4], l4[4];
#pragma unroll
        for (int j = 0; j < 4; j++) {
            float xv = (__bfloat162float(hp[j]) + __bfloat162float(lp[j])) * sc;
            split_bf16(xv, h4[j], l4[j]);
        }
        *(uint2*)&smb[SA_XH + s * 40 + q] = *(uint2*)h4;
        *(uint2*)&smb[SA_XL + s * 40 + q] = *(uint2*)l4;
    }
    __syncthreads();

    uint32_t sb = smem_u32(smb);
    int wid = tid >> 5, lane = tid & 31;
    int mw = wid & 1, nw = wid >> 1;
    int gidx = lane >> 3;
    int a_soff = (gidx >> 1) * 8, a_poff = (gidx & 1) * 8;
    int b_soff = ((lane >> 3) & 1) * 8, b_noff = (lane >> 4) * 8;
    float acc[2][4] = {};
#pragma unroll
    for (int kf = 0; kf < 4; kf++) {
        int k0 = kf << 4;
        uint32_t xh4[4], xl4[4], bh4[4], bl4[4];
        uint32_t ax = sb + (uint32_t)((SA_XH + (k0 + a_soff + (lane & 7)) * 40
                                       + mw * 16 + a_poff) * 2);
        LDSM4T(xh4, ax);
        LDSM4T(xl4, ax + (SA_XL - SA_XH) * 2);
        uint32_t bad = sb + (uint32_t)((SA_BH + (k0 + b_soff + (lane & 7)) * 72
                                        + nw * 16 + b_noff) * 2);
        LDSM4T(bh4, bad);
        LDSM4T(bl4, bad + (SA_BL - SA_BH) * 2);
#pragma unroll
        for (int nf = 0; nf < 2; nf++) {
            MMA16816(acc[nf], xh4, bh4[nf * 2], bh4[nf * 2 + 1]);
            MMA16816(acc[nf], xh4, bl4[nf * 2], bl4[nf * 2 + 1]);
            MMA16816(acc[nf], xl4, bh4[nf * 2], bh4[nf * 2 + 1]);
        }
    }
    int g = lane >> 2, tg = lane & 3;
    size_t ub = (size_t)cid * 2048;
#pragma unroll
    for (int nf = 0; nf < 2; nf++) {
        int p = mw * 16 + g, n = nw * 16 + nf * 8 + tg * 2;
#pragma unroll
        for (int e = 0; e < 2; e++) {
            int pp = p + e * 8;
            __nv_bfloat16 h0, l0, h1, l1;
            split_bf16(acc[nf][e * 2 + 0], h0, l0);
            split_bf16(acc[nf][e * 2 + 1], h1, l1);
            __nv_bfloat16 hh[2] = {h0, h1}, ll[2] = {l0, l1};
            *(uint32_t*)&g_Uh[ub + pp * 64 + n] = *(uint32_t*)hh;
            *(uint32_t*)&g_Ul[ub + pp * 64 + n] = *(uint32_t*)ll;
        }
    }
}

// ---------------- SSD pass B: hs = W @ U via HMMA (W computed in-block) -----
#define SB_WH 0
#define SB_WL 4608
#define SB_UH 9216
#define SB_UL 13824
#define SB_END 18432
__global__ void __launch_bounds__(256) k_ssd_b_mma() {
    __shared__ __align__(16) __nv_bfloat16 smb[SB_END];
    __shared__ float sI[64];
    int tid = threadIdx.x, wid = tid >> 5, lane = tid & 31;
    int bh = blockIdx.x;
    int col0 = blockIdx.y * 64;
    if (tid < 64) {
        float v = g_T[bh * 64 + tid];
#pragma unroll
        for (int o = 1; o < 32; o <<= 1) {
            float u = __shfl_up_sync(0xffffffffu, v, o);
            if ((tid & 31) >= o) v += u;
        }
        sI[tid] = v;
    }
    __syncthreads();
    if (tid >= 32 && tid < 64) sI[tid] += sI[31];
    __syncthreads();
    for (int i = tid; i < 4096; i += 256) {
        int c = i >> 6, j = i & 63;
        float w = (j < c) ? __expf(sI[c - 1] - sI[j]) : 0.f;
        __nv_bfloat16 h, l;
        split_bf16(w, h, l);
        smb[SB_WH + c * 72 + j] = h;
        smb[SB_WL + c * 72 + j] = l;
    }
    for (int i = tid; i < 512; i += 256) {
        int j = i >> 3, q = (i & 7) * 8;
        *(uint4*)&smb[SB_UH + j * 72 + q] =
            *(const uint4*)&g_Uh[((size_t)bh * 64 + j) * 2048 + col0 + q];
        *(uint4*)&smb[SB_UL + j * 72 + q] =
            *(const uint4*)&g_Ul[((size_t)bh * 64 + j) * 2048 + col0 + q];
    }
    __syncthreads();
    uint32_t sb = smem_u32(smb);
    int mw = wid & 3, nw = wid >> 2;
    int crow = mw * 16, ncol = nw * 32;
    int lrow = lane & 15, lk = (lane >> 4) << 3;
    int b_soff = ((lane >> 3) & 1) * 8, b_noff = (lane >> 4) * 8;
    float acc[4][4] = {};
#pragma unroll
    for (int kf = 0; kf < 4; kf++) {
        int k0 = kf << 4;
        uint32_t whf[4], wlf[4];
        uint32_t ad = sb + (uint32_t)((SB_WH + (crow + lrow) * 72 + k0 + lk) * 2);
        LDSM4(whf, ad);
        LDSM4(wlf, ad + (SB_WL - SB_WH) * 2);
        uint32_t uh[2][4], ul[2][4];
#pragma unroll
        for (int hf = 0; hf < 2; hf++) {
            uint32_t ad2 = sb + (uint32_t)((SB_UH + (k0 + b_soff + (lane & 7)) * 72
                                            + ncol + hf * 16 + b_noff) * 2);
            LDSM4T(uh[hf], ad2);
            LDSM4T(ul[hf], ad2 + (SB_UL - SB_UH) * 2);
        }
#pragma unroll
        for (int nf = 0; nf < 4; nf++) {
            uint32_t* BH = &uh[nf >> 1][(nf & 1) * 2];
            uint32_t* BL = &ul[nf >> 1][(nf & 1) * 2];
            MMA16816(acc[nf], whf, BH[0], BH[1]);
            MMA16816(acc[nf], whf, BL[0], BL[1]);
            MMA16816(acc[nf], wlf, BH[0], BH[1]);
        }
    }
    int g = lane >> 2, tg = lane & 3;
#pragma unroll
    for (int nf = 0; nf < 4; nf++) {
        int col = col0 + ncol + nf * 8 + tg * 2;
#pragma unroll
        for (int e = 0; e < 2; e++) {
            int c = crow + g + e * 8;
            __nv_bfloat16 h0, l0, h1, l1;
            split_bf16(acc[nf][e * 2 + 0], h0, l0);
            split_bf16(acc[nf][e * 2 + 1], h1, l1);
            __nv_bfloat16 hh[2] = {h0, h1}, ll[2] = {l0, l1};
            *(uint32_t*)&g_hsh[((size_t)bh * 64 + c) * 2048 + col] = *(uint32_t*)hh;
            *(uint32_t*)&g_hsl[((size_t)bh * 64 + c) * 2048 + col] = *(uint32_t*)ll;
        }
    }
}

// ---------------- SSD pass C via HMMA bf16x3 (occ 3) ------------------------
#define SC_P  72
#define SC_CH 0
#define SC_CL 4608
#define SC_BH 9216
#define SC_BL 13824
#define SC_XH 18432
#define SC_XL 20992
#define SC_HH 23552
#define SC_HL 25856
#define SC_END 28160
__global__ void __launch_bounds__(256, 3) k_ssd_c_mma(const float* __restrict__ Dp) {
    extern __shared__ __align__(16) __nv_bfloat16 smb[];
    float* Ssm = (float*)(smb + SC_END);
    float* dts = Ssm + 64;
    int tid = threadIdx.x, wid = tid >> 5, lane = tid & 31;
    int cid = blockIdx.x;
    int bh = cid >> 6, c = cid & 63;
    int b = bh >> 3, h = bh & 7;
    int r0 = b * LSEQ + c * QC;
    float Dh = Dp[h];

    for (int i = tid; i < 512; i += 256) {
        int s = i >> 3, q = (i & 7) * 8;
        size_t ro = (size_t)(r0 + s) * CONVD;
        *(uint4*)&smb[SC_CH + s * SC_P + q] = *(const uint4*)&g_xch[ro + 320 + q];
        *(uint4*)&smb[SC_CL + s * SC_P + q] = *(const uint4*)&g_xcl[ro + 320 + q];
        *(uint4*)&smb[SC_BH + s * SC_P + q] = *(const uint4*)&g_xch[ro + 256 + q];
        *(uint4*)&smb[SC_BL + s * SC_P + q] = *(const uint4*)&g_xcl[ro + 256 + q];
    }
    for (int i = tid; i < 256; i += 256) {
        int s = i >> 2, q = (i & 3) * 8;
        size_t ro = (size_t)(r0 + s) * CONVD + h * HD;
        *(uint4*)&smb[SC_XH + s * 40 + q] = *(const uint4*)&g_xch[ro + q];
        *(uint4*)&smb[SC_XL + s * 40 + q] = *(const uint4*)&g_xcl[ro + q];
    }
    for (int i = tid; i < 256; i += 256) {
        int p = i >> 3, q = (i & 7) * 8;
        size_t ho = (size_t)cid * 2048 + p * 64 + q;
        *(uint4*)&smb[SC_HH + p * SC_P + q] = *(const uint4*)&g_hsh[ho];
        *(uint4*)&smb[SC_HL + p * SC_P + q] = *(const uint4*)&g_hsl[ho];
    }
    if (tid < 64) {
        Ssm[tid] = g_S[(size_t)cid * QC + tid];
        dts[tid] = g_dtb[(size_t)(r0 + tid) * NH + h];
    }
    __syncthreads();

    uint32_t sb = smem_u32(smb);
    int mw = wid & 3, nw = wid >> 2;
    int arow = mw * 16;
    int lrow = lane & 15, lk = (lane >> 4) << 3;
    int brow = (lane & 7) + ((lane >> 4) & 1) * 8;
    int bk = ((lane >> 3) & 1) << 3;
    int b_soff = ((lane >> 3) & 1) * 8, b_noff = (lane >> 4) * 8;

    float accg[4][4] = {};
    if (!(nw == 1 && mw < 2)) {
#pragma unroll
        for (int kf = 0; kf < 4; kf++) {
            int k0 = kf << 4;
            uint32_t ch[4], cl[4];
            uint32_t ad = sb + (uint32_t)(((arow + lrow) * SC_P + k0 + lk) * 2);
            LDSM4(ch, ad + SC_CH * 2);
            LDSM4(cl, ad + SC_CL * 2);
            uint32_t bh2[2][4], bl2[2][4];
#pragma unroll
            for (int ng = 0; ng < 2; ng++) {
                uint32_t ad2 = sb + (uint32_t)(((nw * 32 + ng * 16 + brow) * SC_P + k0 + bk) * 2);
                LDSM4(bh2[ng], ad2 + SC_BH * 2);
                LDSM4(bl2[ng], ad2 + SC_BL * 2);
            }
#pragma unroll
            for (int nf = 0; nf < 4; nf++) {
                uint32_t* BH = &bh2[nf >> 1][(nf & 1) * 2];
                uint32_t* BL = &bl2[nf >> 1][(nf & 1) * 2];
                MMA16816(accg[nf], ch, BH[0], BH[1]);
                MMA16816(accg[nf], ch, BL[0], BL[1]);
                MMA16816(accg[nf], cl, BH[0], BH[1]);
            }
        }
    }
    __syncthreads();

    int g = lane >> 2, tg = lane & 3;
    int t0 = arow + g, t1 = arow + g + 8;
    float St0 = Ssm[t0], St1 = Ssm[t1];
#pragma unroll
    for (int nf = 0; nf < 4; nf++) {
#pragma unroll
        for (int e = 0; e < 2; e++) {
            int s = nw * 32 + nf * 8 + tg * 2 + e;
            float ds = dts[s], Ss = Ssm[s];
            float m0 = (s <= t0) ? accg[nf][e]     * __expf(St0 - Ss) * ds : 0.f;
            float m1 = (s <= t1) ? accg[nf][2 + e] * __expf(St1 - Ss) * ds : 0.f;
            __nv_bfloat16 hh0, ll0, hh1, ll1;
            split_bf16(m0, hh0, ll0);
            split_bf16(m1, hh1, ll1);
            smb[SC_BH + t0 * SC_P + s] = hh0;
            smb[SC_BL + t0 * SC_P + s] = ll0;
            smb[SC_BH + t1 * SC_P + s] = hh1;
            smb[SC_BL + t1 * SC_P + s] = ll1;
        }
    }
    __syncthreads();

    int pw = wid >> 2;
    int prow = pw * 16;
    float ayi[2][4] = {}, ayo[2][4] = {};
#pragma unroll
    for (int kf = 0; kf < 4; kf++) {
        int k0 = kf << 4;
        uint32_t ad = sb + (uint32_t)(((arow + lrow) * SC_P + k0 + lk) * 2);
        uint32_t mh[4], ml[4], ch[4], cl[4];
        LDSM4(mh, ad + SC_BH * 2);
        LDSM4(ml, ad + SC_BL * 2);
        LDSM4(ch, ad + SC_CH * 2);
        LDSM4(cl, ad + SC_CL * 2);
        uint32_t xh[4], xl[4], hh2[4], hl2[4];
        uint32_t adx = sb + (uint32_t)((SC_XH + (k0 + b_soff + (lane & 7)) * 40
                                        + prow + b_noff) * 2);
        LDSM4T(xh, adx);
        LDSM4T(xl, adx + (SC_XL - SC_XH) * 2);
        uint32_t adh = sb + (uint32_t)(((prow + brow) * SC_P + k0 + bk) * 2);
        LDSM4(hh2, adh + SC_HH * 2);
        LDSM4(hl2, adh + SC_HL * 2);
#pragma unroll
        for (int nf = 0; nf < 2; nf++) {
            uint32_t* XH = &xh[nf * 2];  uint32_t* XL = &xl[nf * 2];
            uint32_t* HH = &hh2[nf * 2]; uint32_t* HL = &hl2[nf * 2];
            MMA16816(ayi[nf], mh, XH[0], XH[1]);
            MMA16816(ayi[nf], mh, XL[0], XL[1]);
            MMA16816(ayi[nf], ml, XH[0], XH[1]);
            MMA16816(ayo[nf], ch, HH[0], HH[1]);
            MMA16816(ayo[nf], ch, HL[0], HL[1]);
            MMA16816(ayo[nf], cl, HH[0], HH[1]);
        }
    }

    float eS0 = __expf(St0), eS1 = __expf(St1);
#pragma unroll
    for (int nf = 0; nf < 2; nf++) {
        int p = prow + nf * 8 + tg * 2;
        float xv00 = __bfloat162float(smb[SC_XH + t0 * 40 + p])
                   + __bfloat162float(smb[SC_XL + t0 * 40 + p]);
        float xv01 = __bfloat162float(smb[SC_XH + t0 * 40 + p + 1])
                   + __bfloat162float(smb[SC_XL + t0 * 40 + p + 1]);
        float xv10 = __bfloat162float(smb[SC_XH + t1 * 40 + p])
                   + __bfloat162float(smb[SC_XL + t1 * 40 + p]);
        float xv11 = __bfloat162float(smb[SC_XH + t1 * 40 + p + 1])
                   + __bfloat162float(smb[SC_XL + t1 * 40 + p + 1]);
        *(float2*)&g_y[(size_t)(r0 + t0) * DINNER + h * HD + p] =
            make_float2(ayi[nf][0] + eS0 * ayo[nf][0] + Dh * xv00,
                        ayi[nf][1] + eS0 * ayo[nf][1] + Dh * xv01);
        *(float2*)&g_y[(size_t)(r0 + t1) * DINNER + h * HD + p] =
            make_float2(ayi[nf][2] + eS1 * ayo[nf][2] + Dh * xv10,
                        ayi[nf][3] + eS1 * ayo[nf][3] + Dh * xv11);
    }
}

// ---------------- K4a: gating + gated RMSNorm (warp/row) --------------------
__global__ void k_gate(const float* __restrict__ gw) {
    int r    = blockIdx.x * 8 + (threadIdx.x >> 5);
    int lane = threadIdx.x & 31;
    float4 y0 = *(const float4*)&g_y[(size_t)r * DINNER + lane * 4];
    float4 y1 = *(const float4*)&g_y[(size_t)r * DINNER + 128 + lane * 4];
    float4 z0 = *(const float4*)&g_zx[(size_t)r * DPROJ + lane * 4];
    float4 z1 = *(const float4*)&g_zx[(size_t)r * DPROJ + 128 + lane * 4];
    float gv[8];
    gv[0] = y0.x * silu(z0.x); gv[1] = y0.y * silu(z0.y);
    gv[2] = y0.z * silu(z0.z); gv[3] = y0.w * silu(z0.w);
    gv[4] = y1.x * silu(z1.x); gv[5] = y1.y * silu(z1.y);
    gv[6] = y1.z * silu(z1.z); gv[7] = y1.w * silu(z1.w);
    float ss = 0.f;
#pragma unroll
    for (int j = 0; j < 8; j++) ss += gv[j] * gv[j];
#pragma unroll
    for (int o = 16; o; o >>= 1) ss += __shfl_xor_sync(0xffffffffu, ss, o);
    float sc = rsqrtf(ss * (1.f / DINNER) + 1e-5f);
    float4 w0 = *(const float4*)&gw[lane * 4];
    float4 w1 = *(const float4*)&gw[128 + lane * 4];
    float wv[8] = {w0.x, w0.y, w0.z, w0.w, w1.x, w1.y, w1.z, w1.w};
    __nv_bfloat16 h[8], l[8];
#pragma unroll
    for (int j = 0; j < 8; j++) split_bf16(gv[j] * sc * wv[j], h[j], l[j]);
    *(uint2*)&g_gh[(size_t)r * DINNER + lane * 4]       = *(uint2*)&h[0];
    *(uint2*)&g_gh[(size_t)r * DINNER + 128 + lane * 4] = *(uint2*)&h[4];
    *(uint2*)&g_gl[(size_t)r * DINNER + lane * 4]       = *(uint2*)&l[0];
    *(uint2*)&g_gl[(size_t)r * DINNER + 128 + lane * 4] = *(uint2*)&l[4];
}

// ---------------- K4b: out_proj HMMA bf16x3 + residual, tile 64x128 ---------
#define OP_AH 0
#define OP_AL 8704
#define OP_BH 17408
#define OP_BL 34816
#define OP_TOT 52224
__global__ void __launch_bounds__(256, 2) k_outproj_mma(const float* __restrict__ x,
                                                        float* __restrict__ out) {
    extern __shared__ __align__(16) __nv_bfloat16 smb[];
    int tid = threadIdx.x, wid = tid >> 5, lane = tid & 31;
    int rowBase = blockIdx.x * 64;
    uint32_t sb = smem_u32(smb);
    int mw = wid & 3, nw = wid >> 2;
    int arow = mw * 16, ncol = nw * 64;
    float acc[8][4] = {};
    int lrow = lane & 15, lk = (lane >> 4) << 3;
    int brow = (lane & 7) + ((lane >> 4) & 1) * 8;
    int bk = ((lane >> 3) & 1) << 3;

    for (int kc = 0; kc < 2; kc++) {
        if (kc) __syncthreads();
        for (int i = tid; i < 1024; i += 256) {
            int r = i >> 4, c = (i & 15) << 3;
            size_t ao = (size_t)(rowBase + r) * DINNER + kc * 128 + c;
            *(uint4*)&smb[OP_AH + r * 136 + c] = *(const uint4*)(g_gh + ao);
            *(uint4*)&smb[OP_AL + r * 136 + c] = *(const uint4*)(g_gl + ao);
        }
        for (int i = tid; i < 2048; i += 256) {
            int r = i >> 4, c = (i & 15) << 3;
            size_t bo = (size_t)r * DINNER + kc * 128 + c;
            *(uint4*)&smb[OP_BH + r * 136 + c] = *(const uint4*)(g_woh + bo);
            *(uint4*)&smb[OP_BL + r * 136 + c] = *(const uint4*)(g_wol + bo);
        }
        __syncthreads();
#pragma unroll
        for (int kf = 0; kf < 8; kf++) {
            int k0 = kf << 4;
            uint32_t ah[4], al[4];
            uint32_t ad = sb + (uint32_t)(((arow + lrow) * 136 + k0 + lk) * 2);
            LDSM4(ah, ad + OP_AH * 2);
            LDSM4(al, ad + OP_AL * 2);
            uint32_t bh[4][4], bl[4][4];
#pragma unroll
            for (int ng = 0; ng < 4; ng++) {
                uint32_t ad2 = sb + (uint32_t)(((ncol + ng * 16 + brow) * 136 + k0 + bk) * 2);
                LDSM4(bh[ng], ad2 + OP_BH * 2);
                LDSM4(bl[ng], ad2 + OP_BL * 2);
            }
#pragma unroll
            for (int nf = 0; nf < 8; nf++) {
                uint32_t* BH = &bh[nf >> 1][(nf & 1) * 2];
                uint32_t* BL = &bl[nf >> 1][(nf & 1) * 2];
                MMA16816(acc[nf], ah, BH[0], BH[1]);
                MMA16816(acc[nf], ah, BL[0], BL[1]);
                MMA16816(acc[nf], al, BH[0], BH[1]);
            }
        }
    }
    int g = lane >> 2, tg = lane & 3;
    int r = rowBase + arow + g;
#pragma unroll
    for (int nf = 0; nf < 8; nf++) {
        int c = ncol + nf * 8 + tg * 2;
        float2 x0 = *(const float2*)&x[(size_t)r * DMODEL + c];
        float2 x1 = *(const float2*)&x[(size_t)(r + 8) * DMODEL + c];
        *(float2*)&out[(size_t)r * DMODEL + c] =
            make_float2(acc[nf][0] + x0.x, acc[nf][1] + x0.y);
        *(float2*)&out[(size_t)(r + 8) * DMODEL + c] =
            make_float2(acc[nf][2] + x1.x, acc[nf][3] + x1.y);
    }
}

extern "C" void kernel_launch(void* const* d_in, const int* in_sizes, int n_in,
                              void* d_out, int out_size) {
    const float* x          = (const float*)d_in[0];
    const float* norm_w     = (const float*)d_in[1];
    const float* in_proj_w  = (const float*)d_in[2];
    const float* conv_w     = (const float*)d_in[3];
    const float* conv_b     = (const float*)d_in[4];
    const float* dt_bias    = (const float*)d_in[5];
    const float* A_log      = (const float*)d_in[6];
    const float* D          = (const float*)d_in[7];
    const float* gnorm_w    = (const float*)d_in[8];
    const float* out_proj_w = (const float*)d_in[9];
    float* out = (float*)d_out;

    const int in_smem   = IP_TOT * 2;
    const int out_smem  = OP_TOT * 2;
    const int ssdc_smem = SC_END * 2 + 512;
    cudaFuncSetAttribute(k_inproj_mma,  cudaFuncAttributeMaxDynamicSharedMemorySize, in_smem);
    cudaFuncSetAttribute(k_outproj_mma, cudaFuncAttributeMaxDynamicSharedMemorySize, out_smem);
    cudaFuncSetAttribute(k_ssd_c_mma,   cudaFuncAttributeMaxDynamicSharedMemorySize, ssdc_smem);

    k_prep<<<4096 + 113, 256>>>(x, norm_w, in_proj_w, out_proj_w);
    k_inproj_mma<<<dim3(RTOT / 64, 7), 256, in_smem>>>();
    k_dtscan<<<NBATCH * NCHK, 256>>>(A_log, dt_bias);
    k_conv4<<<RTOT / 16, 384>>>(conv_w, conv_b);
    k_ssd_a_mma<<<NCID, 256>>>();
    k_ssd_b_mma<<<dim3(NBATCH * NH, 32), 256>>>();
    k_ssd_c_mma<<<NCID, 256, ssdc_smem>>>(D);
    k_gate<<<RTOT / 8, 256>>>(gnorm_w);
    k_outproj_mma<<<RTOT / 64, 256, out_smem>>>(x, out);
}

// round 15
// speedup vs baseline: 1.2753x; 1.0146x over previous
#include <cuda_runtime.h>
#include <cuda_bf16.h>
#include <cstdint>

#define RTOT   32768
#define LSEQ   4096
#define NBATCH 8
#define DMODEL 128
#define DPROJ  648
#define DINNER 256
#define CONVD  384
#define NH     8
#define HD     32
#define QC     64
#define NCHK   (LSEQ/QC)
#define NCID   (NBATCH*NH*NCHK)

// ---------------- scratch (device globals) ----------------------------------
__device__ __align__(16) float g_zx [(size_t)RTOT * DPROJ];
__device__ __align__(16) float g_dtb[RTOT * NH];
__device__ __align__(16) float g_y  [RTOT * DINNER];
__device__ __align__(16) float g_S  [(size_t)NCID * QC];
__device__ __align__(16) float g_ssc[(size_t)NCID * QC];
__device__ __align__(16) float g_T  [NCID];
__device__ __align__(16) __nv_bfloat16 g_xch[RTOT * CONVD];
__device__ __align__(16) __nv_bfloat16 g_xcl[RTOT * CONVD];
__device__ __align__(16) __nv_bfloat16 g_Uh [(size_t)NCID * 2048];
__device__ __align__(16) __nv_bfloat16 g_Ul [(size_t)NCID * 2048];
__device__ __align__(16) __nv_bfloat16 g_hsh[(size_t)NCID * 2048];
__device__ __align__(16) __nv_bfloat16 g_hsl[(size_t)NCID * 2048];
__device__ __align__(16) __nv_bfloat16 g_ah [RTOT * DMODEL];
__device__ __align__(16) __nv_bfloat16 g_al [RTOT * DMODEL];
__device__ __align__(16) __nv_bfloat16 g_wih[672 * DMODEL];
__device__ __align__(16) __nv_bfloat16 g_wil[672 * DMODEL];
__device__ __align__(16) __nv_bfloat16 g_gh [RTOT * DINNER];
__device__ __align__(16) __nv_bfloat16 g_gl [RTOT * DINNER];
__device__ __align__(16) __nv_bfloat16 g_woh[DMODEL * DINNER];
__device__ __align__(16) __nv_bfloat16 g_wol[DMODEL * DINNER];
// -----------------------------------------------------------------------------

// ---- warp MMA helpers ----
static __device__ __forceinline__ uint32_t smem_u32(const void* p) {
    uint32_t a;
    asm("{ .reg .u64 t; cvta.to.shared.u64 t, %1; cvt.u32.u64 %0, t; }"
        : "=r"(a) : "l"(p));
    return a;
}
#define LDSM4(r, addr) \
    asm volatile("ldmatrix.sync.aligned.m8n8.x4.shared.b16 {%0,%1,%2,%3}, [%4];" \
        : "=r"((r)[0]), "=r"((r)[1]), "=r"((r)[2]), "=r"((r)[3]) : "r"(addr))
#define LDSM4T(r, addr) \
    asm volatile("ldmatrix.sync.aligned.m8n8.x4.trans.shared.b16 {%0,%1,%2,%3}, [%4];" \
        : "=r"((r)[0]), "=r"((r)[1]), "=r"((r)[2]), "=r"((r)[3]) : "r"(addr))
#define MMA16816(d, a, b0, b1) \
    asm volatile("mma.sync.aligned.m16n8k16.row.col.f32.bf16.bf16.f32 " \
        "{%0,%1,%2,%3}, {%4,%5,%6,%7}, {%8,%9}, {%0,%1,%2,%3};" \
        : "+f"((d)[0]), "+f"((d)[1]), "+f"((d)[2]), "+f"((d)[3]) \
        : "r"((a)[0]), "r"((a)[1]), "r"((a)[2]), "r"((a)[3]), "r"(b0), "r"(b1))

static __device__ __forceinline__ void split_bf16(float v, __nv_bfloat16& h,
                                                  __nv_bfloat16& l) {
    h = __float2bfloat16(v);
    l = __float2bfloat16(v - __bfloat162float(h));
}
static __device__ __forceinline__ void split4(float4 v, __nv_bfloat16* h,
                                              __nv_bfloat16* l) {
    split_bf16(v.x, h[0], l[0]); split_bf16(v.y, h[1], l[1]);
    split_bf16(v.z, h[2], l[2]); split_bf16(v.w, h[3], l[3]);
}
static __device__ __forceinline__ float silu(float v) {
    return v / (1.f + __expf(-v));
}

// ---------------- K0: fused weight-split + RMSNorm --------------------------
__global__ void k_prep(const float* __restrict__ x, const float* __restrict__ w,
                       const float* __restrict__ Wi, const float* __restrict__ Wo) {
    if (blockIdx.x < 4096) {
        int row  = blockIdx.x * 8 + (threadIdx.x >> 5);
        int lane = threadIdx.x & 31;
        float4 v = ((const float4*)(x + (size_t)row * DMODEL))[lane];
        float ss = v.x * v.x + v.y * v.y + v.z * v.z + v.w * v.w;
#pragma unroll
        for (int o = 16; o; o >>= 1) ss += __shfl_xor_sync(0xffffffffu, ss, o);
        float sc = rsqrtf(ss * (1.f / DMODEL) + 1e-5f);
        float4 wv = ((const float4*)w)[lane];
        float4 o4;
        o4.x = v.x * sc * wv.x; o4.y = v.y * sc * wv.y;
        o4.z = v.z * sc * wv.z; o4.w = v.w * sc * wv.w;
        __nv_bfloat16 h[4], l[4];
        split4(o4, h, l);
        ((uint2*)(g_ah + (size_t)row * DMODEL))[lane] = *(uint2*)h;
        ((uint2*)(g_al + (size_t)row * DMODEL))[lane] = *(uint2*)l;
    } else {
        int idx = (blockIdx.x - 4096) * 256 + threadIdx.x;
        const int NWI = DPROJ * DMODEL / 4;
        const int NWO = DMODEL * DINNER / 4;
        if (idx < NWI) {
            float4 v = ((const float4*)Wi)[idx];
            __nv_bfloat16 h[4], l[4];
            split4(v, h, l);
            ((uint2*)g_wih)[idx] = *(uint2*)h;
            ((uint2*)g_wil)[idx] = *(uint2*)l;
        } else if (idx < NWI + NWO) {
            int j = idx - NWI;
            float4 v = ((const float4*)Wo)[j];
            __nv_bfloat16 h[4], l[4];
            split4(v, h, l);
            ((uint2*)g_woh)[j] = *(uint2*)h;
            ((uint2*)g_wol)[j] = *(uint2*)l;
        }
    }
}

// ---------------- K1: in_proj GEMM via HMMA bf16x3, tile 64x96, K=128 -------
#define IP_AH 0
#define IP_AL 8704
#define IP_BH 17408
#define IP_BL 30464
#define IP_TOT 43520
__global__ void __launch_bounds__(256, 2) k_inproj_mma() {
    extern __shared__ __align__(16) __nv_bfloat16 smb[];
    int tid = threadIdx.x, wid = tid >> 5, lane = tid & 31;
    int rowBase = blockIdx.x * 64;
    int colBase = blockIdx.y * 96;

    for (int i = tid; i < 1024; i += 256) {
        int r = i >> 4, c = (i & 15) << 3;
        *(uint4*)&smb[IP_AH + r * 136 + c] =
            *(const uint4*)(g_ah + (size_t)(rowBase + r) * DMODEL + c);
        *(uint4*)&smb[IP_AL + r * 136 + c] =
            *(const uint4*)(g_al + (size_t)(rowBase + r) * DMODEL + c);
    }
    for (int i = tid; i < 1536; i += 256) {
        int r = i >> 4, c = (i & 15) << 3;
        *(uint4*)&smb[IP_BH + r * 136 + c] =
            *(const uint4*)(g_wih + (size_t)(colBase + r) * DMODEL + c);
        *(uint4*)&smb[IP_BL + r * 136 + c] =
            *(const uint4*)(g_wil + (size_t)(colBase + r) * DMODEL + c);
    }
    __syncthreads();

    uint32_t sb = smem_u32(smb);
    int mw = wid & 3, nw = wid >> 2;
    int arow = mw * 16, ncol = nw * 48;
    float acc[6][4] = {};
    int lrow = lane & 15, lk = (lane >> 4) << 3;
    int brow = (lane & 7) + ((lane >> 4) & 1) * 8;
    int bk = ((lane >> 3) & 1) << 3;
#pragma unroll
    for (int kf = 0; kf < 8; kf++) {
        int k0 = kf << 4;
        uint32_t ah[4], al[4];
        uint32_t ad = sb + (uint32_t)(((arow + lrow) * 136 + k0 + lk) * 2);
        LDSM4(ah, ad + IP_AH * 2);
        LDSM4(al, ad + IP_AL * 2);
        uint32_t bh[3][4], bl[3][4];
#pragma unroll
        for (int ng = 0; ng < 3; ng++) {
            uint32_t ad2 = sb + (uint32_t)(((ncol + ng * 16 + brow) * 136 + k0 + bk) * 2);
            LDSM4(bh[ng], ad2 + IP_BH * 2);
            LDSM4(bl[ng], ad2 + IP_BL * 2);
        }
#pragma unroll
        for (int nf = 0; nf < 6; nf++) {
            uint32_t* BH = &bh[nf >> 1][(nf & 1) * 2];
            uint32_t* BL = &bl[nf >> 1][(nf & 1) * 2];
            MMA16816(acc[nf], ah, BH[0], BH[1]);
            MMA16816(acc[nf], ah, BL[0], BL[1]);
            MMA16816(acc[nf], al, BH[0], BH[1]);
        }
    }
    int g = lane >> 2, tg = lane & 3;
    int r = rowBase + arow + g;
#pragma unroll
    for (int nf = 0; nf < 6; nf++) {
        int c = colBase + ncol + nf * 8 + tg * 2;
        if (c < DPROJ) {
            *(float2*)&g_zx[(size_t)r * DPROJ + c] =
                make_float2(acc[nf][0], acc[nf][1]);
            *(float2*)&g_zx[(size_t)(r + 8) * DPROJ + c] =
                make_float2(acc[nf][2], acc[nf][3]);
        }
    }
}

// ---------------- K2: conv(K=4)+SiLU + dt-scan (tail blocks) ----------------
// blocks [0,2048): conv, occ 3; blocks [2048,2560): per-(b,chunk) dt scan.
__global__ void __launch_bounds__(384, 3) k_conv4(const float* __restrict__ cw,
                                                  const float* __restrict__ cb,
                                                  const float* __restrict__ A_log,
                                                  const float* __restrict__ dtb) {
    __shared__ float sdt[512];
    int t = threadIdx.x;
    if (blockIdx.x < 2048) {
        int c = (t % 96) * 4;
        int r0 = blockIdx.x * 16 + (t / 96) * 4;
        bool hist = (r0 & (LSEQ - 1)) != 0;
        float4 wA = *(const float4*)&cw[(c + 0) * 4];
        float4 wB = *(const float4*)&cw[(c + 1) * 4];
        float4 wC = *(const float4*)&cw[(c + 2) * 4];
        float4 wD = *(const float4*)&cw[(c + 3) * 4];
        float4 bias = *(const float4*)&cb[c];
        const float* src = g_zx + 256 + c;
        float4 z = make_float4(0.f, 0.f, 0.f, 0.f);
        float4 x0 = hist ? *(const float4*)&src[(size_t)(r0 - 3) * DPROJ] : z;
        float4 x1 = hist ? *(const float4*)&src[(size_t)(r0 - 2) * DPROJ] : z;
        float4 x2 = hist ? *(const float4*)&src[(size_t)(r0 - 1) * DPROJ] : z;
#pragma unroll
        for (int s = 0; s < 4; s++) {
            int r = r0 + s;
            float4 x3 = *(const float4*)&src[(size_t)r * DPROJ];
            float4 o;
            o.x = silu(bias.x + wA.x * x0.x + wA.y * x1.x + wA.z * x2.x + wA.w * x3.x);
            o.y = silu(bias.y + wB.x * x0.y + wB.y * x1.y + wB.z * x2.y + wB.w * x3.y);
            o.z = silu(bias.z + wC.x * x0.z + wC.y * x1.z + wC.z * x2.z + wC.w * x3.z);
            o.w = silu(bias.w + wD.x * x0.w + wD.y * x1.w + wD.z * x2.w + wD.w * x3.w);
            __nv_bfloat16 h4[4], l4[4];
            split4(o, h4, l4);
            *(uint2*)&g_xch[(size_t)r * CONVD + c] = *(uint2*)h4;
            *(uint2*)&g_xcl[(size_t)r * CONVD + c] = *(uint2*)l4;
            x0 = x1; x1 = x2; x2 = x3;
        }
    } else {
        int bc = blockIdx.x - 2048;
        int b = bc >> 6, c = bc & 63;
        int r0 = b * LSEQ + c * QC;
        for (int i = t; i < 512; i += 384) {
            int s = i >> 3, hh = i & 7;
            float v = g_zx[(size_t)(r0 + s) * DPROJ + 640 + hh] + dtb[hh];
            v = (v > 20.f) ? v : log1pf(__expf(v));
            sdt[hh * 64 + s] = v;
            g_dtb[(size_t)(r0 + s) * NH + hh] = v;
        }
        __syncthreads();
        if (t < 256) {
            int w = t >> 5, j = t & 31;
            float A = -__expf(A_log[w]);
            float d0 = sdt[w * 64 + 2 * j], d1 = sdt[w * 64 + 2 * j + 1];
            float v0 = d0 * A, v1 = d1 * A;
            float pair = v0 + v1;
            float ps = pair;
#pragma unroll
            for (int o = 1; o < 32; o <<= 1) {
                float u = __shfl_up_sync(0xffffffffu, ps, o);
                if (j >= o) ps += u;
            }
            float S0 = ps - pair + v0, S1 = ps;
            float T = __shfl_sync(0xffffffffu, ps, 31);
            int cid = ((b * NH + w) << 6) | c;
            *(float2*)&g_S[(size_t)cid * QC + 2 * j]   = make_float2(S0, S1);
            *(float2*)&g_ssc[(size_t)cid * QC + 2 * j] =
                make_float2(__expf(T - S0) * d0, __expf(T - S1) * d1);
            if (j == 0) g_T[cid] = T;
        }
    }
}

// ---------------- SSD pass A via HMMA bf16x3 (single sync) ------------------
#define SA_BH 0
#define SA_BL 4608
#define SA_XH 9216
#define SA_XL 11776
#define SA_END 14336
__global__ void __launch_bounds__(256) k_ssd_a_mma() {
    __shared__ __align__(16) __nv_bfloat16 smb[SA_END];
    int tid = threadIdx.x;
    int cid = blockIdx.x;
    int bh = cid >> 6, c = cid & 63;
    int b = bh >> 3, h = bh & 7;
    int r0 = b * LSEQ + c * QC;

    for (int i = tid; i < 512; i += 256) {
        int s = i >> 3, q = (i & 7) * 8;
        *(uint4*)&smb[SA_BH + s * 72 + q] =
            *(const uint4*)&g_xch[(size_t)(r0 + s) * CONVD + 256 + q];
        *(uint4*)&smb[SA_BL + s * 72 + q] =
            *(const uint4*)&g_xcl[(size_t)(r0 + s) * CONVD + 256 + q];
    }
    for (int i = tid; i < 512; i += 256) {
        int s = i >> 3, q = (i & 7) * 4;
        uint2 hv = *(const uint2*)&g_xch[(size_t)(r0 + s) * CONVD + h * HD + q];
        uint2 lv = *(const uint2*)&g_xcl[(size_t)(r0 + s) * CONVD + h * HD + q];
        __nv_bfloat16* hp = (__nv_bfloat16*)&hv;
        __nv_bfloat16* lp = (__nv_bfloat16*)&lv;
        float sc = g_ssc[(size_t)cid * QC + s];
        __nv_bfloat16 h4[4], l4[4];
#pragma unroll
        for (int j = 0; j < 4; j++) {
            float xv = (__bfloat162float(hp[j]) + __bfloat162float(lp[j])) * sc;
            split_bf16(xv, h4[j], l4[j]);
        }
        *(uint2*)&smb[SA_XH + s * 40 + q] = *(uint2*)h4;
        *(uint2*)&smb[SA_XL + s * 40 + q] = *(uint2*)l4;
    }
    __syncthreads();

    uint32_t sb = smem_u32(smb);
    int wid = tid >> 5, lane = tid & 31;
    int mw = wid & 1, nw = wid >> 1;
    int gidx = lane >> 3;
    int a_soff = (gidx >> 1) * 8, a_poff = (gidx & 1) * 8;
    int b_soff = ((lane >> 3) & 1) * 8, b_noff = (lane >> 4) * 8;
    float acc[2][4] = {};
#pragma unroll
    for (int kf = 0; kf < 4; kf++) {
        int k0 = kf << 4;
        uint32_t xh4[4], xl4[4], bh4[4], bl4[4];
        uint32_t ax = sb + (uint32_t)((SA_XH + (k0 + a_soff + (lane & 7)) * 40
                                       + mw * 16 + a_poff) * 2);
        LDSM4T(xh4, ax);
        LDSM4T(xl4, ax + (SA_XL - SA_XH) * 2);
        uint32_t bad = sb + (uint32_t)((SA_BH + (k0 + b_soff + (lane & 7)) * 72
                                        + nw * 16 + b_noff) * 2);
        LDSM4T(bh4, bad);
        LDSM4T(bl4, bad + (SA_BL - SA_BH) * 2);
#pragma unroll
        for (int nf = 0; nf < 2; nf++) {
            MMA16816(acc[nf], xh4, bh4[nf * 2], bh4[nf * 2 + 1]);
            MMA16816(acc[nf], xh4, bl4[nf * 2], bl4[nf * 2 + 1]);
            MMA16816(acc[nf], xl4, bh4[nf * 2], bh4[nf * 2 + 1]);
        }
    }
    int g = lane >> 2, tg = lane & 3;
    size_t ub = (size_t)cid * 2048;
#pragma unroll
    for (int nf = 0; nf < 2; nf++) {
        int p = mw * 16 + g, n = nw * 16 + nf * 8 + tg * 2;
#pragma unroll
        for (int e = 0; e < 2; e++) {
            int pp = p + e * 8;
            __nv_bfloat16 h0, l0, h1, l1;
            split_bf16(acc[nf][e * 2 + 0], h0, l0);
            split_bf16(acc[nf][e * 2 + 1], h1, l1);
            __nv_bfloat16 hh[2] = {h0, h1}, ll[2] = {l0, l1};
            *(uint32_t*)&g_Uh[ub + pp * 64 + n] = *(uint32_t*)hh;
            *(uint32_t*)&g_Ul[ub + pp * 64 + n] = *(uint32_t*)ll;
        }
    }
}

// ---------------- SSD pass B: hs = W @ U via HMMA (W computed in-block) -----
#define SB_WH 0
#define SB_WL 4608
#define SB_UH 9216
#define SB_UL 13824
#define SB_END 18432
__global__ void __launch_bounds__(256) k_ssd_b_mma() {
    __shared__ __align__(16) __nv_bfloat16 smb[SB_END];
    __shared__ float sI[64];
    int tid = threadIdx.x, wid = tid >> 5, lane = tid & 31;
    int bh = blockIdx.x;
    int col0 = blockIdx.y * 64;
    if (tid < 64) {
        float v = g_T[bh * 64 + tid];
#pragma unroll
        for (int o = 1; o < 32; o <<= 1) {
            float u = __shfl_up_sync(0xffffffffu, v, o);
            if ((tid & 31) >= o) v += u;
        }
        sI[tid] = v;
    }
    __syncthreads();
    if (tid >= 32 && tid < 64) sI[tid] += sI[31];
    __syncthreads();
    for (int i = tid; i < 4096; i += 256) {
        int c = i >> 6, j = i & 63;
        float w = (j < c) ? __expf(sI[c - 1] - sI[j]) : 0.f;
        __nv_bfloat16 h, l;
        split_bf16(w, h, l);
        smb[SB_WH + c * 72 + j] = h;
        smb[SB_WL + c * 72 + j] = l;
    }
    for (int i = tid; i < 512; i += 256) {
        int j = i >> 3, q = (i & 7) * 8;
        *(uint4*)&smb[SB_UH + j * 72 + q] =
            *(const uint4*)&g_Uh[((size_t)bh * 64 + j) * 2048 + col0 + q];
        *(uint4*)&smb[SB_UL + j * 72 + q] =
            *(const uint4*)&g_Ul[((size_t)bh * 64 + j) * 2048 + col0 + q];
    }
    __syncthreads();
    uint32_t sb = smem_u32(smb);
    int mw = wid & 3, nw = wid >> 2;
    int crow = mw * 16, ncol = nw * 32;
    int lrow = lane & 15, lk = (lane >> 4) << 3;
    int b_soff = ((lane >> 3) & 1) * 8, b_noff = (lane >> 4) * 8;
    float acc[4][4] = {};
#pragma unroll
    for (int kf = 0; kf < 4; kf++) {
        int k0 = kf << 4;
        uint32_t whf[4], wlf[4];
        uint32_t ad = sb + (uint32_t)((SB_WH + (crow + lrow) * 72 + k0 + lk) * 2);
        LDSM4(whf, ad);
        LDSM4(wlf, ad + (SB_WL - SB_WH) * 2);
        uint32_t uh[2][4], ul[2][4];
#pragma unroll
        for (int hf = 0; hf < 2; hf++) {
            uint32_t ad2 = sb + (uint32_t)((SB_UH + (k0 + b_soff + (lane & 7)) * 72
                                            + ncol + hf * 16 + b_noff) * 2);
            LDSM4T(uh[hf], ad2);
            LDSM4T(ul[hf], ad2 + (SB_UL - SB_UH) * 2);
        }
#pragma unroll
        for (int nf = 0; nf < 4; nf++) {
            uint32_t* BH = &uh[nf >> 1][(nf & 1) * 2];
            uint32_t* BL = &ul[nf >> 1][(nf & 1) * 2];
            MMA16816(acc[nf], whf, BH[0], BH[1]);
            MMA16816(acc[nf], whf, BL[0], BL[1]);
            MMA16816(acc[nf], wlf, BH[0], BH[1]);
        }
    }
    int g = lane >> 2, tg = lane & 3;
#pragma unroll
    for (int nf = 0; nf < 4; nf++) {
        int col = col0 + ncol + nf * 8 + tg * 2;
#pragma unroll
        for (int e = 0; e < 2; e++) {
            int c = crow + g + e * 8;
            __nv_bfloat16 h0, l0, h1, l1;
            split_bf16(acc[nf][e * 2 + 0], h0, l0);
            split_bf16(acc[nf][e * 2 + 1], h1, l1);
            __nv_bfloat16 hh[2] = {h0, h1}, ll[2] = {l0, l1};
            *(uint32_t*)&g_hsh[((size_t)bh * 64 + c) * 2048 + col] = *(uint32_t*)hh;
            *(uint32_t*)&g_hsl[((size_t)bh * 64 + c) * 2048 + col] = *(uint32_t*)ll;
        }
    }
}

// ---------------- SSD pass C via HMMA bf16x3 (occ 3) ------------------------
#define SC_P  72
#define SC_CH 0
#define SC_CL 4608
#define SC_BH 9216
#define SC_BL 13824
#define SC_XH 18432
#define SC_XL 20992
#define SC_HH 23552
#define SC_HL 25856
#define SC_END 28160
__global__ void __launch_bounds__(256, 3) k_ssd_c_mma(const float* __restrict__ Dp) {
    extern __shared__ __align__(16) __nv_bfloat16 smb[];
    float* Ssm = (float*)(smb + SC_END);
    float* dts = Ssm + 64;
    int tid = threadIdx.x, wid = tid >> 5, lane = tid & 31;
    int cid = blockIdx.x;
    int bh = cid >> 6, c = cid & 63;
    int b = bh >> 3, h = bh & 7;
    int r0 = b * LSEQ + c * QC;
    float Dh = Dp[h];

    for (int i = tid; i < 512; i += 256) {
        int s = i >> 3, q = (i & 7) * 8;
        size_t ro = (size_t)(r0 + s) * CONVD;
        *(uint4*)&smb[SC_CH + s * SC_P + q] = *(const uint4*)&g_xch[ro + 320 + q];
        *(uint4*)&smb[SC_CL + s * SC_P + q] = *(const uint4*)&g_xcl[ro + 320 + q];
        *(uint4*)&smb[SC_BH + s * SC_P + q] = *(const uint4*)&g_xch[ro + 256 + q];
        *(uint4*)&smb[SC_BL + s * SC_P + q] = *(const uint4*)&g_xcl[ro + 256 + q];
    }
    for (int i = tid; i < 256; i += 256) {
        int s = i >> 2, q = (i & 3) * 8;
        size_t ro = (size_t)(r0 + s) * CONVD + h * HD;
        *(uint4*)&smb[SC_XH + s * 40 + q] = *(const uint4*)&g_xch[ro + q];
        *(uint4*)&smb[SC_XL + s * 40 + q] = *(const uint4*)&g_xcl[ro + q];
    }
    for (int i = tid; i < 256; i += 256) {
        int p = i >> 3, q = (i & 7) * 8;
        size_t ho = (size_t)cid * 2048 + p * 64 + q;
        *(uint4*)&smb[SC_HH + p * SC_P + q] = *(const uint4*)&g_hsh[ho];
        *(uint4*)&smb[SC_HL + p * SC_P + q] = *(const uint4*)&g_hsl[ho];
    }
    if (tid < 64) {
        Ssm[tid] = g_S[(size_t)cid * QC + tid];
        dts[tid] = g_dtb[(size_t)(r0 + tid) * NH + h];
    }
    __syncthreads();

    uint32_t sb = smem_u32(smb);
    int mw = wid & 3, nw = wid >> 2;
    int arow = mw * 16;
    int lrow = lane & 15, lk = (lane >> 4) << 3;
    int brow = (lane & 7) + ((lane >> 4) & 1) * 8;
    int bk = ((lane >> 3) & 1) << 3;
    int b_soff = ((lane >> 3) & 1) * 8, b_noff = (lane >> 4) * 8;

    float accg[4][4] = {};
    if (!(nw == 1 && mw < 2)) {
#pragma unroll
        for (int kf = 0; kf < 4; kf++) {
            int k0 = kf << 4;
            uint32_t ch[4], cl[4];
            uint32_t ad = sb + (uint32_t)(((arow + lrow) * SC_P + k0 + lk) * 2);
            LDSM4(ch, ad + SC_CH * 2);
            LDSM4(cl, ad + SC_CL * 2);
            uint32_t bh2[2][4], bl2[2][4];
#pragma unroll
            for (int ng = 0; ng < 2; ng++) {
                uint32_t ad2 = sb + (uint32_t)(((nw * 32 + ng * 16 + brow) * SC_P + k0 + bk) * 2);
                LDSM4(bh2[ng], ad2 + SC_BH * 2);
                LDSM4(bl2[ng], ad2 + SC_BL * 2);
            }
#pragma unroll
            for (int nf = 0; nf < 4; nf++) {
                uint32_t* BH = &bh2[nf >> 1][(nf & 1) * 2];
                uint32_t* BL = &bl2[nf >> 1][(nf & 1) * 2];
                MMA16816(accg[nf], ch, BH[0], BH[1]);
                MMA16816(accg[nf], ch, BL[0], BL[1]);
                MMA16816(accg[nf], cl, BH[0], BH[1]);
            }
        }
    }
    __syncthreads();

    int g = lane >> 2, tg = lane & 3;
    int t0 = arow + g, t1 = arow + g + 8;
    float St0 = Ssm[t0], St1 = Ssm[t1];
#pragma unroll
    for (int nf = 0; nf < 4; nf++) {
#pragma unroll
        for (int e = 0; e < 2; e++) {
            int s = nw * 32 + nf * 8 + tg * 2 + e;
            float ds = dts[s], Ss = Ssm[s];
            float m0 = (s <= t0) ? accg[nf][e]     * __expf(St0 - Ss) * ds : 0.f;
            float m1 = (s <= t1) ? accg[nf][2 + e] * __expf(St1 - Ss) * ds : 0.f;
            __nv_bfloat16 hh0, ll0, hh1, ll1;
            split_bf16(m0, hh0, ll0);
            split_bf16(m1, hh1, ll1);
            smb[SC_BH + t0 * SC_P + s] = hh0;
            smb[SC_BL + t0 * SC_P + s] = ll0;
            smb[SC_BH + t1 * SC_P + s] = hh1;
            smb[SC_BL + t1 * SC_P + s] = ll1;
        }
    }
    __syncthreads();

    int pw = wid >> 2;
    int prow = pw * 16;
    float ayi[2][4] = {}, ayo[2][4] = {};
#pragma unroll
    for (int kf = 0; kf < 4; kf++) {
        int k0 = kf << 4;
        uint32_t ad = sb + (uint32_t)(((arow + lrow) * SC_P + k0 + lk) * 2);
        uint32_t mh[4], ml[4], ch[4], cl[4];
        LDSM4(mh, ad + SC_BH * 2);
        LDSM4(ml, ad + SC_BL * 2);
        LDSM4(ch, ad + SC_CH * 2);
        LDSM4(cl, ad + SC_CL * 2);
        uint32_t xh[4], xl[4], hh2[4], hl2[4];
        uint32_t adx = sb + (uint32_t)((SC_XH + (k0 + b_soff + (lane & 7)) * 40
                                        + prow + b_noff) * 2);
        LDSM4T(xh, adx);
        LDSM4T(xl, adx + (SC_XL - SC_XH) * 2);
        uint32_t adh = sb + (uint32_t)(((prow + brow) * SC_P + k0 + bk) * 2);
        LDSM4(hh2, adh + SC_HH * 2);
        LDSM4(hl2, adh + SC_HL * 2);
#pragma unroll
        for (int nf = 0; nf < 2; nf++) {
            uint32_t* XH = &xh[nf * 2];  uint32_t* XL = &xl[nf * 2];
            uint32_t* HH = &hh2[nf * 2]; uint32_t* HL = &hl2[nf * 2];
            MMA16816(ayi[nf], mh, XH[0], XH[1]);
            MMA16816(ayi[nf], mh, XL[0], XL[1]);
            MMA16816(ayi[nf], ml, XH[0], XH[1]);
            MMA16816(ayo[nf], ch, HH[0], HH[1]);
            MMA16816(ayo[nf], ch, HL[0], HL[1]);
            MMA16816(ayo[nf], cl, HH[0], HH[1]);
        }
    }

    float eS0 = __expf(St0), eS1 = __expf(St1);
#pragma unroll
    for (int nf = 0; nf < 2; nf++) {
        int p = prow + nf * 8 + tg * 2;
        float xv00 = __bfloat162float(smb[SC_XH + t0 * 40 + p])
                   + __bfloat162float(smb[SC_XL + t0 * 40 + p]);
        float xv01 = __bfloat162float(smb[SC_XH + t0 * 40 + p + 1])
                   + __bfloat162float(smb[SC_XL + t0 * 40 + p + 1]);
        float xv10 = __bfloat162float(smb[SC_XH + t1 * 40 + p])
                   + __bfloat162float(smb[SC_XL + t1 * 40 + p]);
        float xv11 = __bfloat162float(smb[SC_XH + t1 * 40 + p + 1])
                   + __bfloat162float(smb[SC_XL + t1 * 40 + p + 1]);
        *(float2*)&g_y[(size_t)(r0 + t0) * DINNER + h * HD + p] =
            make_float2(ayi[nf][0] + eS0 * ayo[nf][0] + Dh * xv00,
                        ayi[nf][1] + eS0 * ayo[nf][1] + Dh * xv01);
        *(float2*)&g_y[(size_t)(r0 + t1) * DINNER + h * HD + p] =
            make_float2(ayi[nf][2] + eS1 * ayo[nf][2] + Dh * xv10,
                        ayi[nf][3] + eS1 * ayo[nf][3] + Dh * xv11);
    }
}

// ---------------- K4a: gating + gated RMSNorm (warp/row) --------------------
__global__ void k_gate(const float* __restrict__ gw) {
    int r    = blockIdx.x * 8 + (threadIdx.x >> 5);
    int lane = threadIdx.x & 31;
    float4 y0 = *(const float4*)&g_y[(size_t)r * DINNER + lane * 4];
    float4 y1 = *(const float4*)&g_y[(size_t)r * DINNER + 128 + lane * 4];
    float4 z0 = *(const float4*)&g_zx[(size_t)r * DPROJ + lane * 4];
    float4 z1 = *(const float4*)&g_zx[(size_t)r * DPROJ + 128 + lane * 4];
    float gv[8];
    gv[0] = y0.x * silu(z0.x); gv[1] = y0.y * silu(z0.y);
    gv[2] = y0.z * silu(z0.z); gv[3] = y0.w * silu(z0.w);
    gv[4] = y1.x * silu(z1.x); gv[5] = y1.y * silu(z1.y);
    gv[6] = y1.z * silu(z1.z); gv[7] = y1.w * silu(z1.w);
    float ss = 0.f;
#pragma unroll
    for (int j = 0; j < 8; j++) ss += gv[j] * gv[j];
#pragma unroll
    for (int o = 16; o; o >>= 1) ss += __shfl_xor_sync(0xffffffffu, ss, o);
    float sc = rsqrtf(ss * (1.f / DINNER) + 1e-5f);
    float4 w0 = *(const float4*)&gw[lane * 4];
    float4 w1 = *(const float4*)&gw[128 + lane * 4];
    float wv[8] = {w0.x, w0.y, w0.z, w0.w, w1.x, w1.y, w1.z, w1.w};
    __nv_bfloat16 h[8], l[8];
#pragma unroll
    for (int j = 0; j < 8; j++) split_bf16(gv[j] * sc * wv[j], h[j], l[j]);
    *(uint2*)&g_gh[(size_t)r * DINNER + lane * 4]       = *(uint2*)&h[0];
    *(uint2*)&g_gh[(size_t)r * DINNER + 128 + lane * 4] = *(uint2*)&h[4];
    *(uint2*)&g_gl[(size_t)r * DINNER + lane * 4]       = *(uint2*)&l[0];
    *(uint2*)&g_gl[(size_t)r * DINNER + 128 + lane * 4] = *(uint2*)&l[4];
}

// ---------------- K4b: out_proj HMMA bf16x3 + residual, tile 64x128 ---------
#define OP_AH 0
#define OP_AL 8704
#define OP_BH 17408
#define OP_BL 34816
#define OP_TOT 52224
__global__ void __launch_bounds__(256, 2) k_outproj_mma(const float* __restrict__ x,
                                                        float* __restrict__ out) {
    extern __shared__ __align__(16) __nv_bfloat16 smb[];
    int tid = threadIdx.x, wid = tid >> 5, lane = tid & 31;
    int rowBase = blockIdx.x * 64;
    uint32_t sb = smem_u32(smb);
    int mw = wid & 3, nw = wid >> 2;
    int arow = mw * 16, ncol = nw * 64;
    float acc[8][4] = {};
    int lrow = lane & 15, lk = (lane >> 4) << 3;
    int brow = (lane & 7) + ((lane >> 4) & 1) * 8;
    int bk = ((lane >> 3) & 1) << 3;

    for (int kc = 0; kc < 2; kc++) {
        if (kc) __syncthreads();
        for (int i = tid; i < 1024; i += 256) {
            int r = i >> 4, c = (i & 15) << 3;
            size_t ao = (size_t)(rowBase + r) * DINNER + kc * 128 + c;
            *(uint4*)&smb[OP_AH + r * 136 + c] = *(const uint4*)(g_gh + ao);
            *(uint4*)&smb[OP_AL + r * 136 + c] = *(const uint4*)(g_gl + ao);
        }
        for (int i = tid; i < 2048; i += 256) {
            int r = i >> 4, c = (i & 15) << 3;
            size_t bo = (size_t)r * DINNER + kc * 128 + c;
            *(uint4*)&smb[OP_BH + r * 136 + c] = *(const uint4*)(g_woh + bo);
            *(uint4*)&smb[OP_BL + r * 136 + c] = *(const uint4*)(g_wol + bo);
        }
        __syncthreads();
#pragma unroll
        for (int kf = 0; kf < 8; kf++) {
            int k0 = kf << 4;
            uint32_t ah[4], al[4];
            uint32_t ad = sb + (uint32_t)(((arow + lrow) * 136 + k0 + lk) * 2);
            LDSM4(ah, ad + OP_AH * 2);
            LDSM4(al, ad + OP_AL * 2);
            uint32_t bh[4][4], bl[4][4];
#pragma unroll
            for (int ng = 0; ng < 4; ng++) {
                uint32_t ad2 = sb + (uint32_t)(((ncol + ng * 16 + brow) * 136 + k0 + bk) * 2);
                LDSM4(bh[ng], ad2 + OP_BH * 2);
                LDSM4(bl[ng], ad2 + OP_BL * 2);
            }
#pragma unroll
            for (int nf = 0; nf < 8; nf++) {
                uint32_t* BH = &bh[nf >> 1][(nf & 1) * 2];
                uint32_t* BL = &bl[nf >> 1][(nf & 1) * 2];
                MMA16816(acc[nf], ah, BH[0], BH[1]);
                MMA16816(acc[nf], ah, BL[0], BL[1]);
                MMA16816(acc[nf], al, BH[0], BH[1]);
            }
        }
    }
    int g = lane >> 2, tg = lane & 3;
    int r = rowBase + arow + g;
#pragma unroll
    for (int nf = 0; nf < 8; nf++) {
        int c = ncol + nf * 8 + tg * 2;
        float2 x0 = *(const float2*)&x[(size_t)r * DMODEL + c];
        float2 x1 = *(const float2*)&x[(size_t)(r + 8) * DMODEL + c];
        *(float2*)&out[(size_t)r * DMODEL + c] =
            make_float2(acc[nf][0] + x0.x, acc[nf][1] + x0.y);
        *(float2*)&out[(size_t)(r + 8) * DMODEL + c] =
            make_float2(acc[nf][2] + x1.x, acc[nf][3] + x1.y);
    }
}

extern "C" void kernel_launch(void* const* d_in, const int* in_sizes, int n_in,
                              void* d_out, int out_size) {
    const float* x          = (const float*)d_in[0];
    const float* norm_w     = (const float*)d_in[1];
    const float* in_proj_w  = (const float*)d_in[2];
    const float* conv_w     = (const float*)d_in[3];
    const float* conv_b     = (const float*)d_in[4];
    const float* dt_bias    = (const float*)d_in[5];
    const float* A_log      = (const float*)d_in[6];
    const float* D          = (const float*)d_in[7];
    const float* gnorm_w    = (const float*)d_in[8];
    const float* out_proj_w = (const float*)d_in[9];
    float* out = (float*)d_out;

    const int in_smem   = IP_TOT * 2;
    const int out_smem  = OP_TOT * 2;
    const int ssdc_smem = SC_END * 2 + 512;
    cudaFuncSetAttribute(k_inproj_mma,  cudaFuncAttributeMaxDynamicSharedMemorySize, in_smem);
    cudaFuncSetAttribute(k_outproj_mma, cudaFuncAttributeMaxDynamicSharedMemorySize, out_smem);
    cudaFuncSetAttribute(k_ssd_c_mma,   cudaFuncAttributeMaxDynamicSharedMemorySize, ssdc_smem);

    k_prep<<<4096 + 113, 256>>>(x, norm_w, in_proj_w, out_proj_w);
    k_inproj_mma<<<dim3(RTOT / 64, 7), 256, in_smem>>>();
    k_conv4<<<2048 + NBATCH * NCHK, 384>>>(conv_w, conv_b, A_log, dt_bias);
    k_ssd_a_mma<<<NCID, 256>>>();
    k_ssd_b_mma<<<dim3(NBATCH * NH, 32), 256>>>();
    k_ssd_c_mma<<<NCID, 256, ssdc_smem>>>(D);
    k_gate<<<RTOT / 8, 256>>>(gnorm_w);
    k_outproj_mma<<<RTOT / 64, 256, out_smem>>>(x, out);
}

// round 16
// speedup vs baseline: 1.2858x; 1.0082x over previous
#include <cuda_runtime.h>
#include <cuda_bf16.h>
#include <cstdint>

#define RTOT   32768
#define LSEQ   4096
#define NBATCH 8
#define DMODEL 128
#define DPROJ  648
#define DINNER 256
#define CONVD  384
#define NH     8
#define HD     32
#define QC     64
#define NCHK   (LSEQ/QC)
#define NCID   (NBATCH*NH*NCHK)

// ---------------- scratch (device globals) ----------------------------------
__device__ __align__(16) float g_zx [(size_t)RTOT * DPROJ];
__device__ __align__(16) float g_dtb[RTOT * NH];
__device__ __align__(16) float g_y  [RTOT * DINNER];
__device__ __align__(16) float g_S  [(size_t)NCID * QC];
__device__ __align__(16) float g_ssc[(size_t)NCID * QC];
__device__ __align__(16) float g_T  [NCID];
__device__ __align__(16) __nv_bfloat16 g_xch[RTOT * CONVD];
__device__ __align__(16) __nv_bfloat16 g_xcl[RTOT * CONVD];
__device__ __align__(16) __nv_bfloat16 g_Uh [(size_t)NCID * 2048];
__device__ __align__(16) __nv_bfloat16 g_Ul [(size_t)NCID * 2048];
__device__ __align__(16) __nv_bfloat16 g_hsh[(size_t)NCID * 2048];
__device__ __align__(16) __nv_bfloat16 g_hsl[(size_t)NCID * 2048];
__device__ __align__(16) __nv_bfloat16 g_ah [RTOT * DMODEL];
__device__ __align__(16) __nv_bfloat16 g_al [RTOT * DMODEL];
__device__ __align__(16) __nv_bfloat16 g_wih[672 * DMODEL];
__device__ __align__(16) __nv_bfloat16 g_wil[672 * DMODEL];
__device__ __align__(16) __nv_bfloat16 g_gh [RTOT * DINNER];
__device__ __align__(16) __nv_bfloat16 g_gl [RTOT * DINNER];
__device__ __align__(16) __nv_bfloat16 g_woh[DMODEL * DINNER];
__device__ __align__(16) __nv_bfloat16 g_wol[DMODEL * DINNER];
// -----------------------------------------------------------------------------

// ---- warp MMA helpers ----
static __device__ __forceinline__ uint32_t smem_u32(const void* p) {
    uint32_t a;
    asm("{ .reg .u64 t; cvta.to.shared.u64 t, %1; cvt.u32.u64 %0, t; }"
        : "=r"(a) : "l"(p));
    return a;
}
#define LDSM4(r, addr) \
    asm volatile("ldmatrix.sync.aligned.m8n8.x4.shared.b16 {%0,%1,%2,%3}, [%4];" \
        : "=r"((r)[0]), "=r"((r)[1]), "=r"((r)[2]), "=r"((r)[3]) : "r"(addr))
#define LDSM4T(r, addr) \
    asm volatile("ldmatrix.sync.aligned.m8n8.x4.trans.shared.b16 {%0,%1,%2,%3}, [%4];" \
        : "=r"((r)[0]), "=r"((r)[1]), "=r"((r)[2]), "=r"((r)[3]) : "r"(addr))
#define MMA16816(d, a, b0, b1) \
    asm volatile("mma.sync.aligned.m16n8k16.row.col.f32.bf16.bf16.f32 " \
        "{%0,%1,%2,%3}, {%4,%5,%6,%7}, {%8,%9}, {%0,%1,%2,%3};" \
        : "+f"((d)[0]), "+f"((d)[1]), "+f"((d)[2]), "+f"((d)[3]) \
        : "r"((a)[0]), "r"((a)[1]), "r"((a)[2]), "r"((a)[3]), "r"(b0), "r"(b1))

// ---- packed bf16 split helpers (bit-identical to scalar rn split) ----
static __device__ __forceinline__ uint32_t cvt_bf2(float lo, float hi) {
    uint32_t r;
    asm("cvt.rn.bf16x2.f32 %0, %1, %2;" : "=r"(r) : "f"(hi), "f"(lo));
    return r;
}
static __device__ __forceinline__ float bflo(uint32_t v) {
    return __uint_as_float(v << 16);
}
static __device__ __forceinline__ float bfhi(uint32_t v) {
    return __uint_as_float(v & 0xffff0000u);
}
static __device__ __forceinline__ void split2(float a, float b,
                                              uint32_t& h2, uint32_t& l2) {
    h2 = cvt_bf2(a, b);
    l2 = cvt_bf2(a - bflo(h2), b - bfhi(h2));
}
static __device__ __forceinline__ float silu(float v) {
    return v / (1.f + __expf(-v));
}

// ---------------- K0: fused weight-split + RMSNorm --------------------------
__global__ void k_prep(const float* __restrict__ x, const float* __restrict__ w,
                       const float* __restrict__ Wi, const float* __restrict__ Wo) {
    if (blockIdx.x < 4096) {
        int row  = blockIdx.x * 8 + (threadIdx.x >> 5);
        int lane = threadIdx.x & 31;
        float4 v = ((const float4*)(x + (size_t)row * DMODEL))[lane];
        float ss = v.x * v.x + v.y * v.y + v.z * v.z + v.w * v.w;
#pragma unroll
        for (int o = 16; o; o >>= 1) ss += __shfl_xor_sync(0xffffffffu, ss, o);
        float sc = rsqrtf(ss * (1.f / DMODEL) + 1e-5f);
        float4 wv = ((const float4*)w)[lane];
        uint32_t h0, l0, h1, l1;
        split2(v.x * sc * wv.x, v.y * sc * wv.y, h0, l0);
        split2(v.z * sc * wv.z, v.w * sc * wv.w, h1, l1);
        ((uint2*)(g_ah + (size_t)row * DMODEL))[lane] = make_uint2(h0, h1);
        ((uint2*)(g_al + (size_t)row * DMODEL))[lane] = make_uint2(l0, l1);
    } else {
        int idx = (blockIdx.x - 4096) * 256 + threadIdx.x;
        const int NWI = DPROJ * DMODEL / 4;
        const int NWO = DMODEL * DINNER / 4;
        if (idx < NWI) {
            float4 v = ((const float4*)Wi)[idx];
            uint32_t h0, l0, h1, l1;
            split2(v.x, v.y, h0, l0);
            split2(v.z, v.w, h1, l1);
            ((uint2*)g_wih)[idx] = make_uint2(h0, h1);
            ((uint2*)g_wil)[idx] = make_uint2(l0, l1);
        } else if (idx < NWI + NWO) {
            int j = idx - NWI;
            float4 v = ((const float4*)Wo)[j];
            uint32_t h0, l0, h1, l1;
            split2(v.x, v.y, h0, l0);
            split2(v.z, v.w, h1, l1);
            ((uint2*)g_woh)[j] = make_uint2(h0, h1);
            ((uint2*)g_wol)[j] = make_uint2(l0, l1);
        }
    }
}

// ---------------- K1: in_proj GEMM via HMMA bf16x3, tile 64x96, K=128 -------
#define IP_AH 0
#define IP_AL 8704
#define IP_BH 17408
#define IP_BL 30464
#define IP_TOT 43520
__global__ void __launch_bounds__(256, 2) k_inproj_mma() {
    extern __shared__ __align__(16) __nv_bfloat16 smb[];
    int tid = threadIdx.x, wid = tid >> 5, lane = tid & 31;
    int rowBase = blockIdx.x * 64;
    int colBase = blockIdx.y * 96;

    for (int i = tid; i < 1024; i += 256) {
        int r = i >> 4, c = (i & 15) << 3;
        *(uint4*)&smb[IP_AH + r * 136 + c] =
            *(const uint4*)(g_ah + (size_t)(rowBase + r) * DMODEL + c);
        *(uint4*)&smb[IP_AL + r * 136 + c] =
            *(const uint4*)(g_al + (size_t)(rowBase + r) * DMODEL + c);
    }
    for (int i = tid; i < 1536; i += 256) {
        int r = i >> 4, c = (i & 15) << 3;
        *(uint4*)&smb[IP_BH + r * 136 + c] =
            *(const uint4*)(g_wih + (size_t)(colBase + r) * DMODEL + c);
        *(uint4*)&smb[IP_BL + r * 136 + c] =
            *(const uint4*)(g_wil + (size_t)(colBase + r) * DMODEL + c);
    }
    __syncthreads();

    uint32_t sb = smem_u32(smb);
    int mw = wid & 3, nw = wid >> 2;
    int arow = mw * 16, ncol = nw * 48;
    float acc[6][4] = {};
    int lrow = lane & 15, lk = (lane >> 4) << 3;
    int brow = (lane & 7) + ((lane >> 4) & 1) * 8;
    int bk = ((lane >> 3) & 1) << 3;
#pragma unroll
    for (int kf = 0; kf < 8; kf++) {
        int k0 = kf << 4;
        uint32_t ah[4], al[4];
        uint32_t ad = sb + (uint32_t)(((arow + lrow) * 136 + k0 + lk) * 2);
        LDSM4(ah, ad + IP_AH * 2);
        LDSM4(al, ad + IP_AL * 2);
        uint32_t bh[3][4], bl[3][4];
#pragma unroll
        for (int ng = 0; ng < 3; ng++) {
            uint32_t ad2 = sb + (uint32_t)(((ncol + ng * 16 + brow) * 136 + k0 + bk) * 2);
            LDSM4(bh[ng], ad2 + IP_BH * 2);
            LDSM4(bl[ng], ad2 + IP_BL * 2);
        }
#pragma unroll
        for (int nf = 0; nf < 6; nf++) {
            uint32_t* BH = &bh[nf >> 1][(nf & 1) * 2];
            uint32_t* BL = &bl[nf >> 1][(nf & 1) * 2];
            MMA16816(acc[nf], ah, BH[0], BH[1]);
            MMA16816(acc[nf], ah, BL[0], BL[1]);
            MMA16816(acc[nf], al, BH[0], BH[1]);
        }
    }
    int g = lane >> 2, tg = lane & 3;
    int r = rowBase + arow + g;
#pragma unroll
    for (int nf = 0; nf < 6; nf++) {
        int c = colBase + ncol + nf * 8 + tg * 2;
        if (c < DPROJ) {
            *(float2*)&g_zx[(size_t)r * DPROJ + c] =
                make_float2(acc[nf][0], acc[nf][1]);
            *(float2*)&g_zx[(size_t)(r + 8) * DPROJ + c] =
                make_float2(acc[nf][2], acc[nf][3]);
        }
    }
}

// ---------------- K2: conv(K=4)+SiLU + dt-scan (tail blocks) ----------------
__global__ void __launch_bounds__(384, 3) k_conv4(const float* __restrict__ cw,
                                                  const float* __restrict__ cb,
                                                  const float* __restrict__ A_log,
                                                  const float* __restrict__ dtb) {
    __shared__ float sdt[512];
    int t = threadIdx.x;
    if (blockIdx.x < 2048) {
        int c = (t % 96) * 4;
        int r0 = blockIdx.x * 16 + (t / 96) * 4;
        bool hist = (r0 & (LSEQ - 1)) != 0;
        float4 wA = *(const float4*)&cw[(c + 0) * 4];
        float4 wB = *(const float4*)&cw[(c + 1) * 4];
        float4 wC = *(const float4*)&cw[(c + 2) * 4];
        float4 wD = *(const float4*)&cw[(c + 3) * 4];
        float4 bias = *(const float4*)&cb[c];
        const float* src = g_zx + 256 + c;
        float4 z = make_float4(0.f, 0.f, 0.f, 0.f);
        float4 x0 = hist ? *(const float4*)&src[(size_t)(r0 - 3) * DPROJ] : z;
        float4 x1 = hist ? *(const float4*)&src[(size_t)(r0 - 2) * DPROJ] : z;
        float4 x2 = hist ? *(const float4*)&src[(size_t)(r0 - 1) * DPROJ] : z;
#pragma unroll
        for (int s = 0; s < 4; s++) {
            int r = r0 + s;
            float4 x3 = *(const float4*)&src[(size_t)r * DPROJ];
            float oa = silu(bias.x + wA.x * x0.x + wA.y * x1.x + wA.z * x2.x + wA.w * x3.x);
            float ob = silu(bias.y + wB.x * x0.y + wB.y * x1.y + wB.z * x2.y + wB.w * x3.y);
            float oc = silu(bias.z + wC.x * x0.z + wC.y * x1.z + wC.z * x2.z + wC.w * x3.z);
            float od = silu(bias.w + wD.x * x0.w + wD.y * x1.w + wD.z * x2.w + wD.w * x3.w);
            uint32_t h0, l0, h1, l1;
            split2(oa, ob, h0, l0);
            split2(oc, od, h1, l1);
            *(uint2*)&g_xch[(size_t)r * CONVD + c] = make_uint2(h0, h1);
            *(uint2*)&g_xcl[(size_t)r * CONVD + c] = make_uint2(l0, l1);
            x0 = x1; x1 = x2; x2 = x3;
        }
    } else {
        int bc = blockIdx.x - 2048;
        int b = bc >> 6, c = bc & 63;
        int r0 = b * LSEQ + c * QC;
        for (int i = t; i < 512; i += 384) {
            int s = i >> 3, hh = i & 7;
            float v = g_zx[(size_t)(r0 + s) * DPROJ + 640 + hh] + dtb[hh];
            v = (v > 20.f) ? v : log1pf(__expf(v));
            sdt[hh * 64 + s] = v;
            g_dtb[(size_t)(r0 + s) * NH + hh] = v;
        }
        __syncthreads();
        if (t < 256) {
            int w = t >> 5, j = t & 31;
            float A = -__expf(A_log[w]);
            float d0 = sdt[w * 64 + 2 * j], d1 = sdt[w * 64 + 2 * j + 1];
            float v0 = d0 * A, v1 = d1 * A;
            float pair = v0 + v1;
            float ps = pair;
#pragma unroll
            for (int o = 1; o < 32; o <<= 1) {
                float u = __shfl_up_sync(0xffffffffu, ps, o);
                if (j >= o) ps += u;
            }
            float S0 = ps - pair + v0, S1 = ps;
            float T = __shfl_sync(0xffffffffu, ps, 31);
            int cid = ((b * NH + w) << 6) | c;
            *(float2*)&g_S[(size_t)cid * QC + 2 * j]   = make_float2(S0, S1);
            *(float2*)&g_ssc[(size_t)cid * QC + 2 * j] =
                make_float2(__expf(T - S0) * d0, __expf(T - S1) * d1);
            if (j == 0) g_T[cid] = T;
        }
    }
}

// ---------------- SSD pass A via HMMA bf16x3 (single sync) ------------------
#define SA_BH 0
#define SA_BL 4608
#define SA_XH 9216
#define SA_XL 11776
#define SA_END 14336
__global__ void __launch_bounds__(256) k_ssd_a_mma() {
    __shared__ __align__(16) __nv_bfloat16 smb[SA_END];
    int tid = threadIdx.x;
    int cid = blockIdx.x;
    int bh = cid >> 6, c = cid & 63;
    int b = bh >> 3, h = bh & 7;
    int r0 = b * LSEQ + c * QC;

    for (int i = tid; i < 512; i += 256) {
        int s = i >> 3, q = (i & 7) * 8;
        *(uint4*)&smb[SA_BH + s * 72 + q] =
            *(const uint4*)&g_xch[(size_t)(r0 + s) * CONVD + 256 + q];
        *(uint4*)&smb[SA_BL + s * 72 + q] =
            *(const uint4*)&g_xcl[(size_t)(r0 + s) * CONVD + 256 + q];
    }
    for (int i = tid; i < 512; i += 256) {
        int s = i >> 3, q = (i & 7) * 4;
        uint2 hv = *(const uint2*)&g_xch[(size_t)(r0 + s) * CONVD + h * HD + q];
        uint2 lv = *(const uint2*)&g_xcl[(size_t)(r0 + s) * CONVD + h * HD + q];
        float sc = g_ssc[(size_t)cid * QC + s];
        uint32_t h0, l0, h1, l1;
        split2((bflo(hv.x) + bflo(lv.x)) * sc, (bfhi(hv.x) + bfhi(lv.x)) * sc, h0, l0);
        split2((bflo(hv.y) + bflo(lv.y)) * sc, (bfhi(hv.y) + bfhi(lv.y)) * sc, h1, l1);
        *(uint2*)&smb[SA_XH + s * 40 + q] = make_uint2(h0, h1);
        *(uint2*)&smb[SA_XL + s * 40 + q] = make_uint2(l0, l1);
    }
    __syncthreads();

    uint32_t sb = smem_u32(smb);
    int wid = tid >> 5, lane = tid & 31;
    int mw = wid & 1, nw = wid >> 1;
    int gidx = lane >> 3;
    int a_soff = (gidx >> 1) * 8, a_poff = (gidx & 1) * 8;
    int b_soff = ((lane >> 3) & 1) * 8, b_noff = (lane >> 4) * 8;
    float acc[2][4] = {};
#pragma unroll
    for (int kf = 0; kf < 4; kf++) {
        int k0 = kf << 4;
        uint32_t xh4[4], xl4[4], bh4[4], bl4[4];
        uint32_t ax = sb + (uint32_t)((SA_XH + (k0 + a_soff + (lane & 7)) * 40
                                       + mw * 16 + a_poff) * 2);
        LDSM4T(xh4, ax);
        LDSM4T(xl4, ax + (SA_XL - SA_XH) * 2);
        uint32_t bad = sb + (uint32_t)((SA_BH + (k0 + b_soff + (lane & 7)) * 72
                                        + nw * 16 + b_noff) * 2);
        LDSM4T(bh4, bad);
        LDSM4T(bl4, bad + (SA_BL - SA_BH) * 2);
#pragma unroll
        for (int nf = 0; nf < 2; nf++) {
            MMA16816(acc[nf], xh4, bh4[nf * 2], bh4[nf * 2 + 1]);
            MMA16816(acc[nf], xh4, bl4[nf * 2], bl4[nf * 2 + 1]);
            MMA16816(acc[nf], xl4, bh4[nf * 2], bh4[nf * 2 + 1]);
        }
    }
    int g = lane >> 2, tg = lane & 3;
    size_t ub = (size_t)cid * 2048;
#pragma unroll
    for (int nf = 0; nf < 2; nf++) {
        int p = mw * 16 + g, n = nw * 16 + nf * 8 + tg * 2;
#pragma unroll
        for (int e = 0; e < 2; e++) {
            int pp = p + e * 8;
            uint32_t h2, l2;
            split2(acc[nf][e * 2 + 0], acc[nf][e * 2 + 1], h2, l2);
            *(uint32_t*)&g_Uh[ub + pp * 64 + n] = h2;
            *(uint32_t*)&g_Ul[ub + pp * 64 + n] = l2;
        }
    }
}

// ---------------- SSD pass B: hs = W @ U via HMMA (W computed in-block) -----
#define SB_WH 0
#define SB_WL 4608
#define SB_UH 9216
#define SB_UL 13824
#define SB_END 18432
__global__ void __launch_bounds__(256) k_ssd_b_mma() {
    __shared__ __align__(16) __nv_bfloat16 smb[SB_END];
    __shared__ float sI[64];
    int tid = threadIdx.x, wid = tid >> 5, lane = tid & 31;
    int bh = blockIdx.x;
    int col0 = blockIdx.y * 64;
    if (tid < 64) {
        float v = g_T[bh * 64 + tid];
#pragma unroll
        for (int o = 1; o < 32; o <<= 1) {
            float u = __shfl_up_sync(0xffffffffu, v, o);
            if ((tid & 31) >= o) v += u;
        }
        sI[tid] = v;
    }
    __syncthreads();
    if (tid >= 32 && tid < 64) sI[tid] += sI[31];
    __syncthreads();
    for (int i = tid; i < 2048; i += 256) {
        int c = i >> 5, j = (i & 31) * 2;
        float w0 = (j < c)     ? __expf(sI[c - 1] - sI[j])     : 0.f;
        float w1 = (j + 1 < c) ? __expf(sI[c - 1] - sI[j + 1]) : 0.f;
        uint32_t h2, l2;
        split2(w0, w1, h2, l2);
        *(uint32_t*)&smb[SB_WH + c * 72 + j] = h2;
        *(uint32_t*)&smb[SB_WL + c * 72 + j] = l2;
    }
    for (int i = tid; i < 512; i += 256) {
        int j = i >> 3, q = (i & 7) * 8;
        *(uint4*)&smb[SB_UH + j * 72 + q] =
            *(const uint4*)&g_Uh[((size_t)bh * 64 + j) * 2048 + col0 + q];
        *(uint4*)&smb[SB_UL + j * 72 + q] =
            *(const uint4*)&g_Ul[((size_t)bh * 64 + j) * 2048 + col0 + q];
    }
    __syncthreads();
    uint32_t sb = smem_u32(smb);
    int mw = wid & 3, nw = wid >> 2;
    int crow = mw * 16, ncol = nw * 32;
    int lrow = lane & 15, lk = (lane >> 4) << 3;
    int b_soff = ((lane >> 3) & 1) * 8, b_noff = (lane >> 4) * 8;
    float acc[4][4] = {};
#pragma unroll
    for (int kf = 0; kf < 4; kf++) {
        int k0 = kf << 4;
        uint32_t whf[4], wlf[4];
        uint32_t ad = sb + (uint32_t)((SB_WH + (crow + lrow) * 72 + k0 + lk) * 2);
        LDSM4(whf, ad);
        LDSM4(wlf, ad + (SB_WL - SB_WH) * 2);
        uint32_t uh[2][4], ul[2][4];
#pragma unroll
        for (int hf = 0; hf < 2; hf++) {
            uint32_t ad2 = sb + (uint32_t)((SB_UH + (k0 + b_soff + (lane & 7)) * 72
                                            + ncol + hf * 16 + b_noff) * 2);
            LDSM4T(uh[hf], ad2);
            LDSM4T(ul[hf], ad2 + (SB_UL - SB_UH) * 2);
        }
#pragma unroll
        for (int nf = 0; nf < 4; nf++) {
            uint32_t* BH = &uh[nf >> 1][(nf & 1) * 2];
            uint32_t* BL = &ul[nf >> 1][(nf & 1) * 2];
            MMA16816(acc[nf], whf, BH[0], BH[1]);
            MMA16816(acc[nf], whf, BL[0], BL[1]);
            MMA16816(acc[nf], wlf, BH[0], BH[1]);
        }
    }
    int g = lane >> 2, tg = lane & 3;
#pragma unroll
    for (int nf = 0; nf < 4; nf++) {
        int col = col0 + ncol + nf * 8 + tg * 2;
#pragma unroll
        for (int e = 0; e < 2; e++) {
            int c = crow + g + e * 8;
            uint32_t h2, l2;
            split2(acc[nf][e * 2 + 0], acc[nf][e * 2 + 1], h2, l2);
            *(uint32_t*)&g_hsh[((size_t)bh * 64 + c) * 2048 + col] = h2;
            *(uint32_t*)&g_hsl[((size_t)bh * 64 + c) * 2048 + col] = l2;
        }
    }
}

// ---------------- SSD pass C via HMMA bf16x3 (occ 3) ------------------------
#define SC_P  72
#define SC_CH 0
#define SC_CL 4608
#define SC_BH 9216
#define SC_BL 13824
#define SC_XH 18432
#define SC_XL 20992
#define SC_HH 23552
#define SC_HL 25856
#define SC_END 28160
__global__ void __launch_bounds__(256, 3) k_ssd_c_mma(const float* __restrict__ Dp) {
    extern __shared__ __align__(16) __nv_bfloat16 smb[];
    float* Ssm = (float*)(smb + SC_END);
    float* dts = Ssm + 64;
    int tid = threadIdx.x, wid = tid >> 5, lane = tid & 31;
    int cid = blockIdx.x;
    int bh = cid >> 6, c = cid & 63;
    int b = bh >> 3, h = bh & 7;
    int r0 = b * LSEQ + c * QC;
    float Dh = Dp[h];

    for (int i = tid; i < 512; i += 256) {
        int s = i >> 3, q = (i & 7) * 8;
        size_t ro = (size_t)(r0 + s) * CONVD;
        *(uint4*)&smb[SC_CH + s * SC_P + q] = *(const uint4*)&g_xch[ro + 320 + q];
        *(uint4*)&smb[SC_CL + s * SC_P + q] = *(const uint4*)&g_xcl[ro + 320 + q];
        *(uint4*)&smb[SC_BH + s * SC_P + q] = *(const uint4*)&g_xch[ro + 256 + q];
        *(uint4*)&smb[SC_BL + s * SC_P + q] = *(const uint4*)&g_xcl[ro + 256 + q];
    }
    for (int i = tid; i < 256; i += 256) {
        int s = i >> 2, q = (i & 3) * 8;
        size_t ro = (size_t)(r0 + s) * CONVD + h * HD;
        *(uint4*)&smb[SC_XH + s * 40 + q] = *(const uint4*)&g_xch[ro + q];
        *(uint4*)&smb[SC_XL + s * 40 + q] = *(const uint4*)&g_xcl[ro + q];
    }
    for (int i = tid; i < 256; i += 256) {
        int p = i >> 3, q = (i & 7) * 8;
        size_t ho = (size_t)cid * 2048 + p * 64 + q;
        *(uint4*)&smb[SC_HH + p * SC_P + q] = *(const uint4*)&g_hsh[ho];
        *(uint4*)&smb[SC_HL + p * SC_P + q] = *(const uint4*)&g_hsl[ho];
    }
    if (tid < 64) {
        Ssm[tid] = g_S[(size_t)cid * QC + tid];
        dts[tid] = g_dtb[(size_t)(r0 + tid) * NH + h];
    }
    __syncthreads();

    uint32_t sb = smem_u32(smb);
    int mw = wid & 3, nw = wid >> 2;
    int arow = mw * 16;
    int lrow = lane & 15, lk = (lane >> 4) << 3;
    int brow = (lane & 7) + ((lane >> 4) & 1) * 8;
    int bk = ((lane >> 3) & 1) << 3;
    int b_soff = ((lane >> 3) & 1) * 8, b_noff = (lane >> 4) * 8;

    float accg[4][4] = {};
    if (!(nw == 1 && mw < 2)) {
#pragma unroll
        for (int kf = 0; kf < 4; kf++) {
            int k0 = kf << 4;
            uint32_t ch[4], cl[4];
            uint32_t ad = sb + (uint32_t)(((arow + lrow) * SC_P + k0 + lk) * 2);
            LDSM4(ch, ad + SC_CH * 2);
            LDSM4(cl, ad + SC_CL * 2);
            uint32_t bh2[2][4], bl2[2][4];
#pragma unroll
            for (int ng = 0; ng < 2; ng++) {
                uint32_t ad2 = sb + (uint32_t)(((nw * 32 + ng * 16 + brow) * SC_P + k0 + bk) * 2);
                LDSM4(bh2[ng], ad2 + SC_BH * 2);
                LDSM4(bl2[ng], ad2 + SC_BL * 2);
            }
#pragma unroll
            for (int nf = 0; nf < 4; nf++) {
                uint32_t* BH = &bh2[nf >> 1][(nf & 1) * 2];
                uint32_t* BL = &bl2[nf >> 1][(nf & 1) * 2];
                MMA16816(accg[nf], ch, BH[0], BH[1]);
                MMA16816(accg[nf], ch, BL[0], BL[1]);
                MMA16816(accg[nf], cl, BH[0], BH[1]);
            }
        }
    }
    __syncthreads();

    int g = lane >> 2, tg = lane & 3;
    int t0 = arow + g, t1 = arow + g + 8;
    float St0 = Ssm[t0], St1 = Ssm[t1];
#pragma unroll
    for (int nf = 0; nf < 4; nf++) {
        int s0 = nw * 32 + nf * 8 + tg * 2;
        float ds0 = dts[s0], Ss0 = Ssm[s0];
        float ds1 = dts[s0 + 1], Ss1 = Ssm[s0 + 1];
        float m00 = (s0 <= t0)     ? accg[nf][0] * __expf(St0 - Ss0) * ds0 : 0.f;
        float m01 = (s0 + 1 <= t0) ? accg[nf][1] * __expf(St0 - Ss1) * ds1 : 0.f;
        float m10 = (s0 <= t1)     ? accg[nf][2] * __expf(St1 - Ss0) * ds0 : 0.f;
        float m11 = (s0 + 1 <= t1) ? accg[nf][3] * __expf(St1 - Ss1) * ds1 : 0.f;
        uint32_t h2, l2;
        split2(m00, m01, h2, l2);
        *(uint32_t*)&smb[SC_BH + t0 * SC_P + s0] = h2;
        *(uint32_t*)&smb[SC_BL + t0 * SC_P + s0] = l2;
        split2(m10, m11, h2, l2);
        *(uint32_t*)&smb[SC_BH + t1 * SC_P + s0] = h2;
        *(uint32_t*)&smb[SC_BL + t1 * SC_P + s0] = l2;
    }
    __syncthreads();

    int pw = wid >> 2;
    int prow = pw * 16;
    float ayi[2][4] = {}, ayo[2][4] = {};
#pragma unroll
    for (int kf = 0; kf < 4; kf++) {
        int k0 = kf << 4;
        uint32_t ad = sb + (uint32_t)(((arow + lrow) * SC_P + k0 + lk) * 2);
        uint32_t mh[4], ml[4], ch[4], cl[4];
        LDSM4(mh, ad + SC_BH * 2);
        LDSM4(ml, ad + SC_BL * 2);
        LDSM4(ch, ad + SC_CH * 2);
        LDSM4(cl, ad + SC_CL * 2);
        uint32_t xh[4], xl[4], hh2[4], hl2[4];
        uint32_t adx = sb + (uint32_t)((SC_XH + (k0 + b_soff + (lane & 7)) * 40
                                        + prow + b_noff) * 2);
        LDSM4T(xh, adx);
        LDSM4T(xl, adx + (SC_XL - SC_XH) * 2);
        uint32_t adh = sb + (uint32_t)(((prow + brow) * SC_P + k0 + bk) * 2);
        LDSM4(hh2, adh + SC_HH * 2);
        LDSM4(hl2, adh + SC_HL * 2);
#pragma unroll
        for (int nf = 0; nf < 2; nf++) {
            uint32_t* XH = &xh[nf * 2];  uint32_t* XL = &xl[nf * 2];
            uint32_t* HH = &hh2[nf * 2]; uint32_t* HL = &hl2[nf * 2];
            MMA16816(ayi[nf], mh, XH[0], XH[1]);
            MMA16816(ayi[nf], mh, XL[0], XL[1]);
            MMA16816(ayi[nf], ml, XH[0], XH[1]);
            MMA16816(ayo[nf], ch, HH[0], HH[1]);
            MMA16816(ayo[nf], ch, HL[0], HL[1]);
            MMA16816(ayo[nf], cl, HH[0], HH[1]);
        }
    }

    float eS0 = __expf(St0), eS1 = __expf(St1);
#pragma unroll
    for (int nf = 0; nf < 2; nf++) {
        int p = prow + nf * 8 + tg * 2;
        uint32_t xh0 = *(const uint32_t*)&smb[SC_XH + t0 * 40 + p];
        uint32_t xl0 = *(const uint32_t*)&smb[SC_XL + t0 * 40 + p];
        uint32_t xh1 = *(const uint32_t*)&smb[SC_XH + t1 * 40 + p];
        uint32_t xl1 = *(const uint32_t*)&smb[SC_XL + t1 * 40 + p];
        float xv00 = bflo(xh0) + bflo(xl0);
        float xv01 = bfhi(xh0) + bfhi(xl0);
        float xv10 = bflo(xh1) + bflo(xl1);
        float xv11 = bfhi(xh1) + bfhi(xl1);
        *(float2*)&g_y[(size_t)(r0 + t0) * DINNER + h * HD + p] =
            make_float2(ayi[nf][0] + eS0 * ayo[nf][0] + Dh * xv00,
                        ayi[nf][1] + eS0 * ayo[nf][1] + Dh * xv01);
        *(float2*)&g_y[(size_t)(r0 + t1) * DINNER + h * HD + p] =
            make_float2(ayi[nf][2] + eS1 * ayo[nf][2] + Dh * xv10,
                        ayi[nf][3] + eS1 * ayo[nf][3] + Dh * xv11);
    }
}

// ---------------- K4a: gating + gated RMSNorm (warp/row) --------------------
__global__ void k_gate(const float* __restrict__ gw) {
    int r    = blockIdx.x * 8 + (threadIdx.x >> 5);
    int lane = threadIdx.x & 31;
    float4 y0 = *(const float4*)&g_y[(size_t)r * DINNER + lane * 4];
    float4 y1 = *(const float4*)&g_y[(size_t)r * DINNER + 128 + lane * 4];
    float4 z0 = *(const float4*)&g_zx[(size_t)r * DPROJ + lane * 4];
    float4 z1 = *(const float4*)&g_zx[(size_t)r * DPROJ + 128 + lane * 4];
    float gv[8];
    gv[0] = y0.x * silu(z0.x); gv[1] = y0.y * silu(z0.y);
    gv[2] = y0.z * silu(z0.z); gv[3] = y0.w * silu(z0.w);
    gv[4] = y1.x * silu(z1.x); gv[5] = y1.y * silu(z1.y);
    gv[6] = y1.z * silu(z1.z); gv[7] = y1.w * silu(z1.w);
    float ss = 0.f;
#pragma unroll
    for (int j = 0; j < 8; j++) ss += gv[j] * gv[j];
#pragma unroll
    for (int o = 16; o; o >>= 1) ss += __shfl_xor_sync(0xffffffffu, ss, o);
    float sc = rsqrtf(ss * (1.f / DINNER) + 1e-5f);
    float4 w0 = *(const float4*)&gw[lane * 4];
    float4 w1 = *(const float4*)&gw[128 + lane * 4];
    float wv[8] = {w0.x, w0.y, w0.z, w0.w, w1.x, w1.y, w1.z, w1.w};
    uint32_t h2[4], l2[4];
#pragma unroll
    for (int j = 0; j < 4; j++)
        split2(gv[2 * j] * sc * wv[2 * j], gv[2 * j + 1] * sc * wv[2 * j + 1],
               h2[j], l2[j]);
    *(uint2*)&g_gh[(size_t)r * DINNER + lane * 4]       = make_uint2(h2[0], h2[1]);
    *(uint2*)&g_gh[(size_t)r * DINNER + 128 + lane * 4] = make_uint2(h2[2], h2[3]);
    *(uint2*)&g_gl[(size_t)r * DINNER + lane * 4]       = make_uint2(l2[0], l2[1]);
    *(uint2*)&g_gl[(size_t)r * DINNER + 128 + lane * 4] = make_uint2(l2[2], l2[3]);
}

// ---------------- K4b: out_proj HMMA bf16x3 + residual, tile 64x128 ---------
#define OP_AH 0
#define OP_AL 8704
#define OP_BH 17408
#define OP_BL 34816
#define OP_TOT 52224
__global__ void __launch_bounds__(256, 2) k_outproj_mma(const float* __restrict__ x,
                                                        float* __restrict__ out) {
    extern __shared__ __align__(16) __nv_bfloat16 smb[];
    int tid = threadIdx.x, wid = tid >> 5, lane = tid & 31;
    int rowBase = blockIdx.x * 64;
    uint32_t sb = smem_u32(smb);
    int mw = wid & 3, nw = wid >> 2;
    int arow = mw * 16, ncol = nw * 64;
    float acc[8][4] = {};
    int lrow = lane & 15, lk = (lane >> 4) << 3;
    int brow = (lane & 7) + ((lane >> 4) & 1) * 8;
    int bk = ((lane >> 3) & 1) << 3;

    for (int kc = 0; kc < 2; kc++) {
        if (kc) __syncthreads();
        for (int i = tid; i < 1024; i += 256) {
            int r = i >> 4, c = (i & 15) << 3;
            size_t ao = (size_t)(rowBase + r) * DINNER + kc * 128 + c;
            *(uint4*)&smb[OP_AH + r * 136 + c] = *(const uint4*)(g_gh + ao);
            *(uint4*)&smb[OP_AL + r * 136 + c] = *(const uint4*)(g_gl + ao);
        }
        for (int i = tid; i < 2048; i += 256) {
            int r = i >> 4, c = (i & 15) << 3;
            size_t bo = (size_t)r * DINNER + kc * 128 + c;
            *(uint4*)&smb[OP_BH + r * 136 + c] = *(const uint4*)(g_woh + bo);
            *(uint4*)&smb[OP_BL + r * 136 + c] = *(const uint4*)(g_wol + bo);
        }
        __syncthreads();
#pragma unroll
        for (int kf = 0; kf < 8; kf++) {
            int k0 = kf << 4;
            uint32_t ah[4], al[4];
            uint32_t ad = sb + (uint32_t)(((arow + lrow) * 136 + k0 + lk) * 2);
            LDSM4(ah, ad + OP_AH * 2);
            LDSM4(al, ad + OP_AL * 2);
            uint32_t bh[4][4], bl[4][4];
#pragma unroll
            for (int ng = 0; ng < 4; ng++) {
                uint32_t ad2 = sb + (uint32_t)(((ncol + ng * 16 + brow) * 136 + k0 + bk) * 2);
                LDSM4(bh[ng], ad2 + OP_BH * 2);
                LDSM4(bl[ng], ad2 + OP_BL * 2);
            }
#pragma unroll
            for (int nf = 0; nf < 8; nf++) {
                uint32_t* BH = &bh[nf >> 1][(nf & 1) * 2];
                uint32_t* BL = &bl[nf >> 1][(nf & 1) * 2];
                MMA16816(acc[nf], ah, BH[0], BH[1]);
                MMA16816(acc[nf], ah, BL[0], BL[1]);
                MMA16816(acc[nf], al, BH[0], BH[1]);
            }
        }
    }
    int g = lane >> 2, tg = lane & 3;
    int r = rowBase + arow + g;
#pragma unroll
    for (int nf = 0; nf < 8; nf++) {
        int c = ncol + nf * 8 + tg * 2;
        float2 x0 = *(const float2*)&x[(size_t)r * DMODEL + c];
        float2 x1 = *(const float2*)&x[(size_t)(r + 8) * DMODEL + c];
        *(float2*)&out[(size_t)r * DMODEL + c] =
            make_float2(acc[nf][0] + x0.x, acc[nf][1] + x0.y);
        *(float2*)&out[(size_t)(r + 8) * DMODEL + c] =
            make_float2(acc[nf][2] + x1.x, acc[nf][3] + x1.y);
    }
}

extern "C" void kernel_launch(void* const* d_in, const int* in_sizes, int n_in,
                              void* d_out, int out_size) {
    const float* x          = (const float*)d_in[0];
    const float* norm_w     = (const float*)d_in[1];
    const float* in_proj_w  = (const float*)d_in[2];
    const float* conv_w     = (const float*)d_in[3];
    const float* conv_b     = (const float*)d_in[4];
    const float* dt_bias    = (const float*)d_in[5];
    const float* A_log      = (const float*)d_in[6];
    const float* D          = (const float*)d_in[7];
    const float* gnorm_w    = (const float*)d_in[8];
    const float* out_proj_w = (const float*)d_in[9];
    float* out = (float*)d_out;

    const int in_smem   = IP_TOT * 2;
    const int out_smem  = OP_TOT * 2;
    const int ssdc_smem = SC_END * 2 + 512;
    cudaFuncSetAttribute(k_inproj_mma,  cudaFuncAttributeMaxDynamicSharedMemorySize, in_smem);
    cudaFuncSetAttribute(k_outproj_mma, cudaFuncAttributeMaxDynamicSharedMemorySize, out_smem);
    cudaFuncSetAttribute(k_ssd_c_mma,   cudaFuncAttributeMaxDynamicSharedMemorySize, ssdc_smem);

    k_prep<<<4096 + 113, 256>>>(x, norm_w, in_proj_w, out_proj_w);
    k_inproj_mma<<<dim3(RTOT / 64, 7), 256, in_smem>>>();
    k_conv4<<<2048 + NBATCH * NCHK, 384>>>(conv_w, conv_b, A_log, dt_bias);
    k_ssd_a_mma<<<NCID, 256>>>();
    k_ssd_b_mma<<<dim3(NBATCH * NH, 32), 256>>>();
    k_ssd_c_mma<<<NCID, 256, ssdc_smem>>>(D);
    k_gate<<<RTOT / 8, 256>>>(gnorm_w);
    k_outproj_mma<<<RTOT / 64, 256, out_smem>>>(x, out);
}

// round 17
// speedup vs baseline: 1.3058x; 1.0156x over previous
#include <cuda_runtime.h>
#include <cuda_bf16.h>
#include <cstdint>

#define RTOT   32768
#define LSEQ   4096
#define NBATCH 8
#define DMODEL 128
#define DPROJ  648
#define DINNER 256
#define CONVD  384
#define NH     8
#define HD     32
#define QC     64
#define NCHK   (LSEQ/QC)
#define NCID   (NBATCH*NH*NCHK)

// ---------------- scratch (device globals) ----------------------------------
__device__ __align__(16) float g_zx [(size_t)RTOT * DPROJ];
__device__ __align__(16) float g_dtb[RTOT * NH];
__device__ __align__(16) float g_y  [RTOT * DINNER];
__device__ __align__(16) float g_S  [(size_t)NCID * QC];
__device__ __align__(16) float g_ssc[(size_t)NCID * QC];
__device__ __align__(16) float g_T  [NCID];
__device__ __align__(16) __nv_bfloat16 g_xch[RTOT * CONVD];
__device__ __align__(16) __nv_bfloat16 g_xcl[RTOT * CONVD];
__device__ __align__(16) __nv_bfloat16 g_Uh [(size_t)NCID * 2048];
__device__ __align__(16) __nv_bfloat16 g_Ul [(size_t)NCID * 2048];
__device__ __align__(16) __nv_bfloat16 g_hsh[(size_t)NCID * 2048];
__device__ __align__(16) __nv_bfloat16 g_hsl[(size_t)NCID * 2048];
__device__ __align__(16) __nv_bfloat16 g_ah [RTOT * DMODEL];
__device__ __align__(16) __nv_bfloat16 g_al [RTOT * DMODEL];
__device__ __align__(16) __nv_bfloat16 g_wih[672 * DMODEL];
__device__ __align__(16) __nv_bfloat16 g_wil[672 * DMODEL];
__device__ __align__(16) __nv_bfloat16 g_gh [RTOT * DINNER];
__device__ __align__(16) __nv_bfloat16 g_gl [RTOT * DINNER];
__device__ __align__(16) __nv_bfloat16 g_woh[DMODEL * DINNER];
__device__ __align__(16) __nv_bfloat16 g_wol[DMODEL * DINNER];
// -----------------------------------------------------------------------------

// ---- warp MMA helpers ----
static __device__ __forceinline__ uint32_t smem_u32(const void* p) {
    uint32_t a;
    asm("{ .reg .u64 t; cvta.to.shared.u64 t, %1; cvt.u32.u64 %0, t; }"
        : "=r"(a) : "l"(p));
    return a;
}
#define LDSM4(r, addr) \
    asm volatile("ldmatrix.sync.aligned.m8n8.x4.shared.b16 {%0,%1,%2,%3}, [%4];" \
        : "=r"((r)[0]), "=r"((r)[1]), "=r"((r)[2]), "=r"((r)[3]) : "r"(addr))
#define LDSM4T(r, addr) \
    asm volatile("ldmatrix.sync.aligned.m8n8.x4.trans.shared.b16 {%0,%1,%2,%3}, [%4];" \
        : "=r"((r)[0]), "=r"((r)[1]), "=r"((r)[2]), "=r"((r)[3]) : "r"(addr))
#define MMA16816(d, a, b0, b1) \
    asm volatile("mma.sync.aligned.m16n8k16.row.col.f32.bf16.bf16.f32 " \
        "{%0,%1,%2,%3}, {%4,%5,%6,%7}, {%8,%9}, {%0,%1,%2,%3};" \
        : "+f"((d)[0]), "+f"((d)[1]), "+f"((d)[2]), "+f"((d)[3]) \
        : "r"((a)[0]), "r"((a)[1]), "r"((a)[2]), "r"((a)[3]), "r"(b0), "r"(b1))

// ---- packed bf16 split helpers ----
static __device__ __forceinline__ uint32_t cvt_bf2(float lo, float hi) {
    uint32_t r;
    asm("cvt.rn.bf16x2.f32 %0, %1, %2;" : "=r"(r) : "f"(hi), "f"(lo));
    return r;
}
static __device__ __forceinline__ float bflo(uint32_t v) {
    return __uint_as_float(v << 16);
}
static __device__ __forceinline__ float bfhi(uint32_t v) {
    return __uint_as_float(v & 0xffff0000u);
}
static __device__ __forceinline__ void split2(float a, float b,
                                              uint32_t& h2, uint32_t& l2) {
    h2 = cvt_bf2(a, b);
    l2 = cvt_bf2(a - bflo(h2), b - bfhi(h2));
}
static __device__ __forceinline__ float silu(float v) {
    return v / (1.f + __expf(-v));
}

// ---------------- K0: fused weight-split + RMSNorm --------------------------
__global__ void k_prep(const float* __restrict__ x, const float* __restrict__ w,
                       const float* __restrict__ Wi, const float* __restrict__ Wo) {
    if (blockIdx.x < 4096) {
        int row  = blockIdx.x * 8 + (threadIdx.x >> 5);
        int lane = threadIdx.x & 31;
        float4 v = ((const float4*)(x + (size_t)row * DMODEL))[lane];
        float ss = v.x * v.x + v.y * v.y + v.z * v.z + v.w * v.w;
#pragma unroll
        for (int o = 16; o; o >>= 1) ss += __shfl_xor_sync(0xffffffffu, ss, o);
        float sc = rsqrtf(ss * (1.f / DMODEL) + 1e-5f);
        float4 wv = ((const float4*)w)[lane];
        uint32_t h0, l0, h1, l1;
        split2(v.x * sc * wv.x, v.y * sc * wv.y, h0, l0);
        split2(v.z * sc * wv.z, v.w * sc * wv.w, h1, l1);
        ((uint2*)(g_ah + (size_t)row * DMODEL))[lane] = make_uint2(h0, h1);
        ((uint2*)(g_al + (size_t)row * DMODEL))[lane] = make_uint2(l0, l1);
    } else {
        int idx = (blockIdx.x - 4096) * 256 + threadIdx.x;
        const int NWI = DPROJ * DMODEL / 4;
        const int NWO = DMODEL * DINNER / 4;
        if (idx < NWI) {
            float4 v = ((const float4*)Wi)[idx];
            uint32_t h0, l0, h1, l1;
            split2(v.x, v.y, h0, l0);
            split2(v.z, v.w, h1, l1);
            ((uint2*)g_wih)[idx] = make_uint2(h0, h1);
            ((uint2*)g_wil)[idx] = make_uint2(l0, l1);
        } else if (idx < NWI + NWO) {
            int j = idx - NWI;
            float4 v = ((const float4*)Wo)[j];
            uint32_t h0, l0, h1, l1;
            split2(v.x, v.y, h0, l0);
            split2(v.z, v.w, h1, l1);
            ((uint2*)g_woh)[j] = make_uint2(h0, h1);
            ((uint2*)g_wol)[j] = make_uint2(l0, l1);
        }
    }
}

// ---------------- K1: in_proj GEMM via HMMA bf16x3, tile 64x96, K=128 -------
#define IP_AH 0
#define IP_AL 8704
#define IP_BH 17408
#define IP_BL 30464
#define IP_TOT 43520
__global__ void __launch_bounds__(256, 2) k_inproj_mma() {
    extern __shared__ __align__(16) __nv_bfloat16 smb[];
    int tid = threadIdx.x, wid = tid >> 5, lane = tid & 31;
    int rowBase = blockIdx.x * 64;
    int colBase = blockIdx.y * 96;

    for (int i = tid; i < 1024; i += 256) {
        int r = i >> 4, c = (i & 15) << 3;
        *(uint4*)&smb[IP_AH + r * 136 + c] =
            *(const uint4*)(g_ah + (size_t)(rowBase + r) * DMODEL + c);
        *(uint4*)&smb[IP_AL + r * 136 + c] =
            *(const uint4*)(g_al + (size_t)(rowBase + r) * DMODEL + c);
    }
    for (int i = tid; i < 1536; i += 256) {
        int r = i >> 4, c = (i & 15) << 3;
        *(uint4*)&smb[IP_BH + r * 136 + c] =
            *(const uint4*)(g_wih + (size_t)(colBase + r) * DMODEL + c);
        *(uint4*)&smb[IP_BL + r * 136 + c] =
            *(const uint4*)(g_wil + (size_t)(colBase + r) * DMODEL + c);
    }
    __syncthreads();

    uint32_t sb = smem_u32(smb);
    int mw = wid & 3, nw = wid >> 2;
    int arow = mw * 16, ncol = nw * 48;
    float acc[6][4] = {};
    int lrow = lane & 15, lk = (lane >> 4) << 3;
    int brow = (lane & 7) + ((lane >> 4) & 1) * 8;
    int bk = ((lane >> 3) & 1) << 3;
#pragma unroll
    for (int kf = 0; kf < 8; kf++) {
        int k0 = kf << 4;
        uint32_t ah[4], al[4];
        uint32_t ad = sb + (uint32_t)(((arow + lrow) * 136 + k0 + lk) * 2);
        LDSM4(ah, ad + IP_AH * 2);
        LDSM4(al, ad + IP_AL * 2);
        uint32_t bh[3][4], bl[3][4];
#pragma unroll
        for (int ng = 0; ng < 3; ng++) {
            uint32_t ad2 = sb + (uint32_t)(((ncol + ng * 16 + brow) * 136 + k0 + bk) * 2);
            LDSM4(bh[ng], ad2 + IP_BH * 2);
            LDSM4(bl[ng], ad2 + IP_BL * 2);
        }
#pragma unroll
        for (int nf = 0; nf < 6; nf++) {
            uint32_t* BH = &bh[nf >> 1][(nf & 1) * 2];
            uint32_t* BL = &bl[nf >> 1][(nf & 1) * 2];
            MMA16816(acc[nf], ah, BH[0], BH[1]);
            MMA16816(acc[nf], ah, BL[0], BL[1]);
            MMA16816(acc[nf], al, BH[0], BH[1]);
        }
    }
    int g = lane >> 2, tg = lane & 3;
    int r = rowBase + arow + g;
#pragma unroll
    for (int nf = 0; nf < 6; nf++) {
        int c = colBase + ncol + nf * 8 + tg * 2;
        if (c < DPROJ) {
            *(float2*)&g_zx[(size_t)r * DPROJ + c] =
                make_float2(acc[nf][0], acc[nf][1]);
            *(float2*)&g_zx[(size_t)(r + 8) * DPROJ + c] =
                make_float2(acc[nf][2], acc[nf][3]);
        }
    }
}

// ---------------- K2: conv(K=4)+SiLU + dt-scan (tail blocks) ----------------
__global__ void __launch_bounds__(384, 3) k_conv4(const float* __restrict__ cw,
                                                  const float* __restrict__ cb,
                                                  const float* __restrict__ A_log,
                                                  const float* __restrict__ dtb) {
    __shared__ float sdt[512];
    int t = threadIdx.x;
    if (blockIdx.x < 2048) {
        int c = (t % 96) * 4;
        int r0 = blockIdx.x * 16 + (t / 96) * 4;
        bool hist = (r0 & (LSEQ - 1)) != 0;
        float4 wA = *(const float4*)&cw[(c + 0) * 4];
        float4 wB = *(const float4*)&cw[(c + 1) * 4];
        float4 wC = *(const float4*)&cw[(c + 2) * 4];
        float4 wD = *(const float4*)&cw[(c + 3) * 4];
        float4 bias = *(const float4*)&cb[c];
        const float* src = g_zx + 256 + c;
        float4 z = make_float4(0.f, 0.f, 0.f, 0.f);
        float4 x0 = hist ? *(const float4*)&src[(size_t)(r0 - 3) * DPROJ] : z;
        float4 x1 = hist ? *(const float4*)&src[(size_t)(r0 - 2) * DPROJ] : z;
        float4 x2 = hist ? *(const float4*)&src[(size_t)(r0 - 1) * DPROJ] : z;
#pragma unroll
        for (int s = 0; s < 4; s++) {
            int r = r0 + s;
            float4 x3 = *(const float4*)&src[(size_t)r * DPROJ];
            float oa = silu(bias.x + wA.x * x0.x + wA.y * x1.x + wA.z * x2.x + wA.w * x3.x);
            float ob = silu(bias.y + wB.x * x0.y + wB.y * x1.y + wB.z * x2.y + wB.w * x3.y);
            float oc = silu(bias.z + wC.x * x0.z + wC.y * x1.z + wC.z * x2.z + wC.w * x3.z);
            float od = silu(bias.w + wD.x * x0.w + wD.y * x1.w + wD.z * x2.w + wD.w * x3.w);
            uint32_t h0, l0, h1, l1;
            split2(oa, ob, h0, l0);
            split2(oc, od, h1, l1);
            *(uint2*)&g_xch[(size_t)r * CONVD + c] = make_uint2(h0, h1);
            *(uint2*)&g_xcl[(size_t)r * CONVD + c] = make_uint2(l0, l1);
            x0 = x1; x1 = x2; x2 = x3;
        }
    } else {
        int bc = blockIdx.x - 2048;
        int b = bc >> 6, c = bc & 63;
        int r0 = b * LSEQ + c * QC;
        for (int i = t; i < 512; i += 384) {
            int s = i >> 3, hh = i & 7;
            float v = g_zx[(size_t)(r0 + s) * DPROJ + 640 + hh] + dtb[hh];
            v = (v > 20.f) ? v : log1pf(__expf(v));
            sdt[hh * 64 + s] = v;
            g_dtb[(size_t)(r0 + s) * NH + hh] = v;
        }
        __syncthreads();
        if (t < 256) {
            int w = t >> 5, j = t & 31;
            float A = -__expf(A_log[w]);
            float d0 = sdt[w * 64 + 2 * j], d1 = sdt[w * 64 + 2 * j + 1];
            float v0 = d0 * A, v1 = d1 * A;
            float pair = v0 + v1;
            float ps = pair;
#pragma unroll
            for (int o = 1; o < 32; o <<= 1) {
                float u = __shfl_up_sync(0xffffffffu, ps, o);
                if (j >= o) ps += u;
            }
            float S0 = ps - pair + v0, S1 = ps;
            float T = __shfl_sync(0xffffffffu, ps, 31);
            int cid = ((b * NH + w) << 6) | c;
            *(float2*)&g_S[(size_t)cid * QC + 2 * j]   = make_float2(S0, S1);
            *(float2*)&g_ssc[(size_t)cid * QC + 2 * j] =
                make_float2(__expf(T - S0) * d0, __expf(T - S1) * d1);
            if (j == 0) g_T[cid] = T;
        }
    }
}

// ---------------- SSD pass A via HMMA bf16x3, 2 heads per block -------------
// grid 2048 = (b, hpair, c). X tile (s=64, p=64) covers heads 2hp, 2hp+1
// (contiguous xc columns); B tile shared by both heads.
#define SA_BH 0
#define SA_BL 4608
#define SA_XH 9216
#define SA_XL 13824
#define SA_END 18432
__global__ void __launch_bounds__(256) k_ssd_a_mma() {
    __shared__ __align__(16) __nv_bfloat16 smb[SA_END];
    int tid = threadIdx.x;
    int blk = blockIdx.x;
    int bp = blk >> 6, c = blk & 63;
    int b = bp >> 2, hp = bp & 3;
    int r0 = b * LSEQ + c * QC;
    int cid0 = ((b * NH + hp * 2) << 6) | c;        // head 2hp
    int cid1 = cid0 + (1 << 6);                     // head 2hp+1

    // stage B (shared by both heads)
    for (int i = tid; i < 512; i += 256) {
        int s = i >> 3, q = (i & 7) * 8;
        *(uint4*)&smb[SA_BH + s * 72 + q] =
            *(const uint4*)&g_xch[(size_t)(r0 + s) * CONVD + 256 + q];
        *(uint4*)&smb[SA_BL + s * 72 + q] =
            *(const uint4*)&g_xcl[(size_t)(r0 + s) * CONVD + 256 + q];
    }
    // stage scaled X (s, 64p = 2 heads), reconstruct+scale+resplit
    for (int i = tid; i < 1024; i += 256) {
        int s = i >> 4, q = (i & 15) * 4;
        size_t ro = (size_t)(r0 + s) * CONVD + hp * 64;
        uint2 hv = *(const uint2*)&g_xch[ro + q];
        uint2 lv = *(const uint2*)&g_xcl[ro + q];
        float sc = g_ssc[(size_t)((q < 32) ? cid0 : cid1) * QC + s];
        uint32_t h0, l0, h1, l1;
        split2((bflo(hv.x) + bflo(lv.x)) * sc, (bfhi(hv.x) + bfhi(lv.x)) * sc, h0, l0);
        split2((bflo(hv.y) + bflo(lv.y)) * sc, (bfhi(hv.y) + bfhi(lv.y)) * sc, h1, l1);
        *(uint2*)&smb[SA_XH + s * 72 + q] = make_uint2(h0, h1);
        *(uint2*)&smb[SA_XL + s * 72 + q] = make_uint2(l0, l1);
    }
    __syncthreads();

    uint32_t sb = smem_u32(smb);
    int wid = tid >> 5, lane = tid & 31;
    int mw = wid & 3, nw = wid >> 2;       // 4 m-tiles (16p) x 2 n-tiles (32n)
    int gidx = lane >> 3;
    int a_soff = (gidx >> 1) * 8, a_poff = (gidx & 1) * 8;
    int b_soff = ((lane >> 3) & 1) * 8, b_noff = (lane >> 4) * 8;
    float acc[4][4] = {};
#pragma unroll
    for (int kf = 0; kf < 4; kf++) {
        int k0 = kf << 4;
        uint32_t xh4[4], xl4[4];
        uint32_t ax = sb + (uint32_t)((SA_XH + (k0 + a_soff + (lane & 7)) * 72
                                       + mw * 16 + a_poff) * 2);
        LDSM4T(xh4, ax);
        LDSM4T(xl4, ax + (SA_XL - SA_XH) * 2);
        uint32_t bh4[2][4], bl4[2][4];
#pragma unroll
        for (int ng = 0; ng < 2; ng++) {
            uint32_t bad = sb + (uint32_t)((SA_BH + (k0 + b_soff + (lane & 7)) * 72
                                            + nw * 32 + ng * 16 + b_noff) * 2);
            LDSM4T(bh4[ng], bad);
            LDSM4T(bl4[ng], bad + (SA_BL - SA_BH) * 2);
        }
#pragma unroll
        for (int nf = 0; nf < 4; nf++) {
            uint32_t* BH = &bh4[nf >> 1][(nf & 1) * 2];
            uint32_t* BL = &bl4[nf >> 1][(nf & 1) * 2];
            MMA16816(acc[nf], xh4, BH[0], BH[1]);
            MMA16816(acc[nf], xh4, BL[0], BL[1]);
            MMA16816(acc[nf], xl4, BH[0], BH[1]);
        }
    }
    int g = lane >> 2, tg = lane & 3;
    int head = mw >> 1;
    size_t ub = (size_t)(head ? cid1 : cid0) * 2048;
    int pbase = (mw & 1) * 16 + g;
#pragma unroll
    for (int nf = 0; nf < 4; nf++) {
        int n = nw * 32 + nf * 8 + tg * 2;
#pragma unroll
        for (int e = 0; e < 2; e++) {
            int pp = pbase + e * 8;
            uint32_t h2, l2;
            split2(acc[nf][e * 2 + 0], acc[nf][e * 2 + 1], h2, l2);
            *(uint32_t*)&g_Uh[ub + pp * 64 + n] = h2;
            *(uint32_t*)&g_Ul[ub + pp * 64 + n] = l2;
        }
    }
}

// ---------------- SSD pass B: hs = W @ U via HMMA (W computed in-block) -----
#define SB_WH 0
#define SB_WL 4608
#define SB_UH 9216
#define SB_UL 13824
#define SB_END 18432
__global__ void __launch_bounds__(256) k_ssd_b_mma() {
    __shared__ __align__(16) __nv_bfloat16 smb[SB_END];
    __shared__ float sI[64];
    int tid = threadIdx.x, wid = tid >> 5, lane = tid & 31;
    int bh = blockIdx.x;
    int col0 = blockIdx.y * 64;
    if (tid < 64) {
        float v = g_T[bh * 64 + tid];
#pragma unroll
        for (int o = 1; o < 32; o <<= 1) {
            float u = __shfl_up_sync(0xffffffffu, v, o);
            if ((tid & 31) >= o) v += u;
        }
        sI[tid] = v;
    }
    __syncthreads();
    if (tid >= 32 && tid < 64) sI[tid] += sI[31];
    __syncthreads();
    for (int i = tid; i < 2048; i += 256) {
        int c = i >> 5, j = (i & 31) * 2;
        float w0 = (j < c)     ? __expf(sI[c - 1] - sI[j])     : 0.f;
        float w1 = (j + 1 < c) ? __expf(sI[c - 1] - sI[j + 1]) : 0.f;
        uint32_t h2, l2;
        split2(w0, w1, h2, l2);
        *(uint32_t*)&smb[SB_WH + c * 72 + j] = h2;
        *(uint32_t*)&smb[SB_WL + c * 72 + j] = l2;
    }
    for (int i = tid; i < 512; i += 256) {
        int j = i >> 3, q = (i & 7) * 8;
        *(uint4*)&smb[SB_UH + j * 72 + q] =
            *(const uint4*)&g_Uh[((size_t)bh * 64 + j) * 2048 + col0 + q];
        *(uint4*)&smb[SB_UL + j * 72 + q] =
            *(const uint4*)&g_Ul[((size_t)bh * 64 + j) * 2048 + col0 + q];
    }
    __syncthreads();
    uint32_t sb = smem_u32(smb);
    int mw = wid & 3, nw = wid >> 2;
    int crow = mw * 16, ncol = nw * 32;
    int lrow = lane & 15, lk = (lane >> 4) << 3;
    int b_soff = ((lane >> 3) & 1) * 8, b_noff = (lane >> 4) * 8;
    float acc[4][4] = {};
#pragma unroll
    for (int kf = 0; kf < 4; kf++) {
        int k0 = kf << 4;
        uint32_t whf[4], wlf[4];
        uint32_t ad = sb + (uint32_t)((SB_WH + (crow + lrow) * 72 + k0 + lk) * 2);
        LDSM4(whf, ad);
        LDSM4(wlf, ad + (SB_WL - SB_WH) * 2);
        uint32_t uh[2][4], ul[2][4];
#pragma unroll
        for (int hf = 0; hf < 2; hf++) {
            uint32_t ad2 = sb + (uint32_t)((SB_UH + (k0 + b_soff + (lane & 7)) * 72
                                            + ncol + hf * 16 + b_noff) * 2);
            LDSM4T(uh[hf], ad2);
            LDSM4T(ul[hf], ad2 + (SB_UL - SB_UH) * 2);
        }
#pragma unroll
        for (int nf = 0; nf < 4; nf++) {
            uint32_t* BH = &uh[nf >> 1][(nf & 1) * 2];
            uint32_t* BL = &ul[nf >> 1][(nf & 1) * 2];
            MMA16816(acc[nf], whf, BH[0], BH[1]);
            MMA16816(acc[nf], whf, BL[0], BL[1]);
            MMA16816(acc[nf], wlf, BH[0], BH[1]);
        }
    }
    int g = lane >> 2, tg = lane & 3;
#pragma unroll
    for (int nf = 0; nf < 4; nf++) {
        int col = col0 + ncol + nf * 8 + tg * 2;
#pragma unroll
        for (int e = 0; e < 2; e++) {
            int c = crow + g + e * 8;
            uint32_t h2, l2;
            split2(acc[nf][e * 2 + 0], acc[nf][e * 2 + 1], h2, l2);
            *(uint32_t*)&g_hsh[((size_t)bh * 64 + c) * 2048 + col] = h2;
            *(uint32_t*)&g_hsl[((size_t)bh * 64 + c) * 2048 + col] = l2;
        }
    }
}

// ---------------- SSD pass C via HMMA bf16x3 (occ 3) ------------------------
#define SC_P  72
#define SC_CH 0
#define SC_CL 4608
#define SC_BH 9216
#define SC_BL 13824
#define SC_XH 18432
#define SC_XL 20992
#define SC_HH 23552
#define SC_HL 25856
#define SC_END 28160
__global__ void __launch_bounds__(256, 3) k_ssd_c_mma(const float* __restrict__ Dp) {
    extern __shared__ __align__(16) __nv_bfloat16 smb[];
    float* Ssm = (float*)(smb + SC_END);
    float* dts = Ssm + 64;
    int tid = threadIdx.x, wid = tid >> 5, lane = tid & 31;
    int cid = blockIdx.x;
    int bh = cid >> 6, c = cid & 63;
    int b = bh >> 3, h = bh & 7;
    int r0 = b * LSEQ + c * QC;
    float Dh = Dp[h];

    for (int i = tid; i < 512; i += 256) {
        int s = i >> 3, q = (i & 7) * 8;
        size_t ro = (size_t)(r0 + s) * CONVD;
        *(uint4*)&smb[SC_CH + s * SC_P + q] = *(const uint4*)&g_xch[ro + 320 + q];
        *(uint4*)&smb[SC_CL + s * SC_P + q] = *(const uint4*)&g_xcl[ro + 320 + q];
        *(uint4*)&smb[SC_BH + s * SC_P + q] = *(const uint4*)&g_xch[ro + 256 + q];
        *(uint4*)&smb[SC_BL + s * SC_P + q] = *(const uint4*)&g_xcl[ro + 256 + q];
    }
    for (int i = tid; i < 256; i += 256) {
        int s = i >> 2, q = (i & 3) * 8;
        size_t ro = (size_t)(r0 + s) * CONVD + h * HD;
        *(uint4*)&smb[SC_XH + s * 40 + q] = *(const uint4*)&g_xch[ro + q];
        *(uint4*)&smb[SC_XL + s * 40 + q] = *(const uint4*)&g_xcl[ro + q];
    }
    for (int i = tid; i < 256; i += 256) {
        int p = i >> 3, q = (i & 7) * 8;
        size_t ho = (size_t)cid * 2048 + p * 64 + q;
        *(uint4*)&smb[SC_HH + p * SC_P + q] = *(const uint4*)&g_hsh[ho];
        *(uint4*)&smb[SC_HL + p * SC_P + q] = *(const uint4*)&g_hsl[ho];
    }
    if (tid < 64) {
        Ssm[tid] = g_S[(size_t)cid * QC + tid];
        dts[tid] = g_dtb[(size_t)(r0 + tid) * NH + h];
    }
    __syncthreads();

    uint32_t sb = smem_u32(smb);
    int mw = wid & 3, nw = wid >> 2;
    int arow = mw * 16;
    int lrow = lane & 15, lk = (lane >> 4) << 3;
    int brow = (lane & 7) + ((lane >> 4) & 1) * 8;
    int bk = ((lane >> 3) & 1) << 3;
    int b_soff = ((lane >> 3) & 1) * 8, b_noff = (lane >> 4) * 8;

    float accg[4][4] = {};
    if (!(nw == 1 && mw < 2)) {
#pragma unroll
        for (int kf = 0; kf < 4; kf++) {
            int k0 = kf << 4;
            uint32_t ch[4], cl[4];
            uint32_t ad = sb + (uint32_t)(((arow + lrow) * SC_P + k0 + lk) * 2);
            LDSM4(ch, ad + SC_CH * 2);
            LDSM4(cl, ad + SC_CL * 2);
            uint32_t bh2[2][4], bl2[2][4];
#pragma unroll
            for (int ng = 0; ng < 2; ng++) {
                uint32_t ad2 = sb + (uint32_t)(((nw * 32 + ng * 16 + brow) * SC_P + k0 + bk) * 2);
                LDSM4(bh2[ng], ad2 + SC_BH * 2);
                LDSM4(bl2[ng], ad2 + SC_BL * 2);
            }
#pragma unroll
            for (int nf = 0; nf < 4; nf++) {
                uint32_t* BH = &bh2[nf >> 1][(nf & 1) * 2];
                uint32_t* BL = &bl2[nf >> 1][(nf & 1) * 2];
                MMA16816(accg[nf], ch, BH[0], BH[1]);
                MMA16816(accg[nf], ch, BL[0], BL[1]);
                MMA16816(accg[nf], cl, BH[0], BH[1]);
            }
        }
    }
    __syncthreads();

    int g = lane >> 2, tg = lane & 3;
    int t0 = arow + g, t1 = arow + g + 8;
    float St0 = Ssm[t0], St1 = Ssm[t1];
#pragma unroll
    for (int nf = 0; nf < 4; nf++) {
        int s0 = nw * 32 + nf * 8 + tg * 2;
        float ds0 = dts[s0], Ss0 = Ssm[s0];
        float ds1 = dts[s0 + 1], Ss1 = Ssm[s0 + 1];
        float m00 = (s0 <= t0)     ? accg[nf][0] * __expf(St0 - Ss0) * ds0 : 0.f;
        float m01 = (s0 + 1 <= t0) ? accg[nf][1] * __expf(St0 - Ss1) * ds1 : 0.f;
        float m10 = (s0 <= t1)     ? accg[nf][2] * __expf(St1 - Ss0) * ds0 : 0.f;
        float m11 = (s0 + 1 <= t1) ? accg[nf][3] * __expf(St1 - Ss1) * ds1 : 0.f;
        uint32_t h2, l2;
        split2(m00, m01, h2, l2);
        *(uint32_t*)&smb[SC_BH + t0 * SC_P + s0] = h2;
        *(uint32_t*)&smb[SC_BL + t0 * SC_P + s0] = l2;
        split2(m10, m11, h2, l2);
        *(uint32_t*)&smb[SC_BH + t1 * SC_P + s0] = h2;
        *(uint32_t*)&smb[SC_BL + t1 * SC_P + s0] = l2;
    }
    __syncthreads();

    int pw = wid >> 2;
    int prow = pw * 16;
    float ayi[2][4] = {}, ayo[2][4] = {};
#pragma unroll
    for (int kf = 0; kf < 4; kf++) {
        int k0 = kf << 4;
        uint32_t ad = sb + (uint32_t)(((arow + lrow) * SC_P + k0 + lk) * 2);
        uint32_t mh[4], ml[4], ch[4], cl[4];
        LDSM4(mh, ad + SC_BH * 2);
        LDSM4(ml, ad + SC_BL * 2);
        LDSM4(ch, ad + SC_CH * 2);
        LDSM4(cl, ad + SC_CL * 2);
        uint32_t xh[4], xl[4], hh2[4], hl2[4];
        uint32_t adx = sb + (uint32_t)((SC_XH + (k0 + b_soff + (lane & 7)) * 40
                                        + prow + b_noff) * 2);
        LDSM4T(xh, adx);
        LDSM4T(xl, adx + (SC_XL - SC_XH) * 2);
        uint32_t adh = sb + (uint32_t)(((prow + brow) * SC_P + k0 + bk) * 2);
        LDSM4(hh2, adh + SC_HH * 2);
        LDSM4(hl2, adh + SC_HL * 2);
#pragma unroll
        for (int nf = 0; nf < 2; nf++) {
            uint32_t* XH = &xh[nf * 2];  uint32_t* XL = &xl[nf * 2];
            uint32_t* HH = &hh2[nf * 2]; uint32_t* HL = &hl2[nf * 2];
            MMA16816(ayi[nf], mh, XH[0], XH[1]);
            MMA16816(ayi[nf], mh, XL[0], XL[1]);
            MMA16816(ayi[nf], ml, XH[0], XH[1]);
            MMA16816(ayo[nf], ch, HH[0], HH[1]);
            MMA16816(ayo[nf], ch, HL[0], HL[1]);
            MMA16816(ayo[nf], cl, HH[0], HH[1]);
        }
    }

    float eS0 = __expf(St0), eS1 = __expf(St1);
#pragma unroll
    for (int nf = 0; nf < 2; nf++) {
        int p = prow + nf * 8 + tg * 2;
        uint32_t xh0 = *(const uint32_t*)&smb[SC_XH + t0 * 40 + p];
        uint32_t xl0 = *(const uint32_t*)&smb[SC_XL + t0 * 40 + p];
        uint32_t xh1 = *(const uint32_t*)&smb[SC_XH + t1 * 40 + p];
        uint32_t xl1 = *(const uint32_t*)&smb[SC_XL + t1 * 40 + p];
        float xv00 = bflo(xh0) + bflo(xl0);
        float xv01 = bfhi(xh0) + bfhi(xl0);
        float xv10 = bflo(xh1) + bflo(xl1);
        float xv11 = bfhi(xh1) + bfhi(xl1);
        *(float2*)&g_y[(size_t)(r0 + t0) * DINNER + h * HD + p] =
            make_float2(ayi[nf][0] + eS0 * ayo[nf][0] + Dh * xv00,
                        ayi[nf][1] + eS0 * ayo[nf][1] + Dh * xv01);
        *(float2*)&g_y[(size_t)(r0 + t1) * DINNER + h * HD + p] =
            make_float2(ayi[nf][2] + eS1 * ayo[nf][2] + Dh * xv10,
                        ayi[nf][3] + eS1 * ayo[nf][3] + Dh * xv11);
    }
}

// ---------------- K4a: gating + gated RMSNorm (warp/row) --------------------
__global__ void k_gate(const float* __restrict__ gw) {
    int r    = blockIdx.x * 8 + (threadIdx.x >> 5);
    int lane = threadIdx.x & 31;
    float4 y0 = *(const float4*)&g_y[(size_t)r * DINNER + lane * 4];
    float4 y1 = *(const float4*)&g_y[(size_t)r * DINNER + 128 + lane * 4];
    float4 z0 = *(const float4*)&g_zx[(size_t)r * DPROJ + lane * 4];
    float4 z1 = *(const float4*)&g_zx[(size_t)r * DPROJ + 128 + lane * 4];
    float gv[8];
    gv[0] = y0.x * silu(z0.x); gv[1] = y0.y * silu(z0.y);
    gv[2] = y0.z * silu(z0.z); gv[3] = y0.w * silu(z0.w);
    gv[4] = y1.x * silu(z1.x); gv[5] = y1.y * silu(z1.y);
    gv[6] = y1.z * silu(z1.z); gv[7] = y1.w * silu(z1.w);
    float ss = 0.f;
#pragma unroll
    for (int j = 0; j < 8; j++) ss += gv[j] * gv[j];
#pragma unroll
    for (int o = 16; o; o >>= 1) ss += __shfl_xor_sync(0xffffffffu, ss, o);
    float sc = rsqrtf(ss * (1.f / DINNER) + 1e-5f);
    float4 w0 = *(const float4*)&gw[lane * 4];
    float4 w1 = *(const float4*)&gw[128 + lane * 4];
    float wv[8] = {w0.x, w0.y, w0.z, w0.w, w1.x, w1.y, w1.z, w1.w};
    uint32_t h2[4], l2[4];
#pragma unroll
    for (int j = 0; j < 4; j++)
        split2(gv[2 * j] * sc * wv[2 * j], gv[2 * j + 1] * sc * wv[2 * j + 1],
               h2[j], l2[j]);
    *(uint2*)&g_gh[(size_t)r * DINNER + lane * 4]       = make_uint2(h2[0], h2[1]);
    *(uint2*)&g_gh[(size_t)r * DINNER + 128 + lane * 4] = make_uint2(h2[2], h2[3]);
    *(uint2*)&g_gl[(size_t)r * DINNER + lane * 4]       = make_uint2(l2[0], l2[1]);
    *(uint2*)&g_gl[(size_t)r * DINNER + 128 + lane * 4] = make_uint2(l2[2], l2[3]);
}

// ---------------- K4b: out_proj HMMA bf16x3 + residual, tile 64x128 ---------
#define OP_AH 0
#define OP_AL 8704
#define OP_BH 17408
#define OP_BL 34816
#define OP_TOT 52224
__global__ void __launch_bounds__(256, 2) k_outproj_mma(const float* __restrict__ x,
                                                        float* __restrict__ out) {
    extern __shared__ __align__(16) __nv_bfloat16 smb[];
    int tid = threadIdx.x, wid = tid >> 5, lane = tid & 31;
    int rowBase = blockIdx.x * 64;
    uint32_t sb = smem_u32(smb);
    int mw = wid & 3, nw = wid >> 2;
    int arow = mw * 16, ncol = nw * 64;
    float acc[8][4] = {};
    int lrow = lane & 15, lk = (lane >> 4) << 3;
    int brow = (lane & 7) + ((lane >> 4) & 1) * 8;
    int bk = ((lane >> 3) & 1) << 3;

    for (int kc = 0; kc < 2; kc++) {
        if (kc) __syncthreads();
        for (int i = tid; i < 1024; i += 256) {
            int r = i >> 4, c = (i & 15) << 3;
            size_t ao = (size_t)(rowBase + r) * DINNER + kc * 128 + c;
            *(uint4*)&smb[OP_AH + r * 136 + c] = *(const uint4*)(g_gh + ao);
            *(uint4*)&smb[OP_AL + r * 136 + c] = *(const uint4*)(g_gl + ao);
        }
        for (int i = tid; i < 2048; i += 256) {
            int r = i >> 4, c = (i & 15) << 3;
            size_t bo = (size_t)r * DINNER + kc * 128 + c;
            *(uint4*)&smb[OP_BH + r * 136 + c] = *(const uint4*)(g_woh + bo);
            *(uint4*)&smb[OP_BL + r * 136 + c] = *(const uint4*)(g_wol + bo);
        }
        __syncthreads();
#pragma unroll
        for (int kf = 0; kf < 8; kf++) {
            int k0 = kf << 4;
            uint32_t ah[4], al[4];
            uint32_t ad = sb + (uint32_t)(((arow + lrow) * 136 + k0 + lk) * 2);
            LDSM4(ah, ad + OP_AH * 2);
            LDSM4(al, ad + OP_AL * 2);
            uint32_t bh[4][4], bl[4][4];
#pragma unroll
            for (int ng = 0; ng < 4; ng++) {
                uint32_t ad2 = sb + (uint32_t)(((ncol + ng * 16 + brow) * 136 + k0 + bk) * 2);
                LDSM4(bh[ng], ad2 + OP_BH * 2);
                LDSM4(bl[ng], ad2 + OP_BL * 2);
            }
#pragma unroll
            for (int nf = 0; nf < 8; nf++) {
                uint32_t* BH = &bh[nf >> 1][(nf & 1) * 2];
                uint32_t* BL = &bl[nf >> 1][(nf & 1) * 2];
                MMA16816(acc[nf], ah, BH[0], BH[1]);
                MMA16816(acc[nf], ah, BL[0], BL[1]);
                MMA16816(acc[nf], al, BH[0], BH[1]);
            }
        }
    }
    int g = lane >> 2, tg = lane & 3;
    int r = rowBase + arow + g;
#pragma unroll
    for (int nf = 0; nf < 8; nf++) {
        int c = ncol + nf * 8 + tg * 2;
        float2 x0 = *(const float2*)&x[(size_t)r * DMODEL + c];
        float2 x1 = *(const float2*)&x[(size_t)(r + 8) * DMODEL + c];
        *(float2*)&out[(size_t)r * DMODEL + c] =
            make_float2(acc[nf][0] + x0.x, acc[nf][1] + x0.y);
        *(float2*)&out[(size_t)(r + 8) * DMODEL + c] =
            make_float2(acc[nf][2] + x1.x, acc[nf][3] + x1.y);
    }
}

extern "C" void kernel_launch(void* const* d_in, const int* in_sizes, int n_in,
                              void* d_out, int out_size) {
    const float* x          = (const float*)d_in[0];
    const float* norm_w     = (const float*)d_in[1];
    const float* in_proj_w  = (const float*)d_in[2];
    const float* conv_w     = (const float*)d_in[3];
    const float* conv_b     = (const float*)d_in[4];
    const float* dt_bias    = (const float*)d_in[5];
    const float* A_log      = (const float*)d_in[6];
    const float* D          = (const float*)d_in[7];
    const float* gnorm_w    = (const float*)d_in[8];
    const float* out_proj_w = (const float*)d_in[9];
    float* out = (float*)d_out;

    const int in_smem   = IP_TOT * 2;
    const int out_smem  = OP_TOT * 2;
    const int ssdc_smem = SC_END * 2 + 512;
    cudaFuncSetAttribute(k_inproj_mma,  cudaFuncAttributeMaxDynamicSharedMemorySize, in_smem);
    cudaFuncSetAttribute(k_outproj_mma, cudaFuncAttributeMaxDynamicSharedMemorySize, out_smem);
    cudaFuncSetAttribute(k_ssd_c_mma,   cudaFuncAttributeMaxDynamicSharedMemorySize, ssdc_smem);

    k_prep<<<4096 + 113, 256>>>(x, norm_w, in_proj_w, out_proj_w);
    k_inproj_mma<<<dim3(RTOT / 64, 7), 256, in_smem>>>();
    k_conv4<<<2048 + NBATCH * NCHK, 384>>>(conv_w, conv_b, A_log, dt_bias);
    k_ssd_a_mma<<<NBATCH * 4 * NCHK, 256>>>();
    k_ssd_b_mma<<<dim3(NBATCH * NH, 32), 256>>>();
    k_ssd_c_mma<<<NCID, 256, ssdc_smem>>>(D);
    k_gate<<<RTOT / 8, 256>>>(gnorm_w);
    k_outproj_mma<<<RTOT / 64, 256, out_smem>>>(x, out);
}